// round 1
// baseline (speedup 1.0000x reference)
#include <cuda_runtime.h>
#include <cuda_bf16.h>
#include <math.h>

// Problem sizes (fixed)
#define BATCH 4
#define TSEQ 2048
#define BT (BATCH*TSEQ)       // 8192
#define DMODEL 1024
#define NHEADS 16
#define DHEAD 64
#define DFF 4096
#define BOT 256
#define ABH 32
#define EPS 1e-6f

// -------- static scratch (allocation-free contract) --------
__device__ float g_xn1[BT*DMODEL];
__device__ float g_q[BT*DMODEL];
__device__ float g_k[BT*DMODEL];
__device__ float g_v[BT*DMODEL];
__device__ float g_att[BT*DMODEL];
__device__ float g_x1[BT*DMODEL];
__device__ float g_n2[BT*DMODEL];
__device__ float g_hid[BT*DFF];
__device__ float g_ffn[BT*DMODEL];
__device__ float g_ph[BT*BOT];
__device__ float g_proj[BT*DMODEL];
__device__ float g_gvec[BATCH*DMODEL];
__device__ float g_ab[2*BATCH];

// ---------------- RMSNorm: one block per row of 1024 ----------------
__global__ void __launch_bounds__(256) rmsnorm_kernel(const float* __restrict__ x,
                                                      const float* __restrict__ w,
                                                      float* __restrict__ out) {
    const int row = blockIdx.x;
    const float* xr = x + (size_t)row * DMODEL;
    float* orow = out + (size_t)row * DMODEL;
    const int tid = threadIdx.x;

    float vals[4];
    float local = 0.f;
#pragma unroll
    for (int i = 0; i < 4; i++) {
        float v = xr[tid + i * 256];
        vals[i] = v;
        local += v * v;
    }
    // block reduce
    for (int off = 16; off; off >>= 1) local += __shfl_xor_sync(0xffffffffu, local, off);
    __shared__ float red[8];
    __shared__ float rinv_s;
    int warp = tid >> 5, lane = tid & 31;
    if (lane == 0) red[warp] = local;
    __syncthreads();
    if (tid == 0) {
        float tot = 0.f;
#pragma unroll
        for (int i = 0; i < 8; i++) tot += red[i];
        rinv_s = rsqrtf(tot * (1.0f / DMODEL) + EPS);
    }
    __syncthreads();
    float rinv = rinv_s;
#pragma unroll
    for (int i = 0; i < 4; i++) {
        int c = tid + i * 256;
        orow[c] = vals[i] * rinv * w[c];
    }
}

// ---------------- SGEMM: C[M,N] = A[M,K] @ B[N,K]^T  (+epilogue) ----------------
// EPI: 0 none, 1 exact GELU, 2 ReLU.  RESID: add R[m*N+n].
template<int EPI, bool RESID>
__global__ void __launch_bounds__(256) gemm_tn(const float* __restrict__ A,
                                               const float* __restrict__ B,
                                               const float* __restrict__ R,
                                               float* __restrict__ C,
                                               int M, int N, int K) {
    __shared__ float As[16][68];
    __shared__ float Bs[16][68];
    const int bm = blockIdx.y * 64;
    const int bn = blockIdx.x * 64;
    const int tid = threadIdx.x;
    const int tx = tid & 15;   // n dir
    const int ty = tid >> 4;   // m dir

    float acc[4][4] = {};

    for (int k0 = 0; k0 < K; k0 += 16) {
#pragma unroll
        for (int i = 0; i < 4; i++) {
            int e = tid + i * 256;
            int r = e >> 4, kk = e & 15;
            As[kk][r] = A[(size_t)(bm + r) * K + k0 + kk];
            Bs[kk][r] = B[(size_t)(bn + r) * K + k0 + kk];
        }
        __syncthreads();
#pragma unroll
        for (int kk = 0; kk < 16; kk++) {
            float4 a = *reinterpret_cast<const float4*>(&As[kk][ty * 4]);
            float4 b = *reinterpret_cast<const float4*>(&Bs[kk][tx * 4]);
            acc[0][0] += a.x * b.x; acc[0][1] += a.x * b.y; acc[0][2] += a.x * b.z; acc[0][3] += a.x * b.w;
            acc[1][0] += a.y * b.x; acc[1][1] += a.y * b.y; acc[1][2] += a.y * b.z; acc[1][3] += a.y * b.w;
            acc[2][0] += a.z * b.x; acc[2][1] += a.z * b.y; acc[2][2] += a.z * b.z; acc[2][3] += a.z * b.w;
            acc[3][0] += a.w * b.x; acc[3][1] += a.w * b.y; acc[3][2] += a.w * b.z; acc[3][3] += a.w * b.w;
        }
        __syncthreads();
    }

#pragma unroll
    for (int i = 0; i < 4; i++) {
#pragma unroll
        for (int j = 0; j < 4; j++) {
            int m = bm + ty * 4 + i;
            int n = bn + tx * 4 + j;
            float v = acc[i][j];
            if (EPI == 1) v = 0.5f * v * (1.f + erff(v * 0.70710678118f));
            if (EPI == 2) v = fmaxf(v, 0.f);
            if (RESID) v += R[(size_t)m * N + n];
            C[(size_t)m * N + n] = v;
        }
    }
}

// ---------------- RoPE (in place on q and k) ----------------
__global__ void rope_kernel(float* __restrict__ q, float* __restrict__ k) {
    int idx = blockIdx.x * blockDim.x + threadIdx.x;   // BT * 512 pairs
    if (idx >= BT * 512) return;
    int row = idx >> 9;
    int p = idx & 511;
    int h = p >> 5;
    int i = p & 31;
    int t = row & (TSEQ - 1);
    // inv_freq = 10000^(-2i/64)
    float inv = expf(-((float)(2 * i) / 64.f) * 9.210340371976184f);
    float ang = (float)t * inv;
    float s, c;
    sincosf(ang, &s, &c);
    size_t base = (size_t)row * DMODEL + h * DHEAD + i;
    float qa = q[base], qb = q[base + 32];
    q[base] = qa * c - qb * s;
    q[base + 32] = qb * c + qa * s;
    float ka = k[base], kb2 = k[base + 32];
    k[base] = ka * c - kb2 * s;
    k[base + 32] = kb2 * c + ka * s;
}

// ---------------- Flash attention (causal, online softmax) ----------------
// grid: (T/64, H, B), 256 threads. Each 4-thread group owns one query row;
// each thread owns 16 head-dims of that row.
__global__ void __launch_bounds__(256) attn_kernel(const float* __restrict__ Q,
                                                   const float* __restrict__ K,
                                                   const float* __restrict__ V,
                                                   float* __restrict__ O) {
    const int qt = blockIdx.x;
    const int h = blockIdx.y;
    const int b = blockIdx.z;

    __shared__ float Ks[64][68];
    __shared__ float Vs[64][68];

    const int tid = threadIdx.x;
    const int q = tid >> 2;            // 0..63
    const int d0 = (tid & 3) * 16;     // 0,16,32,48
    const int qrow = qt * 64 + q;

    const size_t qbase = ((size_t)(b * TSEQ + qrow)) * DMODEL + h * DHEAD + d0;
    float4 qr[4];
#pragma unroll
    for (int i = 0; i < 4; i++)
        qr[i] = *reinterpret_cast<const float4*>(&Q[qbase + i * 4]);

    float o[16];
#pragma unroll
    for (int i = 0; i < 16; i++) o[i] = 0.f;
    float m_run = -INFINITY;
    float l_run = 0.f;

    for (int kb = 0; kb <= qt; kb++) {
        // load K and V tile
#pragma unroll
        for (int i = 0; i < 16; i++) {
            int e = tid + i * 256;
            int r = e >> 6, c = e & 63;
            size_t gbase = ((size_t)(b * TSEQ + kb * 64 + r)) * DMODEL + h * DHEAD + c;
            Ks[r][c] = K[gbase];
            Vs[r][c] = V[gbase];
        }
        __syncthreads();

        float s[64];
#pragma unroll
        for (int j = 0; j < 64; j++) {
            const float4 k0 = *reinterpret_cast<const float4*>(&Ks[j][d0]);
            const float4 k1 = *reinterpret_cast<const float4*>(&Ks[j][d0 + 4]);
            const float4 k2 = *reinterpret_cast<const float4*>(&Ks[j][d0 + 8]);
            const float4 k3 = *reinterpret_cast<const float4*>(&Ks[j][d0 + 12]);
            float p = qr[0].x * k0.x + qr[0].y * k0.y + qr[0].z * k0.z + qr[0].w * k0.w
                    + qr[1].x * k1.x + qr[1].y * k1.y + qr[1].z * k1.z + qr[1].w * k1.w
                    + qr[2].x * k2.x + qr[2].y * k2.y + qr[2].z * k2.z + qr[2].w * k2.w
                    + qr[3].x * k3.x + qr[3].y * k3.y + qr[3].z * k3.z + qr[3].w * k3.w;
            p += __shfl_xor_sync(0xffffffffu, p, 1);
            p += __shfl_xor_sync(0xffffffffu, p, 2);
            s[j] = p * 0.125f;   // 1/sqrt(64)
        }
        if (kb == qt) {
#pragma unroll
            for (int j = 0; j < 64; j++)
                if (j > q) s[j] = -INFINITY;
        }
        float mx = m_run;
#pragma unroll
        for (int j = 0; j < 64; j++) mx = fmaxf(mx, s[j]);
        float scale = __expf(m_run - mx);
        float lsum = 0.f;
#pragma unroll
        for (int j = 0; j < 64; j++) {
            float p = __expf(s[j] - mx);
            s[j] = p;
            lsum += p;
        }
        l_run = l_run * scale + lsum;
        m_run = mx;
#pragma unroll
        for (int i = 0; i < 16; i++) o[i] *= scale;
#pragma unroll
        for (int j = 0; j < 64; j++) {
            const float pj = s[j];
            const float4 v0 = *reinterpret_cast<const float4*>(&Vs[j][d0]);
            const float4 v1 = *reinterpret_cast<const float4*>(&Vs[j][d0 + 4]);
            const float4 v2 = *reinterpret_cast<const float4*>(&Vs[j][d0 + 8]);
            const float4 v3 = *reinterpret_cast<const float4*>(&Vs[j][d0 + 12]);
            o[0] += pj * v0.x;  o[1] += pj * v0.y;  o[2] += pj * v0.z;  o[3] += pj * v0.w;
            o[4] += pj * v1.x;  o[5] += pj * v1.y;  o[6] += pj * v1.z;  o[7] += pj * v1.w;
            o[8] += pj * v2.x;  o[9] += pj * v2.y;  o[10] += pj * v2.z; o[11] += pj * v2.w;
            o[12] += pj * v3.x; o[13] += pj * v3.y; o[14] += pj * v3.z; o[15] += pj * v3.w;
        }
        __syncthreads();
    }

    float inv = 1.f / l_run;
    float4 out4[4];
#pragma unroll
    for (int i = 0; i < 4; i++) {
        out4[i].x = o[i * 4 + 0] * inv;
        out4[i].y = o[i * 4 + 1] * inv;
        out4[i].z = o[i * 4 + 2] * inv;
        out4[i].w = o[i * 4 + 3] * inv;
        *reinterpret_cast<float4*>(&O[qbase + i * 4]) = out4[i];
    }
}

// ---------------- mean over tokens: g[b,d] ----------------
__global__ void mean_kernel(const float* __restrict__ n2, float* __restrict__ g) {
    int b = blockIdx.y;
    int d = blockIdx.x * 256 + threadIdx.x;
    const float* p = n2 + (size_t)b * TSEQ * DMODEL + d;
    float s = 0.f;
    for (int t = 0; t < TSEQ; t++) s += p[(size_t)t * DMODEL];
    g[b * DMODEL + d] = s * (1.f / TSEQ);
}

// ---------------- alpha/beta tiny MLP ----------------
__global__ void ab_kernel(const float* __restrict__ g, const float* __restrict__ fc1,
                          const float* __restrict__ fc2, float* __restrict__ ab) {
    __shared__ float hs[BATCH][ABH];
    int tid = threadIdx.x;              // 128 threads
    int b = tid >> 5, hh = tid & 31;
    float s = 0.f;
    for (int d = 0; d < DMODEL; d++) s += g[b * DMODEL + d] * fc1[hh * DMODEL + d];
    hs[b][hh] = fmaxf(s, 0.f);
    __syncthreads();
    if (tid < 2 * BATCH) {
        int bb = tid >> 1, o = tid & 1;
        float s2 = 0.f;
#pragma unroll
        for (int j = 0; j < ABH; j++) s2 += hs[bb][j] * fc2[o * ABH + j];
        ab[bb * 2 + o] = 1.f / (1.f + expf(-s2));
    }
}

// ---------------- final combine ----------------
__global__ void combine_kernel(const float* __restrict__ x1, const float* __restrict__ ffn,
                               const float* __restrict__ proj, const float* __restrict__ ab,
                               float* __restrict__ out) {
    size_t idx = (size_t)blockIdx.x * blockDim.x + threadIdx.x;
    if (idx >= (size_t)BT * DMODEL) return;
    int b = (int)(idx >> 21);   // 2048*1024 = 2^21 per batch
    out[idx] = x1[idx] + ab[b * 2] * ffn[idx] + ab[b * 2 + 1] * proj[idx];
}

// ---------------- launch ----------------
extern "C" void kernel_launch(void* const* d_in, const int* in_sizes, int n_in,
                              void* d_out, int out_size) {
    const float* x       = (const float*)d_in[0];
    // d_in[1] = mask (unused; causal is hardcoded)
    const float* norm1_w = (const float*)d_in[2];
    const float* Wq      = (const float*)d_in[3];
    const float* Wk      = (const float*)d_in[4];
    const float* Wv      = (const float*)d_in[5];
    const float* Wo      = (const float*)d_in[6];
    const float* norm2_w = (const float*)d_in[7];
    const float* w1      = (const float*)d_in[8];
    const float* w2      = (const float*)d_in[9];
    const float* fc1     = (const float*)d_in[10];
    const float* fc2     = (const float*)d_in[11];
    const float* down    = (const float*)d_in[12];
    const float* up      = (const float*)d_in[13];
    float* out = (float*)d_out;

    float *xn1, *q, *k, *v, *att, *x1, *n2, *hid, *ffn, *ph, *proj, *gvec, *ab;
    cudaGetSymbolAddress((void**)&xn1,  g_xn1);
    cudaGetSymbolAddress((void**)&q,    g_q);
    cudaGetSymbolAddress((void**)&k,    g_k);
    cudaGetSymbolAddress((void**)&v,    g_v);
    cudaGetSymbolAddress((void**)&att,  g_att);
    cudaGetSymbolAddress((void**)&x1,   g_x1);
    cudaGetSymbolAddress((void**)&n2,   g_n2);
    cudaGetSymbolAddress((void**)&hid,  g_hid);
    cudaGetSymbolAddress((void**)&ffn,  g_ffn);
    cudaGetSymbolAddress((void**)&ph,   g_ph);
    cudaGetSymbolAddress((void**)&proj, g_proj);
    cudaGetSymbolAddress((void**)&gvec, g_gvec);
    cudaGetSymbolAddress((void**)&ab,   g_ab);

    // 1. norm1
    rmsnorm_kernel<<<BT, 256>>>(x, norm1_w, xn1);
    // 2. QKV projections
    gemm_tn<0, false><<<dim3(DMODEL / 64, BT / 64), 256>>>(xn1, Wq, nullptr, q, BT, DMODEL, DMODEL);
    gemm_tn<0, false><<<dim3(DMODEL / 64, BT / 64), 256>>>(xn1, Wk, nullptr, k, BT, DMODEL, DMODEL);
    gemm_tn<0, false><<<dim3(DMODEL / 64, BT / 64), 256>>>(xn1, Wv, nullptr, v, BT, DMODEL, DMODEL);
    // 3. RoPE on q, k
    rope_kernel<<<(BT * 512 + 255) / 256, 256>>>(q, k);
    // 4. attention
    attn_kernel<<<dim3(TSEQ / 64, NHEADS, BATCH), 256>>>(q, k, v, att);
    // 5. output proj + residual
    gemm_tn<0, true><<<dim3(DMODEL / 64, BT / 64), 256>>>(att, Wo, x, x1, BT, DMODEL, DMODEL);
    // 6. norm2
    rmsnorm_kernel<<<BT, 256>>>(x1, norm2_w, n2);
    // 7. FFN
    gemm_tn<1, false><<<dim3(DFF / 64, BT / 64), 256>>>(n2, w1, nullptr, hid, BT, DFF, DMODEL);
    gemm_tn<0, false><<<dim3(DMODEL / 64, BT / 64), 256>>>(hid, w2, nullptr, ffn, BT, DMODEL, DFF);
    // 8. projection branch
    gemm_tn<2, false><<<dim3(BOT / 64, BT / 64), 256>>>(n2, down, nullptr, ph, BT, BOT, DMODEL);
    gemm_tn<0, false><<<dim3(DMODEL / 64, BT / 64), 256>>>(ph, up, nullptr, proj, BT, DMODEL, BOT);
    // 9. alpha/beta gate
    mean_kernel<<<dim3(DMODEL / 256, BATCH), 256>>>(n2, gvec);
    ab_kernel<<<1, 128>>>(gvec, fc1, fc2, ab);
    // 10. combine
    combine_kernel<<<(BT * DMODEL + 255) / 256, 256>>>(x1, ffn, proj, ab, out);
}

// round 3
// speedup vs baseline: 1.6180x; 1.6180x over previous
#include <cuda_runtime.h>
#include <cuda_bf16.h>
#include <cstdint>
#include <math.h>

// Problem sizes (fixed)
#define BATCH 4
#define TSEQ 2048
#define BT (BATCH*TSEQ)       // 8192
#define DMODEL 1024
#define NHEADS 16
#define DHEAD 64
#define DFF 4096
#define BOT 256
#define ABH 32
#define EPS 1e-6f

// -------- static scratch (allocation-free contract) --------
__device__ float g_xn1[BT*DMODEL];
__device__ float g_q[BT*DMODEL];
__device__ float g_k[BT*DMODEL];
__device__ float g_v[BT*DMODEL];
__device__ float g_att[BT*DMODEL];
__device__ float g_x1[BT*DMODEL];
__device__ float g_n2[BT*DMODEL];
__device__ float g_hid[BT*DFF];
__device__ float g_ffn[BT*DMODEL];
__device__ float g_ph[BT*BOT];
__device__ float g_proj[BT*DMODEL];
__device__ float g_gvec[BATCH*DMODEL];
__device__ float g_ab[2*BATCH];

// ---------------- tf32 helpers ----------------
__device__ __forceinline__ uint32_t f2tf32(float f) {
    uint32_t u;
    asm("cvt.rna.tf32.f32 %0, %1;" : "=r"(u) : "f"(f));
    return u;
}

__device__ __forceinline__ void mma_tf32(float& c0, float& c1, float& c2, float& c3,
                                         uint32_t a0, uint32_t a1, uint32_t a2, uint32_t a3,
                                         uint32_t b0, uint32_t b1) {
    asm volatile(
        "mma.sync.aligned.m16n8k8.row.col.f32.tf32.tf32.f32 "
        "{%0,%1,%2,%3}, {%4,%5,%6,%7}, {%8,%9}, {%0,%1,%2,%3};"
        : "+f"(c0), "+f"(c1), "+f"(c2), "+f"(c3)
        : "r"(a0), "r"(a1), "r"(a2), "r"(a3), "r"(b0), "r"(b1));
}

// ============ tf32 mma.sync GEMM: C[M,N] = A[M,K] @ B[N,K]^T (+epilogue) ============
// CTA tile 128x128, BK=32, 256 threads = 8 warps (2m x 4n), warp tile 64x32.
// Smem row stride 36 floats -> conflict-free m16n8k8 fragment reads.
// EPI: 0 none, 1 exact GELU, 2 ReLU. RESID adds R.
#define SMS 36

template<int EPI, bool RESID>
__global__ void __launch_bounds__(256) gemm_mma(const float* __restrict__ A,
                                                const float* __restrict__ B,
                                                const float* __restrict__ R,
                                                float* __restrict__ C,
                                                int N, int K) {
    __shared__ uint32_t sA[128 * SMS];
    __shared__ uint32_t sB[128 * SMS];

    const int tid = threadIdx.x;
    const int warp = tid >> 5;
    const int lane = tid & 31;
    const int g = lane >> 2;      // group 0..7
    const int tg = lane & 3;      // thread-in-group 0..3
    const int wm = (warp & 1) * 64;
    const int wn = (warp >> 1) * 32;
    const int bm = blockIdx.y * 128;
    const int bn = blockIdx.x * 128;

    const int NC = K >> 5;  // K chunks of 32

    float acc[4][4][4];
#pragma unroll
    for (int i = 0; i < 4; i++)
#pragma unroll
        for (int j = 0; j < 4; j++)
#pragma unroll
            for (int l = 0; l < 4; l++) acc[i][j][l] = 0.f;

    // register staging for next chunk (4 float4 each for A and B)
    float4 ra[4], rb[4];
#pragma unroll
    for (int i = 0; i < 4; i++) {
        int e = tid + i * 256;
        int r = e >> 3, g4 = e & 7;
        ra[i] = *reinterpret_cast<const float4*>(&A[(size_t)(bm + r) * K + g4 * 4]);
        rb[i] = *reinterpret_cast<const float4*>(&B[(size_t)(bn + r) * K + g4 * 4]);
    }

    for (int kc = 0; kc < NC; kc++) {
        if (kc > 0) __syncthreads();
        // store staged regs -> smem with tf32 rounding
#pragma unroll
        for (int i = 0; i < 4; i++) {
            int e = tid + i * 256;
            int r = e >> 3, g4 = e & 7;
            uint32_t* pa = &sA[r * SMS + g4 * 4];
            pa[0] = f2tf32(ra[i].x); pa[1] = f2tf32(ra[i].y);
            pa[2] = f2tf32(ra[i].z); pa[3] = f2tf32(ra[i].w);
            uint32_t* pb = &sB[r * SMS + g4 * 4];
            pb[0] = f2tf32(rb[i].x); pb[1] = f2tf32(rb[i].y);
            pb[2] = f2tf32(rb[i].z); pb[3] = f2tf32(rb[i].w);
        }
        __syncthreads();

        // prefetch next chunk
        if (kc + 1 < NC) {
            const int k0 = (kc + 1) << 5;
#pragma unroll
            for (int i = 0; i < 4; i++) {
                int e = tid + i * 256;
                int r = e >> 3, g4 = e & 7;
                ra[i] = *reinterpret_cast<const float4*>(&A[(size_t)(bm + r) * K + k0 + g4 * 4]);
                rb[i] = *reinterpret_cast<const float4*>(&B[(size_t)(bn + r) * K + k0 + g4 * 4]);
            }
        }

        // MMA over this chunk: 4 k-steps of 8
#pragma unroll
        for (int ks = 0; ks < 4; ks++) {
            uint32_t af[4][4], bf[4][2];
#pragma unroll
            for (int mt = 0; mt < 4; mt++) {
                int row = wm + mt * 16 + g;
                int col = ks * 8 + tg;
                af[mt][0] = sA[row * SMS + col];
                af[mt][1] = sA[(row + 8) * SMS + col];
                af[mt][2] = sA[row * SMS + col + 4];
                af[mt][3] = sA[(row + 8) * SMS + col + 4];
            }
#pragma unroll
            for (int nt = 0; nt < 4; nt++) {
                int row = wn + nt * 8 + g;
                int col = ks * 8 + tg;
                bf[nt][0] = sB[row * SMS + col];
                bf[nt][1] = sB[row * SMS + col + 4];
            }
#pragma unroll
            for (int mt = 0; mt < 4; mt++)
#pragma unroll
                for (int nt = 0; nt < 4; nt++)
                    mma_tf32(acc[mt][nt][0], acc[mt][nt][1], acc[mt][nt][2], acc[mt][nt][3],
                             af[mt][0], af[mt][1], af[mt][2], af[mt][3],
                             bf[nt][0], bf[nt][1]);
        }
    }

    // epilogue
#pragma unroll
    for (int mt = 0; mt < 4; mt++) {
#pragma unroll
        for (int nt = 0; nt < 4; nt++) {
            int row = bm + wm + mt * 16 + g;
            int col = bn + wn + nt * 8 + tg * 2;
#pragma unroll
            for (int half = 0; half < 2; half++) {
                int m = row + half * 8;
                float v0 = acc[mt][nt][half * 2 + 0];
                float v1 = acc[mt][nt][half * 2 + 1];
                if (EPI == 1) {
                    v0 = 0.5f * v0 * (1.f + erff(v0 * 0.70710678118f));
                    v1 = 0.5f * v1 * (1.f + erff(v1 * 0.70710678118f));
                }
                if (EPI == 2) { v0 = fmaxf(v0, 0.f); v1 = fmaxf(v1, 0.f); }
                if (RESID) {
                    float2 r2 = *reinterpret_cast<const float2*>(&R[(size_t)m * N + col]);
                    v0 += r2.x; v1 += r2.y;
                }
                float2 o2 = make_float2(v0, v1);
                *reinterpret_cast<float2*>(&C[(size_t)m * N + col]) = o2;
            }
        }
    }
}

// ---------------- RMSNorm: one block per row of 1024 ----------------
__global__ void __launch_bounds__(256) rmsnorm_kernel(const float* __restrict__ x,
                                                      const float* __restrict__ w,
                                                      float* __restrict__ out) {
    const int row = blockIdx.x;
    const float* xr = x + (size_t)row * DMODEL;
    float* orow = out + (size_t)row * DMODEL;
    const int tid = threadIdx.x;

    float vals[4];
    float local = 0.f;
#pragma unroll
    for (int i = 0; i < 4; i++) {
        float v = xr[tid + i * 256];
        vals[i] = v;
        local += v * v;
    }
    for (int off = 16; off; off >>= 1) local += __shfl_xor_sync(0xffffffffu, local, off);
    __shared__ float red[8];
    __shared__ float rinv_s;
    int warp = tid >> 5, lane = tid & 31;
    if (lane == 0) red[warp] = local;
    __syncthreads();
    if (tid == 0) {
        float tot = 0.f;
#pragma unroll
        for (int i = 0; i < 8; i++) tot += red[i];
        rinv_s = rsqrtf(tot * (1.0f / DMODEL) + EPS);
    }
    __syncthreads();
    float rinv = rinv_s;
#pragma unroll
    for (int i = 0; i < 4; i++) {
        int c = tid + i * 256;
        orow[c] = vals[i] * rinv * w[c];
    }
}

// ---------------- RoPE (in place on q and k) ----------------
__global__ void rope_kernel(float* __restrict__ q, float* __restrict__ k) {
    int idx = blockIdx.x * blockDim.x + threadIdx.x;   // BT * 512 pairs
    if (idx >= BT * 512) return;
    int row = idx >> 9;
    int p = idx & 511;
    int h = p >> 5;
    int i = p & 31;
    int t = row & (TSEQ - 1);
    float inv = expf(-((float)(2 * i) / 64.f) * 9.210340371976184f);
    float ang = (float)t * inv;
    float s, c;
    sincosf(ang, &s, &c);
    size_t base = (size_t)row * DMODEL + h * DHEAD + i;
    float qa = q[base], qb = q[base + 32];
    q[base] = qa * c - qb * s;
    q[base + 32] = qb * c + qa * s;
    float ka = k[base], kb2 = k[base + 32];
    k[base] = ka * c - kb2 * s;
    k[base + 32] = kb2 * c + ka * s;
}

// ---------------- Flash attention (causal, online softmax) ----------------
__global__ void __launch_bounds__(256) attn_kernel(const float* __restrict__ Q,
                                                   const float* __restrict__ K,
                                                   const float* __restrict__ V,
                                                   float* __restrict__ O) {
    const int qt = blockIdx.x;
    const int h = blockIdx.y;
    const int b = blockIdx.z;

    __shared__ float Ks[64][68];
    __shared__ float Vs[64][68];

    const int tid = threadIdx.x;
    const int q = tid >> 2;            // 0..63
    const int d0 = (tid & 3) * 16;     // 0,16,32,48
    const int qrow = qt * 64 + q;

    const size_t qbase = ((size_t)(b * TSEQ + qrow)) * DMODEL + h * DHEAD + d0;
    float4 qr[4];
#pragma unroll
    for (int i = 0; i < 4; i++)
        qr[i] = *reinterpret_cast<const float4*>(&Q[qbase + i * 4]);

    float o[16];
#pragma unroll
    for (int i = 0; i < 16; i++) o[i] = 0.f;
    float m_run = -INFINITY;
    float l_run = 0.f;

    for (int kb = 0; kb <= qt; kb++) {
#pragma unroll
        for (int i = 0; i < 16; i++) {
            int e = tid + i * 256;
            int r = e >> 6, c = e & 63;
            size_t gbase = ((size_t)(b * TSEQ + kb * 64 + r)) * DMODEL + h * DHEAD + c;
            Ks[r][c] = K[gbase];
            Vs[r][c] = V[gbase];
        }
        __syncthreads();

        float s[64];
#pragma unroll
        for (int j = 0; j < 64; j++) {
            const float4 k0 = *reinterpret_cast<const float4*>(&Ks[j][d0]);
            const float4 k1 = *reinterpret_cast<const float4*>(&Ks[j][d0 + 4]);
            const float4 k2 = *reinterpret_cast<const float4*>(&Ks[j][d0 + 8]);
            const float4 k3 = *reinterpret_cast<const float4*>(&Ks[j][d0 + 12]);
            float p = qr[0].x * k0.x + qr[0].y * k0.y + qr[0].z * k0.z + qr[0].w * k0.w
                    + qr[1].x * k1.x + qr[1].y * k1.y + qr[1].z * k1.z + qr[1].w * k1.w
                    + qr[2].x * k2.x + qr[2].y * k2.y + qr[2].z * k2.z + qr[2].w * k2.w
                    + qr[3].x * k3.x + qr[3].y * k3.y + qr[3].z * k3.z + qr[3].w * k3.w;
            p += __shfl_xor_sync(0xffffffffu, p, 1);
            p += __shfl_xor_sync(0xffffffffu, p, 2);
            s[j] = p * 0.125f;
        }
        if (kb == qt) {
#pragma unroll
            for (int j = 0; j < 64; j++)
                if (j > q) s[j] = -INFINITY;
        }
        float mx = m_run;
#pragma unroll
        for (int j = 0; j < 64; j++) mx = fmaxf(mx, s[j]);
        float scale = __expf(m_run - mx);
        float lsum = 0.f;
#pragma unroll
        for (int j = 0; j < 64; j++) {
            float p = __expf(s[j] - mx);
            s[j] = p;
            lsum += p;
        }
        l_run = l_run * scale + lsum;
        m_run = mx;
#pragma unroll
        for (int i = 0; i < 16; i++) o[i] *= scale;
#pragma unroll
        for (int j = 0; j < 64; j++) {
            const float pj = s[j];
            const float4 v0 = *reinterpret_cast<const float4*>(&Vs[j][d0]);
            const float4 v1 = *reinterpret_cast<const float4*>(&Vs[j][d0 + 4]);
            const float4 v2 = *reinterpret_cast<const float4*>(&Vs[j][d0 + 8]);
            const float4 v3 = *reinterpret_cast<const float4*>(&Vs[j][d0 + 12]);
            o[0] += pj * v0.x;  o[1] += pj * v0.y;  o[2] += pj * v0.z;  o[3] += pj * v0.w;
            o[4] += pj * v1.x;  o[5] += pj * v1.y;  o[6] += pj * v1.z;  o[7] += pj * v1.w;
            o[8] += pj * v2.x;  o[9] += pj * v2.y;  o[10] += pj * v2.z; o[11] += pj * v2.w;
            o[12] += pj * v3.x; o[13] += pj * v3.y; o[14] += pj * v3.z; o[15] += pj * v3.w;
        }
        __syncthreads();
    }

    float inv = 1.f / l_run;
#pragma unroll
    for (int i = 0; i < 4; i++) {
        float4 out4;
        out4.x = o[i * 4 + 0] * inv;
        out4.y = o[i * 4 + 1] * inv;
        out4.z = o[i * 4 + 2] * inv;
        out4.w = o[i * 4 + 3] * inv;
        *reinterpret_cast<float4*>(&O[qbase + i * 4]) = out4;
    }
}

// ---------------- mean over tokens: g[b,d] ----------------
__global__ void mean_kernel(const float* __restrict__ n2, float* __restrict__ g) {
    int b = blockIdx.y;
    int d = blockIdx.x * 256 + threadIdx.x;
    const float* p = n2 + (size_t)b * TSEQ * DMODEL + d;
    float s = 0.f;
    for (int t = 0; t < TSEQ; t++) s += p[(size_t)t * DMODEL];
    g[b * DMODEL + d] = s * (1.f / TSEQ);
}

// ---------------- alpha/beta tiny MLP ----------------
__global__ void ab_kernel(const float* __restrict__ g, const float* __restrict__ fc1,
                          const float* __restrict__ fc2, float* __restrict__ ab) {
    __shared__ float hs[BATCH][ABH];
    int tid = threadIdx.x;              // 128 threads
    int b = tid >> 5, hh = tid & 31;
    float s = 0.f;
    for (int d = 0; d < DMODEL; d++) s += g[b * DMODEL + d] * fc1[hh * DMODEL + d];
    hs[b][hh] = fmaxf(s, 0.f);
    __syncthreads();
    if (tid < 2 * BATCH) {
        int bb = tid >> 1, o = tid & 1;
        float s2 = 0.f;
#pragma unroll
        for (int j = 0; j < ABH; j++) s2 += hs[bb][j] * fc2[o * ABH + j];
        ab[bb * 2 + o] = 1.f / (1.f + expf(-s2));
    }
}

// ---------------- final combine ----------------
__global__ void combine_kernel(const float* __restrict__ x1, const float* __restrict__ ffn,
                               const float* __restrict__ proj, const float* __restrict__ ab,
                               float* __restrict__ out) {
    size_t idx = (size_t)blockIdx.x * blockDim.x + threadIdx.x;
    if (idx >= (size_t)BT * DMODEL) return;
    int b = (int)(idx >> 21);
    out[idx] = x1[idx] + ab[b * 2] * ffn[idx] + ab[b * 2 + 1] * proj[idx];
}

// ---------------- launch ----------------
extern "C" void kernel_launch(void* const* d_in, const int* in_sizes, int n_in,
                              void* d_out, int out_size) {
    const float* x       = (const float*)d_in[0];
    const float* norm1_w = (const float*)d_in[2];
    const float* Wq      = (const float*)d_in[3];
    const float* Wk      = (const float*)d_in[4];
    const float* Wv      = (const float*)d_in[5];
    const float* Wo      = (const float*)d_in[6];
    const float* norm2_w = (const float*)d_in[7];
    const float* w1      = (const float*)d_in[8];
    const float* w2      = (const float*)d_in[9];
    const float* fc1     = (const float*)d_in[10];
    const float* fc2     = (const float*)d_in[11];
    const float* down    = (const float*)d_in[12];
    const float* up      = (const float*)d_in[13];
    float* out = (float*)d_out;

    float *xn1, *q, *k, *v, *att, *x1, *n2, *hid, *ffn, *ph, *proj, *gvec, *ab;
    cudaGetSymbolAddress((void**)&xn1,  g_xn1);
    cudaGetSymbolAddress((void**)&q,    g_q);
    cudaGetSymbolAddress((void**)&k,    g_k);
    cudaGetSymbolAddress((void**)&v,    g_v);
    cudaGetSymbolAddress((void**)&att,  g_att);
    cudaGetSymbolAddress((void**)&x1,   g_x1);
    cudaGetSymbolAddress((void**)&n2,   g_n2);
    cudaGetSymbolAddress((void**)&hid,  g_hid);
    cudaGetSymbolAddress((void**)&ffn,  g_ffn);
    cudaGetSymbolAddress((void**)&ph,   g_ph);
    cudaGetSymbolAddress((void**)&proj, g_proj);
    cudaGetSymbolAddress((void**)&gvec, g_gvec);
    cudaGetSymbolAddress((void**)&ab,   g_ab);

    // 1. norm1
    rmsnorm_kernel<<<BT, 256>>>(x, norm1_w, xn1);
    // 2. QKV projections (tf32 mma.sync)
    gemm_mma<0, false><<<dim3(DMODEL / 128, BT / 128), 256>>>(xn1, Wq, nullptr, q, DMODEL, DMODEL);
    gemm_mma<0, false><<<dim3(DMODEL / 128, BT / 128), 256>>>(xn1, Wk, nullptr, k, DMODEL, DMODEL);
    gemm_mma<0, false><<<dim3(DMODEL / 128, BT / 128), 256>>>(xn1, Wv, nullptr, v, DMODEL, DMODEL);
    // 3. RoPE on q, k
    rope_kernel<<<(BT * 512 + 255) / 256, 256>>>(q, k);
    // 4. attention
    attn_kernel<<<dim3(TSEQ / 64, NHEADS, BATCH), 256>>>(q, k, v, att);
    // 5. output proj + residual
    gemm_mma<0, true><<<dim3(DMODEL / 128, BT / 128), 256>>>(att, Wo, x, x1, DMODEL, DMODEL);
    // 6. norm2
    rmsnorm_kernel<<<BT, 256>>>(x1, norm2_w, n2);
    // 7. FFN
    gemm_mma<1, false><<<dim3(DFF / 128, BT / 128), 256>>>(n2, w1, nullptr, hid, DFF, DMODEL);
    gemm_mma<0, false><<<dim3(DMODEL / 128, BT / 128), 256>>>(hid, w2, nullptr, ffn, DMODEL, DFF);
    // 8. projection branch
    gemm_mma<2, false><<<dim3(BOT / 128, BT / 128), 256>>>(n2, down, nullptr, ph, BOT, DMODEL);
    gemm_mma<0, false><<<dim3(DMODEL / 128, BT / 128), 256>>>(ph, up, nullptr, proj, DMODEL, BOT);
    // 9. alpha/beta gate
    mean_kernel<<<dim3(DMODEL / 256, BATCH), 256>>>(n2, gvec);
    ab_kernel<<<1, 128>>>(gvec, fc1, fc2, ab);
    // 10. combine
    combine_kernel<<<(BT * DMODEL + 255) / 256, 256>>>(x1, ffn, proj, ab, out);
}

// round 4
// speedup vs baseline: 4.1758x; 2.5808x over previous
#include <cuda_runtime.h>
#include <cuda_bf16.h>
#include <cstdint>
#include <math.h>

// Problem sizes (fixed)
#define BATCH 4
#define TSEQ 2048
#define BT (BATCH*TSEQ)       // 8192
#define DMODEL 1024
#define NHEADS 16
#define DHEAD 64
#define DFF 4096
#define BOT 256
#define ABH 32
#define EPS 1e-6f

// -------- static scratch (allocation-free contract) --------
__device__ float g_xn1[BT*DMODEL];
__device__ float g_q[BT*DMODEL];
__device__ float g_k[BT*DMODEL];
__device__ float g_v[BT*DMODEL];
__device__ float g_att[BT*DMODEL];
__device__ float g_x1[BT*DMODEL];
__device__ float g_n2[BT*DMODEL];
__device__ float g_hid[BT*DFF];
__device__ float g_ffn[BT*DMODEL];
__device__ float g_ph[BT*BOT];
__device__ float g_proj[BT*DMODEL];
__device__ float g_gvec[BATCH*DMODEL];
__device__ float g_ab[2*BATCH];

// ---------------- tf32 helpers ----------------
__device__ __forceinline__ uint32_t f2tf32(float f) {
    uint32_t u;
    asm("cvt.rna.tf32.f32 %0, %1;" : "=r"(u) : "f"(f));
    return u;
}

__device__ __forceinline__ void mma_tf32(float& c0, float& c1, float& c2, float& c3,
                                         uint32_t a0, uint32_t a1, uint32_t a2, uint32_t a3,
                                         uint32_t b0, uint32_t b1) {
    asm volatile(
        "mma.sync.aligned.m16n8k8.row.col.f32.tf32.tf32.f32 "
        "{%0,%1,%2,%3}, {%4,%5,%6,%7}, {%8,%9}, {%0,%1,%2,%3};"
        : "+f"(c0), "+f"(c1), "+f"(c2), "+f"(c3)
        : "r"(a0), "r"(a1), "r"(a2), "r"(a3), "r"(b0), "r"(b1));
}

// ============ tf32 mma.sync GEMM: C[M,N] = A[M,K] @ B[N,K]^T (+epilogue) ============
#define SMS 36

template<int EPI, bool RESID>
__global__ void __launch_bounds__(256) gemm_mma(const float* __restrict__ A,
                                                const float* __restrict__ B,
                                                const float* __restrict__ R,
                                                float* __restrict__ C,
                                                int N, int K) {
    __shared__ uint32_t sA[128 * SMS];
    __shared__ uint32_t sB[128 * SMS];

    const int tid = threadIdx.x;
    const int warp = tid >> 5;
    const int lane = tid & 31;
    const int g = lane >> 2;
    const int tg = lane & 3;
    const int wm = (warp & 1) * 64;
    const int wn = (warp >> 1) * 32;
    const int bm = blockIdx.y * 128;
    const int bn = blockIdx.x * 128;

    const int NC = K >> 5;

    float acc[4][4][4];
#pragma unroll
    for (int i = 0; i < 4; i++)
#pragma unroll
        for (int j = 0; j < 4; j++)
#pragma unroll
            for (int l = 0; l < 4; l++) acc[i][j][l] = 0.f;

    float4 ra[4], rb[4];
#pragma unroll
    for (int i = 0; i < 4; i++) {
        int e = tid + i * 256;
        int r = e >> 3, g4 = e & 7;
        ra[i] = *reinterpret_cast<const float4*>(&A[(size_t)(bm + r) * K + g4 * 4]);
        rb[i] = *reinterpret_cast<const float4*>(&B[(size_t)(bn + r) * K + g4 * 4]);
    }

    for (int kc = 0; kc < NC; kc++) {
        if (kc > 0) __syncthreads();
#pragma unroll
        for (int i = 0; i < 4; i++) {
            int e = tid + i * 256;
            int r = e >> 3, g4 = e & 7;
            uint32_t* pa = &sA[r * SMS + g4 * 4];
            pa[0] = f2tf32(ra[i].x); pa[1] = f2tf32(ra[i].y);
            pa[2] = f2tf32(ra[i].z); pa[3] = f2tf32(ra[i].w);
            uint32_t* pb = &sB[r * SMS + g4 * 4];
            pb[0] = f2tf32(rb[i].x); pb[1] = f2tf32(rb[i].y);
            pb[2] = f2tf32(rb[i].z); pb[3] = f2tf32(rb[i].w);
        }
        __syncthreads();

        if (kc + 1 < NC) {
            const int k0 = (kc + 1) << 5;
#pragma unroll
            for (int i = 0; i < 4; i++) {
                int e = tid + i * 256;
                int r = e >> 3, g4 = e & 7;
                ra[i] = *reinterpret_cast<const float4*>(&A[(size_t)(bm + r) * K + k0 + g4 * 4]);
                rb[i] = *reinterpret_cast<const float4*>(&B[(size_t)(bn + r) * K + k0 + g4 * 4]);
            }
        }

#pragma unroll
        for (int ks = 0; ks < 4; ks++) {
            uint32_t af[4][4], bf[4][2];
#pragma unroll
            for (int mt = 0; mt < 4; mt++) {
                int row = wm + mt * 16 + g;
                int col = ks * 8 + tg;
                af[mt][0] = sA[row * SMS + col];
                af[mt][1] = sA[(row + 8) * SMS + col];
                af[mt][2] = sA[row * SMS + col + 4];
                af[mt][3] = sA[(row + 8) * SMS + col + 4];
            }
#pragma unroll
            for (int nt = 0; nt < 4; nt++) {
                int row = wn + nt * 8 + g;
                int col = ks * 8 + tg;
                bf[nt][0] = sB[row * SMS + col];
                bf[nt][1] = sB[row * SMS + col + 4];
            }
#pragma unroll
            for (int mt = 0; mt < 4; mt++)
#pragma unroll
                for (int nt = 0; nt < 4; nt++)
                    mma_tf32(acc[mt][nt][0], acc[mt][nt][1], acc[mt][nt][2], acc[mt][nt][3],
                             af[mt][0], af[mt][1], af[mt][2], af[mt][3],
                             bf[nt][0], bf[nt][1]);
        }
    }

#pragma unroll
    for (int mt = 0; mt < 4; mt++) {
#pragma unroll
        for (int nt = 0; nt < 4; nt++) {
            int row = bm + wm + mt * 16 + g;
            int col = bn + wn + nt * 8 + tg * 2;
#pragma unroll
            for (int half = 0; half < 2; half++) {
                int m = row + half * 8;
                float v0 = acc[mt][nt][half * 2 + 0];
                float v1 = acc[mt][nt][half * 2 + 1];
                if (EPI == 1) {
                    v0 = 0.5f * v0 * (1.f + erff(v0 * 0.70710678118f));
                    v1 = 0.5f * v1 * (1.f + erff(v1 * 0.70710678118f));
                }
                if (EPI == 2) { v0 = fmaxf(v0, 0.f); v1 = fmaxf(v1, 0.f); }
                if (RESID) {
                    float2 r2 = *reinterpret_cast<const float2*>(&R[(size_t)m * N + col]);
                    v0 += r2.x; v1 += r2.y;
                }
                float2 o2 = make_float2(v0, v1);
                *reinterpret_cast<float2*>(&C[(size_t)m * N + col]) = o2;
            }
        }
    }
}

// ============ tf32 mma.sync flash attention (causal) ============
// grid (16, 16, 4): q-tile(128 rows, reversed), head, batch. 256 threads / 8 warps.
// Warp w owns q-rows [w*16, w*16+16). K-tile 64. Smem row stride 68 floats.
#define ASTRIDE 68
#define ATT_SMEM_BYTES ((128*ASTRIDE + 64*ASTRIDE + 64*ASTRIDE) * 4)

__global__ void __launch_bounds__(256) attn_mma_kernel(const float* __restrict__ Q,
                                                       const float* __restrict__ K,
                                                       const float* __restrict__ V,
                                                       float* __restrict__ O) {
    extern __shared__ uint32_t smem[];
    uint32_t* sQP = smem;                     // 128 x 68 (Q tf32, later P tf32)
    uint32_t* sK  = smem + 128 * ASTRIDE;     // 64 x 68
    uint32_t* sV  = sK + 64 * ASTRIDE;        // 64 x 68

    const int qt = (int)(gridDim.x - 1 - blockIdx.x);
    const int h = blockIdx.y;
    const int b = blockIdx.z;
    const int tid = threadIdx.x;
    const int w = tid >> 5;
    const int lane = tid & 31;
    const int g = lane >> 2;
    const int tg = lane & 3;
    const size_t headoff = (size_t)h * DHEAD;

    // fill Q tile (scaled 1/sqrt(64), tf32)
#pragma unroll
    for (int i = 0; i < 8; i++) {
        int e = tid + i * 256;
        int r = e >> 4, f4 = e & 15;
        const float4 v = *reinterpret_cast<const float4*>(
            &Q[((size_t)(b * TSEQ + qt * 128 + r)) * DMODEL + headoff + f4 * 4]);
        uint4 t;
        t.x = f2tf32(v.x * 0.125f); t.y = f2tf32(v.y * 0.125f);
        t.z = f2tf32(v.z * 0.125f); t.w = f2tf32(v.w * 0.125f);
        *reinterpret_cast<uint4*>(&sQP[r * ASTRIDE + f4 * 4]) = t;
    }
    __syncthreads();

    // preload Q fragments (warp-private rows)
    const int r0 = w * 16 + g;
    uint32_t qf[8][4];
#pragma unroll
    for (int ks = 0; ks < 8; ks++) {
        int c = ks * 8 + tg;
        qf[ks][0] = sQP[r0 * ASTRIDE + c];
        qf[ks][1] = sQP[(r0 + 8) * ASTRIDE + c];
        qf[ks][2] = sQP[r0 * ASTRIDE + c + 4];
        qf[ks][3] = sQP[(r0 + 8) * ASTRIDE + c + 4];
    }

    float o[8][4];
#pragma unroll
    for (int nt = 0; nt < 8; nt++)
#pragma unroll
        for (int l = 0; l < 4; l++) o[nt][l] = 0.f;
    float m0 = -1e30f, m1 = -1e30f, l0 = 0.f, l1 = 0.f;

    const int rowg = qt * 128 + w * 16 + g;   // global row (half 0)
    const int kbmax = 2 * qt + 1;

    for (int kb = 0; kb <= kbmax; kb++) {
        __syncthreads();
        // load K,V tile [64 x 64] tf32
#pragma unroll
        for (int i = 0; i < 4; i++) {
            int e = tid + i * 256;
            int r = e >> 4, f4 = e & 15;
            size_t gb = ((size_t)(b * TSEQ + kb * 64 + r)) * DMODEL + headoff + f4 * 4;
            float4 kv = *reinterpret_cast<const float4*>(&K[gb]);
            float4 vv = *reinterpret_cast<const float4*>(&V[gb]);
            uint4 tk, tv;
            tk.x = f2tf32(kv.x); tk.y = f2tf32(kv.y); tk.z = f2tf32(kv.z); tk.w = f2tf32(kv.w);
            tv.x = f2tf32(vv.x); tv.y = f2tf32(vv.y); tv.z = f2tf32(vv.z); tv.w = f2tf32(vv.w);
            *reinterpret_cast<uint4*>(&sK[r * ASTRIDE + f4 * 4]) = tk;
            *reinterpret_cast<uint4*>(&sV[r * ASTRIDE + f4 * 4]) = tv;
        }
        __syncthreads();

        // warp fully masked for this k-block? (keys all > max row of warp)
        if (kb * 64 > qt * 128 + w * 16 + 15) continue;

        // ---- S = Q K^T ----
        float s[8][4];
#pragma unroll
        for (int nt = 0; nt < 8; nt++)
#pragma unroll
            for (int l = 0; l < 4; l++) s[nt][l] = 0.f;
#pragma unroll
        for (int ks = 0; ks < 8; ks++) {
            uint32_t bf[8][2];
#pragma unroll
            for (int nt = 0; nt < 8; nt++) {
                bf[nt][0] = sK[(nt * 8 + g) * ASTRIDE + ks * 8 + tg];
                bf[nt][1] = sK[(nt * 8 + g) * ASTRIDE + ks * 8 + tg + 4];
            }
#pragma unroll
            for (int nt = 0; nt < 8; nt++)
                mma_tf32(s[nt][0], s[nt][1], s[nt][2], s[nt][3],
                         qf[ks][0], qf[ks][1], qf[ks][2], qf[ks][3],
                         bf[nt][0], bf[nt][1]);
        }

        // ---- causal mask ----
        if (kb * 64 + 63 > rowg) {
#pragma unroll
            for (int nt = 0; nt < 8; nt++) {
                int c = kb * 64 + nt * 8 + 2 * tg;
                if (c > rowg) s[nt][0] = -1e30f;
                if (c + 1 > rowg) s[nt][1] = -1e30f;
                if (c > rowg + 8) s[nt][2] = -1e30f;
                if (c + 1 > rowg + 8) s[nt][3] = -1e30f;
            }
        }

        // ---- online softmax ----
        float mx0 = -1e30f, mx1 = -1e30f;
#pragma unroll
        for (int nt = 0; nt < 8; nt++) {
            mx0 = fmaxf(mx0, fmaxf(s[nt][0], s[nt][1]));
            mx1 = fmaxf(mx1, fmaxf(s[nt][2], s[nt][3]));
        }
        mx0 = fmaxf(mx0, __shfl_xor_sync(0xffffffffu, mx0, 1));
        mx0 = fmaxf(mx0, __shfl_xor_sync(0xffffffffu, mx0, 2));
        mx1 = fmaxf(mx1, __shfl_xor_sync(0xffffffffu, mx1, 1));
        mx1 = fmaxf(mx1, __shfl_xor_sync(0xffffffffu, mx1, 2));
        float nm0 = fmaxf(m0, mx0), nm1 = fmaxf(m1, mx1);
        float sc0 = __expf(m0 - nm0), sc1 = __expf(m1 - nm1);
        m0 = nm0; m1 = nm1;
        float sum0 = 0.f, sum1 = 0.f;
#pragma unroll
        for (int nt = 0; nt < 8; nt++) {
            float p0 = __expf(s[nt][0] - nm0);
            float p1 = __expf(s[nt][1] - nm0);
            float p2 = __expf(s[nt][2] - nm1);
            float p3 = __expf(s[nt][3] - nm1);
            sum0 += p0 + p1; sum1 += p2 + p3;
            uint2 u01 = make_uint2(f2tf32(p0), f2tf32(p1));
            uint2 u23 = make_uint2(f2tf32(p2), f2tf32(p3));
            *reinterpret_cast<uint2*>(&sQP[r0 * ASTRIDE + nt * 8 + 2 * tg]) = u01;
            *reinterpret_cast<uint2*>(&sQP[(r0 + 8) * ASTRIDE + nt * 8 + 2 * tg]) = u23;
        }
        sum0 += __shfl_xor_sync(0xffffffffu, sum0, 1);
        sum0 += __shfl_xor_sync(0xffffffffu, sum0, 2);
        sum1 += __shfl_xor_sync(0xffffffffu, sum1, 1);
        sum1 += __shfl_xor_sync(0xffffffffu, sum1, 2);
        l0 = l0 * sc0 + sum0;
        l1 = l1 * sc1 + sum1;
#pragma unroll
        for (int nt = 0; nt < 8; nt++) {
            o[nt][0] *= sc0; o[nt][1] *= sc0;
            o[nt][2] *= sc1; o[nt][3] *= sc1;
        }
        __syncwarp();

        // ---- O += P V ----
#pragma unroll
        for (int ks = 0; ks < 8; ks++) {
            uint32_t a0 = sQP[r0 * ASTRIDE + ks * 8 + tg];
            uint32_t a1 = sQP[(r0 + 8) * ASTRIDE + ks * 8 + tg];
            uint32_t a2 = sQP[r0 * ASTRIDE + ks * 8 + tg + 4];
            uint32_t a3 = sQP[(r0 + 8) * ASTRIDE + ks * 8 + tg + 4];
#pragma unroll
            for (int nt = 0; nt < 8; nt++) {
                uint32_t b0 = sV[(ks * 8 + tg) * ASTRIDE + nt * 8 + g];
                uint32_t b1 = sV[(ks * 8 + tg + 4) * ASTRIDE + nt * 8 + g];
                mma_tf32(o[nt][0], o[nt][1], o[nt][2], o[nt][3], a0, a1, a2, a3, b0, b1);
            }
        }
    }

    // epilogue
    float il0 = 1.f / l0, il1 = 1.f / l1;
    const size_t rg = (size_t)(b * TSEQ + qt * 128 + w * 16 + g);
#pragma unroll
    for (int nt = 0; nt < 8; nt++) {
        size_t col = headoff + nt * 8 + 2 * tg;
        *reinterpret_cast<float2*>(&O[rg * DMODEL + col]) =
            make_float2(o[nt][0] * il0, o[nt][1] * il0);
        *reinterpret_cast<float2*>(&O[(rg + 8) * DMODEL + col]) =
            make_float2(o[nt][2] * il1, o[nt][3] * il1);
    }
}

// ---------------- RMSNorm ----------------
__global__ void __launch_bounds__(256) rmsnorm_kernel(const float* __restrict__ x,
                                                      const float* __restrict__ w,
                                                      float* __restrict__ out) {
    const int row = blockIdx.x;
    const float* xr = x + (size_t)row * DMODEL;
    float* orow = out + (size_t)row * DMODEL;
    const int tid = threadIdx.x;

    float vals[4];
    float local = 0.f;
#pragma unroll
    for (int i = 0; i < 4; i++) {
        float v = xr[tid + i * 256];
        vals[i] = v;
        local += v * v;
    }
    for (int off = 16; off; off >>= 1) local += __shfl_xor_sync(0xffffffffu, local, off);
    __shared__ float red[8];
    __shared__ float rinv_s;
    int warp = tid >> 5, lane = tid & 31;
    if (lane == 0) red[warp] = local;
    __syncthreads();
    if (tid == 0) {
        float tot = 0.f;
#pragma unroll
        for (int i = 0; i < 8; i++) tot += red[i];
        rinv_s = rsqrtf(tot * (1.0f / DMODEL) + EPS);
    }
    __syncthreads();
    float rinv = rinv_s;
#pragma unroll
    for (int i = 0; i < 4; i++) {
        int c = tid + i * 256;
        orow[c] = vals[i] * rinv * w[c];
    }
}

// ---------------- RoPE (in place on q and k) ----------------
__global__ void rope_kernel(float* __restrict__ q, float* __restrict__ k) {
    int idx = blockIdx.x * blockDim.x + threadIdx.x;
    if (idx >= BT * 512) return;
    int row = idx >> 9;
    int p = idx & 511;
    int h = p >> 5;
    int i = p & 31;
    int t = row & (TSEQ - 1);
    float inv = expf(-((float)(2 * i) / 64.f) * 9.210340371976184f);
    float ang = (float)t * inv;
    float s, c;
    sincosf(ang, &s, &c);
    size_t base = (size_t)row * DMODEL + h * DHEAD + i;
    float qa = q[base], qb = q[base + 32];
    q[base] = qa * c - qb * s;
    q[base + 32] = qb * c + qa * s;
    float ka = k[base], kb2 = k[base + 32];
    k[base] = ka * c - kb2 * s;
    k[base + 32] = kb2 * c + ka * s;
}

// ---------------- mean over tokens ----------------
__global__ void mean_kernel(const float* __restrict__ n2, float* __restrict__ g) {
    int b = blockIdx.y;
    int d = blockIdx.x * 256 + threadIdx.x;
    const float* p = n2 + (size_t)b * TSEQ * DMODEL + d;
    float s = 0.f;
    for (int t = 0; t < TSEQ; t++) s += p[(size_t)t * DMODEL];
    g[b * DMODEL + d] = s * (1.f / TSEQ);
}

// ---------------- alpha/beta tiny MLP ----------------
__global__ void ab_kernel(const float* __restrict__ g, const float* __restrict__ fc1,
                          const float* __restrict__ fc2, float* __restrict__ ab) {
    __shared__ float hs[BATCH][ABH];
    int tid = threadIdx.x;
    int b = tid >> 5, hh = tid & 31;
    float s = 0.f;
    for (int d = 0; d < DMODEL; d++) s += g[b * DMODEL + d] * fc1[hh * DMODEL + d];
    hs[b][hh] = fmaxf(s, 0.f);
    __syncthreads();
    if (tid < 2 * BATCH) {
        int bb = tid >> 1, o = tid & 1;
        float s2 = 0.f;
#pragma unroll
        for (int j = 0; j < ABH; j++) s2 += hs[bb][j] * fc2[o * ABH + j];
        ab[bb * 2 + o] = 1.f / (1.f + expf(-s2));
    }
}

// ---------------- final combine ----------------
__global__ void combine_kernel(const float* __restrict__ x1, const float* __restrict__ ffn,
                               const float* __restrict__ proj, const float* __restrict__ ab,
                               float* __restrict__ out) {
    size_t idx = (size_t)blockIdx.x * blockDim.x + threadIdx.x;
    if (idx >= (size_t)BT * DMODEL) return;
    int b = (int)(idx >> 21);
    out[idx] = x1[idx] + ab[b * 2] * ffn[idx] + ab[b * 2 + 1] * proj[idx];
}

// ---------------- launch ----------------
extern "C" void kernel_launch(void* const* d_in, const int* in_sizes, int n_in,
                              void* d_out, int out_size) {
    const float* x       = (const float*)d_in[0];
    const float* norm1_w = (const float*)d_in[2];
    const float* Wq      = (const float*)d_in[3];
    const float* Wk      = (const float*)d_in[4];
    const float* Wv      = (const float*)d_in[5];
    const float* Wo      = (const float*)d_in[6];
    const float* norm2_w = (const float*)d_in[7];
    const float* w1      = (const float*)d_in[8];
    const float* w2      = (const float*)d_in[9];
    const float* fc1     = (const float*)d_in[10];
    const float* fc2     = (const float*)d_in[11];
    const float* down    = (const float*)d_in[12];
    const float* up      = (const float*)d_in[13];
    float* out = (float*)d_out;

    float *xn1, *q, *k, *v, *att, *x1, *n2, *hid, *ffn, *ph, *proj, *gvec, *ab;
    cudaGetSymbolAddress((void**)&xn1,  g_xn1);
    cudaGetSymbolAddress((void**)&q,    g_q);
    cudaGetSymbolAddress((void**)&k,    g_k);
    cudaGetSymbolAddress((void**)&v,    g_v);
    cudaGetSymbolAddress((void**)&att,  g_att);
    cudaGetSymbolAddress((void**)&x1,   g_x1);
    cudaGetSymbolAddress((void**)&n2,   g_n2);
    cudaGetSymbolAddress((void**)&hid,  g_hid);
    cudaGetSymbolAddress((void**)&ffn,  g_ffn);
    cudaGetSymbolAddress((void**)&ph,   g_ph);
    cudaGetSymbolAddress((void**)&proj, g_proj);
    cudaGetSymbolAddress((void**)&gvec, g_gvec);
    cudaGetSymbolAddress((void**)&ab,   g_ab);

    static bool attr_set = false;
    if (!attr_set) {
        cudaFuncSetAttribute((const void*)attn_mma_kernel,
                             cudaFuncAttributeMaxDynamicSharedMemorySize, ATT_SMEM_BYTES);
        attr_set = true;
    }

    // 1. norm1
    rmsnorm_kernel<<<BT, 256>>>(x, norm1_w, xn1);
    // 2. QKV projections (tf32 mma.sync)
    gemm_mma<0, false><<<dim3(DMODEL / 128, BT / 128), 256>>>(xn1, Wq, nullptr, q, DMODEL, DMODEL);
    gemm_mma<0, false><<<dim3(DMODEL / 128, BT / 128), 256>>>(xn1, Wk, nullptr, k, DMODEL, DMODEL);
    gemm_mma<0, false><<<dim3(DMODEL / 128, BT / 128), 256>>>(xn1, Wv, nullptr, v, DMODEL, DMODEL);
    // 3. RoPE on q, k
    rope_kernel<<<(BT * 512 + 255) / 256, 256>>>(q, k);
    // 4. attention (tf32 mma.sync flash)
    attn_mma_kernel<<<dim3(TSEQ / 128, NHEADS, BATCH), 256, ATT_SMEM_BYTES>>>(q, k, v, att);
    // 5. output proj + residual
    gemm_mma<0, true><<<dim3(DMODEL / 128, BT / 128), 256>>>(att, Wo, x, x1, DMODEL, DMODEL);
    // 6. norm2
    rmsnorm_kernel<<<BT, 256>>>(x1, norm2_w, n2);
    // 7. FFN
    gemm_mma<1, false><<<dim3(DFF / 128, BT / 128), 256>>>(n2, w1, nullptr, hid, DFF, DMODEL);
    gemm_mma<0, false><<<dim3(DMODEL / 128, BT / 128), 256>>>(hid, w2, nullptr, ffn, DMODEL, DFF);
    // 8. projection branch
    gemm_mma<2, false><<<dim3(BOT / 128, BT / 128), 256>>>(n2, down, nullptr, ph, BOT, DMODEL);
    gemm_mma<0, false><<<dim3(DMODEL / 128, BT / 128), 256>>>(ph, up, nullptr, proj, DMODEL, BOT);
    // 9. alpha/beta gate
    mean_kernel<<<dim3(DMODEL / 256, BATCH), 256>>>(n2, gvec);
    ab_kernel<<<1, 128>>>(gvec, fc1, fc2, ab);
    // 10. combine
    combine_kernel<<<(BT * DMODEL + 255) / 256, 256>>>(x1, ffn, proj, ab, out);
}

// round 5
// speedup vs baseline: 4.7300x; 1.1327x over previous
#include <cuda_runtime.h>
#include <cuda_bf16.h>
#include <cstdint>
#include <math.h>

// Problem sizes (fixed)
#define BATCH 4
#define TSEQ 2048
#define BT (BATCH*TSEQ)       // 8192
#define DMODEL 1024
#define NHEADS 16
#define DHEAD 64
#define DFF 4096
#define BOT 256
#define ABH 32
#define EPS 1e-6f

// -------- static scratch (allocation-free contract) --------
__device__ float g_xn1[BT*DMODEL];
__device__ float g_q[BT*DMODEL];
__device__ float g_k[BT*DMODEL];
__device__ float g_v[BT*DMODEL];
__device__ float g_att[BT*DMODEL];
__device__ float g_x1[BT*DMODEL];
__device__ float g_n2[BT*DMODEL];
__device__ float g_hid[BT*DFF];
__device__ float g_ffn[BT*DMODEL];
__device__ float g_ph[BT*BOT];
__device__ float g_proj[BT*DMODEL];
__device__ float g_gvec[BATCH*DMODEL];
__device__ float g_ab[2*BATCH];

// ---------------- helpers ----------------
__device__ __forceinline__ uint32_t smem_u32(const void* p) {
    uint32_t a;
    asm("{ .reg .u64 t; cvta.to.shared.u64 t, %1; cvt.u32.u64 %0, t; }" : "=r"(a) : "l"(p));
    return a;
}
__device__ __forceinline__ uint32_t f2tf32(float f) {
    uint32_t u;
    asm("cvt.rna.tf32.f32 %0, %1;" : "=r"(u) : "f"(f));
    return u;
}
__device__ __forceinline__ void cp16(uint32_t daddr, const void* gptr) {
    asm volatile("cp.async.cg.shared.global [%0], [%1], 16;" :: "r"(daddr), "l"(gptr) : "memory");
}
#define CP_COMMIT() asm volatile("cp.async.commit_group;" ::: "memory")
#define CP_WAIT2()  asm volatile("cp.async.wait_group 2;" ::: "memory")

__device__ __forceinline__ void mma_tf32(float& c0, float& c1, float& c2, float& c3,
                                         uint32_t a0, uint32_t a1, uint32_t a2, uint32_t a3,
                                         uint32_t b0, uint32_t b1) {
    asm volatile(
        "mma.sync.aligned.m16n8k8.row.col.f32.tf32.tf32.f32 "
        "{%0,%1,%2,%3}, {%4,%5,%6,%7}, {%8,%9}, {%0,%1,%2,%3};"
        : "+f"(c0), "+f"(c1), "+f"(c2), "+f"(c3)
        : "r"(a0), "r"(a1), "r"(a2), "r"(a3), "r"(b0), "r"(b1));
}

// ============ cp.async pipelined tf32 GEMM: C = A[M,K] @ B[N,K]^T (+epilogue) ============
// CTA tile 128x128, BK=32, 4 stages, 8 warps (2m x 4n). Raw fp32 bits fed as tf32 (HW truncation).
#define SMS 36
#define STAGES 4
#define STAGE_FLOATS (128 * SMS * 2)
#define GEMM_SMEM_BYTES (STAGES * STAGE_FLOATS * 4)

template<int EPI, bool RESID>
__device__ __forceinline__ void gemm_body(const float* __restrict__ A,
                                          const float* __restrict__ B,
                                          const float* __restrict__ R,
                                          float* __restrict__ C,
                                          int N, int K, int bm, int bn) {
    extern __shared__ float gsmem[];
    const uint32_t sbase_u = smem_u32(gsmem);

    const int tid = threadIdx.x;
    const int warp = tid >> 5;
    const int lane = tid & 31;
    const int g = lane >> 2;
    const int tg = lane & 3;
    const int wm = (warp & 1) * 64;
    const int wn = (warp >> 1) * 32;

    const int NC = K >> 5;
    const int r_ld = tid >> 3;        // row this thread loads (2 rows per 16 threads... r in 0..31 step)
    const int f4 = tid & 7;           // float4 column within 32-float chunk

    // issue: load chunk kc into stage kc%STAGES
    auto issue = [&](int kc) {
        const int stage = kc % STAGES;
        const uint32_t abase = sbase_u + stage * (STAGE_FLOATS * 4);
        const uint32_t bbase = abase + 128 * SMS * 4;
        const int k0 = kc << 5;
#pragma unroll
        for (int i = 0; i < 4; i++) {
            int r = r_ld + i * 32;
            uint32_t soff = (uint32_t)(r * SMS + f4 * 4) * 4;
            cp16(abase + soff, &A[(size_t)(bm + r) * K + k0 + f4 * 4]);
            cp16(bbase + soff, &B[(size_t)(bn + r) * K + k0 + f4 * 4]);
        }
    };

    float acc[4][4][4];
#pragma unroll
    for (int i = 0; i < 4; i++)
#pragma unroll
        for (int j = 0; j < 4; j++)
#pragma unroll
            for (int l = 0; l < 4; l++) acc[i][j][l] = 0.f;

    // prologue: stages 0..STAGES-2
#pragma unroll
    for (int s = 0; s < STAGES - 1; s++) {
        issue(s);
        CP_COMMIT();
    }

    for (int kc = 0; kc < NC; kc++) {
        CP_WAIT2();
        __syncthreads();
        if (kc + STAGES - 1 < NC) issue(kc + STAGES - 1);
        CP_COMMIT();

        const int stage = kc % STAGES;
        const uint32_t* sA = (const uint32_t*)(gsmem + stage * STAGE_FLOATS);
        const uint32_t* sB = sA + 128 * SMS;

#pragma unroll
        for (int ks = 0; ks < 4; ks++) {
            uint32_t af[4][4], bf[4][2];
#pragma unroll
            for (int mt = 0; mt < 4; mt++) {
                int row = wm + mt * 16 + g;
                int col = ks * 8 + tg;
                af[mt][0] = sA[row * SMS + col];
                af[mt][1] = sA[(row + 8) * SMS + col];
                af[mt][2] = sA[row * SMS + col + 4];
                af[mt][3] = sA[(row + 8) * SMS + col + 4];
            }
#pragma unroll
            for (int nt = 0; nt < 4; nt++) {
                int row = wn + nt * 8 + g;
                int col = ks * 8 + tg;
                bf[nt][0] = sB[row * SMS + col];
                bf[nt][1] = sB[row * SMS + col + 4];
            }
#pragma unroll
            for (int mt = 0; mt < 4; mt++)
#pragma unroll
                for (int nt = 0; nt < 4; nt++)
                    mma_tf32(acc[mt][nt][0], acc[mt][nt][1], acc[mt][nt][2], acc[mt][nt][3],
                             af[mt][0], af[mt][1], af[mt][2], af[mt][3],
                             bf[nt][0], bf[nt][1]);
        }
    }

    // epilogue
#pragma unroll
    for (int mt = 0; mt < 4; mt++) {
#pragma unroll
        for (int nt = 0; nt < 4; nt++) {
            int row = bm + wm + mt * 16 + g;
            int col = bn + wn + nt * 8 + tg * 2;
#pragma unroll
            for (int half = 0; half < 2; half++) {
                int m = row + half * 8;
                float v0 = acc[mt][nt][half * 2 + 0];
                float v1 = acc[mt][nt][half * 2 + 1];
                if (EPI == 1) {
                    v0 = 0.5f * v0 * (1.f + erff(v0 * 0.70710678118f));
                    v1 = 0.5f * v1 * (1.f + erff(v1 * 0.70710678118f));
                }
                if (EPI == 2) { v0 = fmaxf(v0, 0.f); v1 = fmaxf(v1, 0.f); }
                if (RESID) {
                    float2 r2 = *reinterpret_cast<const float2*>(&R[(size_t)m * N + col]);
                    v0 += r2.x; v1 += r2.y;
                }
                *reinterpret_cast<float2*>(&C[(size_t)m * N + col]) = make_float2(v0, v1);
            }
        }
    }
}

template<int EPI, bool RESID>
__global__ void __launch_bounds__(256, 1) gemm_mma(const float* __restrict__ A,
                                                   const float* __restrict__ B,
                                                   const float* __restrict__ R,
                                                   float* __restrict__ C,
                                                   int N, int K) {
    gemm_body<EPI, RESID>(A, B, R, C, N, K, blockIdx.y * 128, blockIdx.x * 128);
}

// fused QKV: grid.x = 24 (8 n-tiles x 3 matrices)
__global__ void __launch_bounds__(256, 1) gemm_mma_qkv(const float* __restrict__ A,
                                                       const float* __restrict__ B0,
                                                       const float* __restrict__ B1,
                                                       const float* __restrict__ B2,
                                                       float* __restrict__ C0,
                                                       float* __restrict__ C1,
                                                       float* __restrict__ C2) {
    const int sel = blockIdx.x >> 3;
    const float* B = (sel == 0) ? B0 : (sel == 1) ? B1 : B2;
    float* C = (sel == 0) ? C0 : (sel == 1) ? C1 : C2;
    gemm_body<0, false>(A, B, nullptr, C, DMODEL, DMODEL,
                        blockIdx.y * 128, (blockIdx.x & 7) * 128);
}

// ============ tf32 mma.sync flash attention (causal) ============
#define ASTRIDE 68
#define ATT_SMEM_BYTES ((128*ASTRIDE + 64*ASTRIDE + 64*ASTRIDE) * 4)

__global__ void __launch_bounds__(256) attn_mma_kernel(const float* __restrict__ Q,
                                                       const float* __restrict__ K,
                                                       const float* __restrict__ V,
                                                       float* __restrict__ O) {
    extern __shared__ uint32_t smem[];
    uint32_t* sQP = smem;
    uint32_t* sK  = smem + 128 * ASTRIDE;
    uint32_t* sV  = sK + 64 * ASTRIDE;

    const int qt = (int)(gridDim.x - 1 - blockIdx.x);
    const int h = blockIdx.y;
    const int b = blockIdx.z;
    const int tid = threadIdx.x;
    const int w = tid >> 5;
    const int lane = tid & 31;
    const int g = lane >> 2;
    const int tg = lane & 3;
    const size_t headoff = (size_t)h * DHEAD;

#pragma unroll
    for (int i = 0; i < 8; i++) {
        int e = tid + i * 256;
        int r = e >> 4, f4 = e & 15;
        const float4 v = *reinterpret_cast<const float4*>(
            &Q[((size_t)(b * TSEQ + qt * 128 + r)) * DMODEL + headoff + f4 * 4]);
        uint4 t;
        t.x = f2tf32(v.x * 0.125f); t.y = f2tf32(v.y * 0.125f);
        t.z = f2tf32(v.z * 0.125f); t.w = f2tf32(v.w * 0.125f);
        *reinterpret_cast<uint4*>(&sQP[r * ASTRIDE + f4 * 4]) = t;
    }
    __syncthreads();

    const int r0 = w * 16 + g;
    uint32_t qf[8][4];
#pragma unroll
    for (int ks = 0; ks < 8; ks++) {
        int c = ks * 8 + tg;
        qf[ks][0] = sQP[r0 * ASTRIDE + c];
        qf[ks][1] = sQP[(r0 + 8) * ASTRIDE + c];
        qf[ks][2] = sQP[r0 * ASTRIDE + c + 4];
        qf[ks][3] = sQP[(r0 + 8) * ASTRIDE + c + 4];
    }

    float o[8][4];
#pragma unroll
    for (int nt = 0; nt < 8; nt++)
#pragma unroll
        for (int l = 0; l < 4; l++) o[nt][l] = 0.f;
    float m0 = -1e30f, m1 = -1e30f, l0 = 0.f, l1 = 0.f;

    const int rowg = qt * 128 + w * 16 + g;
    const int kbmax = 2 * qt + 1;

    for (int kb = 0; kb <= kbmax; kb++) {
        __syncthreads();
#pragma unroll
        for (int i = 0; i < 4; i++) {
            int e = tid + i * 256;
            int r = e >> 4, f4 = e & 15;
            size_t gb = ((size_t)(b * TSEQ + kb * 64 + r)) * DMODEL + headoff + f4 * 4;
            float4 kv = *reinterpret_cast<const float4*>(&K[gb]);
            float4 vv = *reinterpret_cast<const float4*>(&V[gb]);
            uint4 tk, tv;
            tk.x = f2tf32(kv.x); tk.y = f2tf32(kv.y); tk.z = f2tf32(kv.z); tk.w = f2tf32(kv.w);
            tv.x = f2tf32(vv.x); tv.y = f2tf32(vv.y); tv.z = f2tf32(vv.z); tv.w = f2tf32(vv.w);
            *reinterpret_cast<uint4*>(&sK[r * ASTRIDE + f4 * 4]) = tk;
            *reinterpret_cast<uint4*>(&sV[r * ASTRIDE + f4 * 4]) = tv;
        }
        __syncthreads();

        if (kb * 64 > qt * 128 + w * 16 + 15) continue;

        float s[8][4];
#pragma unroll
        for (int nt = 0; nt < 8; nt++)
#pragma unroll
            for (int l = 0; l < 4; l++) s[nt][l] = 0.f;
#pragma unroll
        for (int ks = 0; ks < 8; ks++) {
            uint32_t bf[8][2];
#pragma unroll
            for (int nt = 0; nt < 8; nt++) {
                bf[nt][0] = sK[(nt * 8 + g) * ASTRIDE + ks * 8 + tg];
                bf[nt][1] = sK[(nt * 8 + g) * ASTRIDE + ks * 8 + tg + 4];
            }
#pragma unroll
            for (int nt = 0; nt < 8; nt++)
                mma_tf32(s[nt][0], s[nt][1], s[nt][2], s[nt][3],
                         qf[ks][0], qf[ks][1], qf[ks][2], qf[ks][3],
                         bf[nt][0], bf[nt][1]);
        }

        if (kb * 64 + 63 > rowg) {
#pragma unroll
            for (int nt = 0; nt < 8; nt++) {
                int c = kb * 64 + nt * 8 + 2 * tg;
                if (c > rowg) s[nt][0] = -1e30f;
                if (c + 1 > rowg) s[nt][1] = -1e30f;
                if (c > rowg + 8) s[nt][2] = -1e30f;
                if (c + 1 > rowg + 8) s[nt][3] = -1e30f;
            }
        }

        float mx0 = -1e30f, mx1 = -1e30f;
#pragma unroll
        for (int nt = 0; nt < 8; nt++) {
            mx0 = fmaxf(mx0, fmaxf(s[nt][0], s[nt][1]));
            mx1 = fmaxf(mx1, fmaxf(s[nt][2], s[nt][3]));
        }
        mx0 = fmaxf(mx0, __shfl_xor_sync(0xffffffffu, mx0, 1));
        mx0 = fmaxf(mx0, __shfl_xor_sync(0xffffffffu, mx0, 2));
        mx1 = fmaxf(mx1, __shfl_xor_sync(0xffffffffu, mx1, 1));
        mx1 = fmaxf(mx1, __shfl_xor_sync(0xffffffffu, mx1, 2));
        float nm0 = fmaxf(m0, mx0), nm1 = fmaxf(m1, mx1);
        float sc0 = __expf(m0 - nm0), sc1 = __expf(m1 - nm1);
        m0 = nm0; m1 = nm1;
        float sum0 = 0.f, sum1 = 0.f;
#pragma unroll
        for (int nt = 0; nt < 8; nt++) {
            float p0 = __expf(s[nt][0] - nm0);
            float p1 = __expf(s[nt][1] - nm0);
            float p2 = __expf(s[nt][2] - nm1);
            float p3 = __expf(s[nt][3] - nm1);
            sum0 += p0 + p1; sum1 += p2 + p3;
            uint2 u01 = make_uint2(f2tf32(p0), f2tf32(p1));
            uint2 u23 = make_uint2(f2tf32(p2), f2tf32(p3));
            *reinterpret_cast<uint2*>(&sQP[r0 * ASTRIDE + nt * 8 + 2 * tg]) = u01;
            *reinterpret_cast<uint2*>(&sQP[(r0 + 8) * ASTRIDE + nt * 8 + 2 * tg]) = u23;
        }
        sum0 += __shfl_xor_sync(0xffffffffu, sum0, 1);
        sum0 += __shfl_xor_sync(0xffffffffu, sum0, 2);
        sum1 += __shfl_xor_sync(0xffffffffu, sum1, 1);
        sum1 += __shfl_xor_sync(0xffffffffu, sum1, 2);
        l0 = l0 * sc0 + sum0;
        l1 = l1 * sc1 + sum1;
#pragma unroll
        for (int nt = 0; nt < 8; nt++) {
            o[nt][0] *= sc0; o[nt][1] *= sc0;
            o[nt][2] *= sc1; o[nt][3] *= sc1;
        }
        __syncwarp();

#pragma unroll
        for (int ks = 0; ks < 8; ks++) {
            uint32_t a0 = sQP[r0 * ASTRIDE + ks * 8 + tg];
            uint32_t a1 = sQP[(r0 + 8) * ASTRIDE + ks * 8 + tg];
            uint32_t a2 = sQP[r0 * ASTRIDE + ks * 8 + tg + 4];
            uint32_t a3 = sQP[(r0 + 8) * ASTRIDE + ks * 8 + tg + 4];
#pragma unroll
            for (int nt = 0; nt < 8; nt++) {
                uint32_t b0 = sV[(ks * 8 + tg) * ASTRIDE + nt * 8 + g];
                uint32_t b1 = sV[(ks * 8 + tg + 4) * ASTRIDE + nt * 8 + g];
                mma_tf32(o[nt][0], o[nt][1], o[nt][2], o[nt][3], a0, a1, a2, a3, b0, b1);
            }
        }
    }

    float il0 = 1.f / l0, il1 = 1.f / l1;
    const size_t rg = (size_t)(b * TSEQ + qt * 128 + w * 16 + g);
#pragma unroll
    for (int nt = 0; nt < 8; nt++) {
        size_t col = headoff + nt * 8 + 2 * tg;
        *reinterpret_cast<float2*>(&O[rg * DMODEL + col]) =
            make_float2(o[nt][0] * il0, o[nt][1] * il0);
        *reinterpret_cast<float2*>(&O[(rg + 8) * DMODEL + col]) =
            make_float2(o[nt][2] * il1, o[nt][3] * il1);
    }
}

// ---------------- RMSNorm ----------------
__global__ void __launch_bounds__(256) rmsnorm_kernel(const float* __restrict__ x,
                                                      const float* __restrict__ w,
                                                      float* __restrict__ out) {
    const int row = blockIdx.x;
    const float* xr = x + (size_t)row * DMODEL;
    float* orow = out + (size_t)row * DMODEL;
    const int tid = threadIdx.x;

    float vals[4];
    float local = 0.f;
#pragma unroll
    for (int i = 0; i < 4; i++) {
        float v = xr[tid + i * 256];
        vals[i] = v;
        local += v * v;
    }
    for (int off = 16; off; off >>= 1) local += __shfl_xor_sync(0xffffffffu, local, off);
    __shared__ float red[8];
    __shared__ float rinv_s;
    int warp = tid >> 5, lane = tid & 31;
    if (lane == 0) red[warp] = local;
    __syncthreads();
    if (tid == 0) {
        float tot = 0.f;
#pragma unroll
        for (int i = 0; i < 8; i++) tot += red[i];
        rinv_s = rsqrtf(tot * (1.0f / DMODEL) + EPS);
    }
    __syncthreads();
    float rinv = rinv_s;
#pragma unroll
    for (int i = 0; i < 4; i++) {
        int c = tid + i * 256;
        orow[c] = vals[i] * rinv * w[c];
    }
}

// ---------------- RoPE (in place on q and k) ----------------
__global__ void rope_kernel(float* __restrict__ q, float* __restrict__ k) {
    int idx = blockIdx.x * blockDim.x + threadIdx.x;
    if (idx >= BT * 512) return;
    int row = idx >> 9;
    int p = idx & 511;
    int h = p >> 5;
    int i = p & 31;
    int t = row & (TSEQ - 1);
    float inv = expf(-((float)(2 * i) / 64.f) * 9.210340371976184f);
    float ang = (float)t * inv;
    float s, c;
    sincosf(ang, &s, &c);
    size_t base = (size_t)row * DMODEL + h * DHEAD + i;
    float qa = q[base], qb = q[base + 32];
    q[base] = qa * c - qb * s;
    q[base + 32] = qb * c + qa * s;
    float ka = k[base], kb2 = k[base + 32];
    k[base] = ka * c - kb2 * s;
    k[base + 32] = kb2 * c + ka * s;
}

// ---------------- mean over tokens ----------------
__global__ void mean_kernel(const float* __restrict__ n2, float* __restrict__ g) {
    int b = blockIdx.y;
    int d = blockIdx.x * 256 + threadIdx.x;
    const float* p = n2 + (size_t)b * TSEQ * DMODEL + d;
    float s = 0.f;
    for (int t = 0; t < TSEQ; t++) s += p[(size_t)t * DMODEL];
    g[b * DMODEL + d] = s * (1.f / TSEQ);
}

// ---------------- alpha/beta tiny MLP ----------------
__global__ void ab_kernel(const float* __restrict__ g, const float* __restrict__ fc1,
                          const float* __restrict__ fc2, float* __restrict__ ab) {
    __shared__ float hs[BATCH][ABH];
    int tid = threadIdx.x;
    int b = tid >> 5, hh = tid & 31;
    float s = 0.f;
    for (int d = 0; d < DMODEL; d++) s += g[b * DMODEL + d] * fc1[hh * DMODEL + d];
    hs[b][hh] = fmaxf(s, 0.f);
    __syncthreads();
    if (tid < 2 * BATCH) {
        int bb = tid >> 1, o = tid & 1;
        float s2 = 0.f;
#pragma unroll
        for (int j = 0; j < ABH; j++) s2 += hs[bb][j] * fc2[o * ABH + j];
        ab[bb * 2 + o] = 1.f / (1.f + expf(-s2));
    }
}

// ---------------- final combine ----------------
__global__ void combine_kernel(const float* __restrict__ x1, const float* __restrict__ ffn,
                               const float* __restrict__ proj, const float* __restrict__ ab,
                               float* __restrict__ out) {
    size_t idx = (size_t)blockIdx.x * blockDim.x + threadIdx.x;
    if (idx >= (size_t)BT * DMODEL) return;
    int b = (int)(idx >> 21);
    out[idx] = x1[idx] + ab[b * 2] * ffn[idx] + ab[b * 2 + 1] * proj[idx];
}

// ---------------- launch ----------------
extern "C" void kernel_launch(void* const* d_in, const int* in_sizes, int n_in,
                              void* d_out, int out_size) {
    const float* x       = (const float*)d_in[0];
    const float* norm1_w = (const float*)d_in[2];
    const float* Wq      = (const float*)d_in[3];
    const float* Wk      = (const float*)d_in[4];
    const float* Wv      = (const float*)d_in[5];
    const float* Wo      = (const float*)d_in[6];
    const float* norm2_w = (const float*)d_in[7];
    const float* w1      = (const float*)d_in[8];
    const float* w2      = (const float*)d_in[9];
    const float* fc1     = (const float*)d_in[10];
    const float* fc2     = (const float*)d_in[11];
    const float* down    = (const float*)d_in[12];
    const float* up      = (const float*)d_in[13];
    float* out = (float*)d_out;

    float *xn1, *q, *k, *v, *att, *x1, *n2, *hid, *ffn, *ph, *proj, *gvec, *ab;
    cudaGetSymbolAddress((void**)&xn1,  g_xn1);
    cudaGetSymbolAddress((void**)&q,    g_q);
    cudaGetSymbolAddress((void**)&k,    g_k);
    cudaGetSymbolAddress((void**)&v,    g_v);
    cudaGetSymbolAddress((void**)&att,  g_att);
    cudaGetSymbolAddress((void**)&x1,   g_x1);
    cudaGetSymbolAddress((void**)&n2,   g_n2);
    cudaGetSymbolAddress((void**)&hid,  g_hid);
    cudaGetSymbolAddress((void**)&ffn,  g_ffn);
    cudaGetSymbolAddress((void**)&ph,   g_ph);
    cudaGetSymbolAddress((void**)&proj, g_proj);
    cudaGetSymbolAddress((void**)&gvec, g_gvec);
    cudaGetSymbolAddress((void**)&ab,   g_ab);

    static bool attr_set = false;
    if (!attr_set) {
        cudaFuncSetAttribute((const void*)attn_mma_kernel,
                             cudaFuncAttributeMaxDynamicSharedMemorySize, ATT_SMEM_BYTES);
        cudaFuncSetAttribute((const void*)gemm_mma<0, false>,
                             cudaFuncAttributeMaxDynamicSharedMemorySize, GEMM_SMEM_BYTES);
        cudaFuncSetAttribute((const void*)gemm_mma<0, true>,
                             cudaFuncAttributeMaxDynamicSharedMemorySize, GEMM_SMEM_BYTES);
        cudaFuncSetAttribute((const void*)gemm_mma<1, false>,
                             cudaFuncAttributeMaxDynamicSharedMemorySize, GEMM_SMEM_BYTES);
        cudaFuncSetAttribute((const void*)gemm_mma<2, false>,
                             cudaFuncAttributeMaxDynamicSharedMemorySize, GEMM_SMEM_BYTES);
        cudaFuncSetAttribute((const void*)gemm_mma_qkv,
                             cudaFuncAttributeMaxDynamicSharedMemorySize, GEMM_SMEM_BYTES);
        attr_set = true;
    }

    // 1. norm1
    rmsnorm_kernel<<<BT, 256>>>(x, norm1_w, xn1);
    // 2. fused QKV projections
    gemm_mma_qkv<<<dim3(24, BT / 128), 256, GEMM_SMEM_BYTES>>>(xn1, Wq, Wk, Wv, q, k, v);
    // 3. RoPE on q, k
    rope_kernel<<<(BT * 512 + 255) / 256, 256>>>(q, k);
    // 4. attention (tf32 mma.sync flash)
    attn_mma_kernel<<<dim3(TSEQ / 128, NHEADS, BATCH), 256, ATT_SMEM_BYTES>>>(q, k, v, att);
    // 5. output proj + residual
    gemm_mma<0, true><<<dim3(DMODEL / 128, BT / 128), 256, GEMM_SMEM_BYTES>>>(att, Wo, x, x1, DMODEL, DMODEL);
    // 6. norm2
    rmsnorm_kernel<<<BT, 256>>>(x1, norm2_w, n2);
    // 7. FFN
    gemm_mma<1, false><<<dim3(DFF / 128, BT / 128), 256, GEMM_SMEM_BYTES>>>(n2, w1, nullptr, hid, DFF, DMODEL);
    gemm_mma<0, false><<<dim3(DMODEL / 128, BT / 128), 256, GEMM_SMEM_BYTES>>>(hid, w2, nullptr, ffn, DMODEL, DFF);
    // 8. projection branch
    gemm_mma<2, false><<<dim3(BOT / 128, BT / 128), 256, GEMM_SMEM_BYTES>>>(n2, down, nullptr, ph, BOT, DMODEL);
    gemm_mma<0, false><<<dim3(DMODEL / 128, BT / 128), 256, GEMM_SMEM_BYTES>>>(ph, up, nullptr, proj, DMODEL, BOT);
    // 9. alpha/beta gate
    mean_kernel<<<dim3(DMODEL / 256, BATCH), 256>>>(n2, gvec);
    ab_kernel<<<1, 128>>>(gvec, fc1, fc2, ab);
    // 10. combine
    combine_kernel<<<(BT * DMODEL + 255) / 256, 256>>>(x1, ffn, proj, ab, out);
}

// round 6
// speedup vs baseline: 4.9379x; 1.0439x over previous
#include <cuda_runtime.h>
#include <cuda_bf16.h>
#include <cstdint>
#include <math.h>

// Problem sizes (fixed)
#define BATCH 4
#define TSEQ 2048
#define BT (BATCH*TSEQ)       // 8192
#define DMODEL 1024
#define NHEADS 16
#define DHEAD 64
#define DFF 4096
#define BOT 256
#define ABH 32
#define EPS 1e-6f

// -------- static scratch (allocation-free contract) --------
__device__ float g_xn1[BT*DMODEL];
__device__ float g_q[BT*DMODEL];
__device__ float g_k[BT*DMODEL];
__device__ float g_v[BT*DMODEL];
__device__ float g_att[BT*DMODEL];
__device__ float g_x1[BT*DMODEL];
__device__ float g_n2[BT*DMODEL];
__device__ float g_hid[BT*DFF];
__device__ float g_ffn[BT*DMODEL];
__device__ float g_ph[BT*BOT];
__device__ float g_proj[BT*DMODEL];
__device__ float g_gpart[8*BATCH*DMODEL];
__device__ float g_gvec[BATCH*DMODEL];
__device__ float g_ab[2*BATCH];

// ---------------- helpers ----------------
__device__ __forceinline__ uint32_t smem_u32(const void* p) {
    uint32_t a;
    asm("{ .reg .u64 t; cvta.to.shared.u64 t, %1; cvt.u32.u64 %0, t; }" : "=r"(a) : "l"(p));
    return a;
}
__device__ __forceinline__ uint32_t f2tf32(float f) {
    uint32_t u;
    asm("cvt.rna.tf32.f32 %0, %1;" : "=r"(u) : "f"(f));
    return u;
}
// round fp32 bit pattern at the tf32 boundary (HMMA truncates low 13 bits;
// adding half-ULP first gives round-half-away instead of biased truncation)
__device__ __forceinline__ uint32_t rnd(uint32_t u) { return u + 0x1000u; }

__device__ __forceinline__ void cp16(uint32_t daddr, const void* gptr) {
    asm volatile("cp.async.cg.shared.global [%0], [%1], 16;" :: "r"(daddr), "l"(gptr) : "memory");
}
#define CP_COMMIT() asm volatile("cp.async.commit_group;" ::: "memory")
#define CP_WAIT2()  asm volatile("cp.async.wait_group 2;" ::: "memory")
#define CP_WAIT0()  asm volatile("cp.async.wait_group 0;" ::: "memory")

__device__ __forceinline__ void mma_tf32(float& c0, float& c1, float& c2, float& c3,
                                         uint32_t a0, uint32_t a1, uint32_t a2, uint32_t a3,
                                         uint32_t b0, uint32_t b1) {
    asm volatile(
        "mma.sync.aligned.m16n8k8.row.col.f32.tf32.tf32.f32 "
        "{%0,%1,%2,%3}, {%4,%5,%6,%7}, {%8,%9}, {%0,%1,%2,%3};"
        : "+f"(c0), "+f"(c1), "+f"(c2), "+f"(c3)
        : "r"(a0), "r"(a1), "r"(a2), "r"(a3), "r"(b0), "r"(b1));
}

// ============ cp.async pipelined tf32 GEMM: C = A[M,K] @ B[N,K]^T (+epilogue) ============
#define SMS 36
#define STAGES 4
#define STAGE_FLOATS (128 * SMS * 2)
#define GEMM_SMEM_BYTES (STAGES * STAGE_FLOATS * 4)

template<int EPI, bool RESID>
__device__ __forceinline__ void gemm_body(const float* __restrict__ A,
                                          const float* __restrict__ B,
                                          const float* __restrict__ R,
                                          float* __restrict__ C,
                                          int N, int K, int bm, int bn) {
    extern __shared__ float gsmem[];
    const uint32_t sbase_u = smem_u32(gsmem);

    const int tid = threadIdx.x;
    const int warp = tid >> 5;
    const int lane = tid & 31;
    const int g = lane >> 2;
    const int tg = lane & 3;
    const int wm = (warp & 1) * 64;
    const int wn = (warp >> 1) * 32;

    const int NC = K >> 5;
    const int r_ld = tid >> 3;
    const int f4 = tid & 7;

    auto issue = [&](int kc) {
        const int stage = kc % STAGES;
        const uint32_t abase = sbase_u + stage * (STAGE_FLOATS * 4);
        const uint32_t bbase = abase + 128 * SMS * 4;
        const int k0 = kc << 5;
#pragma unroll
        for (int i = 0; i < 4; i++) {
            int r = r_ld + i * 32;
            uint32_t soff = (uint32_t)(r * SMS + f4 * 4) * 4;
            cp16(abase + soff, &A[(size_t)(bm + r) * K + k0 + f4 * 4]);
            cp16(bbase + soff, &B[(size_t)(bn + r) * K + k0 + f4 * 4]);
        }
    };

    float acc[4][4][4];
#pragma unroll
    for (int i = 0; i < 4; i++)
#pragma unroll
        for (int j = 0; j < 4; j++)
#pragma unroll
            for (int l = 0; l < 4; l++) acc[i][j][l] = 0.f;

#pragma unroll
    for (int s = 0; s < STAGES - 1; s++) {
        issue(s);
        CP_COMMIT();
    }

    for (int kc = 0; kc < NC; kc++) {
        CP_WAIT2();
        __syncthreads();
        if (kc + STAGES - 1 < NC) issue(kc + STAGES - 1);
        CP_COMMIT();

        const int stage = kc % STAGES;
        const uint32_t* sA = (const uint32_t*)(gsmem + stage * STAGE_FLOATS);
        const uint32_t* sB = sA + 128 * SMS;

#pragma unroll
        for (int ks = 0; ks < 4; ks++) {
            uint32_t af[4][4], bf[4][2];
#pragma unroll
            for (int mt = 0; mt < 4; mt++) {
                int row = wm + mt * 16 + g;
                int col = ks * 8 + tg;
                af[mt][0] = rnd(sA[row * SMS + col]);
                af[mt][1] = rnd(sA[(row + 8) * SMS + col]);
                af[mt][2] = rnd(sA[row * SMS + col + 4]);
                af[mt][3] = rnd(sA[(row + 8) * SMS + col + 4]);
            }
#pragma unroll
            for (int nt = 0; nt < 4; nt++) {
                int row = wn + nt * 8 + g;
                int col = ks * 8 + tg;
                bf[nt][0] = rnd(sB[row * SMS + col]);
                bf[nt][1] = rnd(sB[row * SMS + col + 4]);
            }
#pragma unroll
            for (int mt = 0; mt < 4; mt++)
#pragma unroll
                for (int nt = 0; nt < 4; nt++)
                    mma_tf32(acc[mt][nt][0], acc[mt][nt][1], acc[mt][nt][2], acc[mt][nt][3],
                             af[mt][0], af[mt][1], af[mt][2], af[mt][3],
                             bf[nt][0], bf[nt][1]);
        }
    }

#pragma unroll
    for (int mt = 0; mt < 4; mt++) {
#pragma unroll
        for (int nt = 0; nt < 4; nt++) {
            int row = bm + wm + mt * 16 + g;
            int col = bn + wn + nt * 8 + tg * 2;
#pragma unroll
            for (int half = 0; half < 2; half++) {
                int m = row + half * 8;
                float v0 = acc[mt][nt][half * 2 + 0];
                float v1 = acc[mt][nt][half * 2 + 1];
                if (EPI == 1) {
                    v0 = 0.5f * v0 * (1.f + erff(v0 * 0.70710678118f));
                    v1 = 0.5f * v1 * (1.f + erff(v1 * 0.70710678118f));
                }
                if (EPI == 2) { v0 = fmaxf(v0, 0.f); v1 = fmaxf(v1, 0.f); }
                if (RESID) {
                    float2 r2 = *reinterpret_cast<const float2*>(&R[(size_t)m * N + col]);
                    v0 += r2.x; v1 += r2.y;
                }
                *reinterpret_cast<float2*>(&C[(size_t)m * N + col]) = make_float2(v0, v1);
            }
        }
    }
}

template<int EPI, bool RESID>
__global__ void __launch_bounds__(256, 1) gemm_mma(const float* __restrict__ A,
                                                   const float* __restrict__ B,
                                                   const float* __restrict__ R,
                                                   float* __restrict__ C,
                                                   int N, int K) {
    gemm_body<EPI, RESID>(A, B, R, C, N, K, blockIdx.y * 128, blockIdx.x * 128);
}

__global__ void __launch_bounds__(256, 1) gemm_mma_qkv(const float* __restrict__ A,
                                                       const float* __restrict__ B0,
                                                       const float* __restrict__ B1,
                                                       const float* __restrict__ B2,
                                                       float* __restrict__ C0,
                                                       float* __restrict__ C1,
                                                       float* __restrict__ C2) {
    const int sel = blockIdx.x >> 3;
    const float* B = (sel == 0) ? B0 : (sel == 1) ? B1 : B2;
    float* C = (sel == 0) ? C0 : (sel == 1) ? C1 : C2;
    gemm_body<0, false>(A, B, nullptr, C, DMODEL, DMODEL,
                        blockIdx.y * 128, (blockIdx.x & 7) * 128);
}

// ============ tf32 mma.sync flash attention (causal, cp.async double-buffered) ============
#define ASTRIDE 68
#define ATT_QP (128*ASTRIDE)
#define ATT_TILE (64*ASTRIDE)
#define ATT_SMEM_BYTES ((ATT_QP + 4*ATT_TILE) * 4)

__global__ void __launch_bounds__(256) attn_mma_kernel(const float* __restrict__ Q,
                                                       const float* __restrict__ K,
                                                       const float* __restrict__ V,
                                                       float* __restrict__ O) {
    extern __shared__ uint32_t smem[];
    uint32_t* sQP = smem;                                 // 128 x 68 (Q tf32, later P tf32)
    const uint32_t sbase = smem_u32(smem);

    const int qt = (int)(gridDim.x - 1 - blockIdx.x);
    const int h = blockIdx.y;
    const int b = blockIdx.z;
    const int tid = threadIdx.x;
    const int w = tid >> 5;
    const int lane = tid & 31;
    const int g = lane >> 2;
    const int tg = lane & 3;
    const size_t headoff = (size_t)h * DHEAD;

    // issue cp.async load of K/V tile kb into buffer buf
    auto issue = [&](int kb, int buf) {
#pragma unroll
        for (int i = 0; i < 4; i++) {
            int e = tid + i * 256;
            int r = e >> 4, f4 = e & 15;
            size_t gb = ((size_t)(b * TSEQ + kb * 64 + r)) * DMODEL + headoff + f4 * 4;
            uint32_t soff = (uint32_t)(r * ASTRIDE + f4 * 4) * 4;
            cp16(sbase + (ATT_QP + buf * ATT_TILE) * 4 + soff, &K[gb]);
            cp16(sbase + (ATT_QP + (2 + buf) * ATT_TILE) * 4 + soff, &V[gb]);
        }
    };

    // start first K/V load immediately
    issue(0, 0);
    CP_COMMIT();

    // fill Q tile (scaled 1/sqrt(64), tf32-rounded)
#pragma unroll
    for (int i = 0; i < 8; i++) {
        int e = tid + i * 256;
        int r = e >> 4, f4 = e & 15;
        const float4 v = *reinterpret_cast<const float4*>(
            &Q[((size_t)(b * TSEQ + qt * 128 + r)) * DMODEL + headoff + f4 * 4]);
        uint4 t;
        t.x = f2tf32(v.x * 0.125f); t.y = f2tf32(v.y * 0.125f);
        t.z = f2tf32(v.z * 0.125f); t.w = f2tf32(v.w * 0.125f);
        *reinterpret_cast<uint4*>(&sQP[r * ASTRIDE + f4 * 4]) = t;
    }
    __syncthreads();

    const int r0 = w * 16 + g;
    uint32_t qf[8][4];
#pragma unroll
    for (int ks = 0; ks < 8; ks++) {
        int c = ks * 8 + tg;
        qf[ks][0] = sQP[r0 * ASTRIDE + c];
        qf[ks][1] = sQP[(r0 + 8) * ASTRIDE + c];
        qf[ks][2] = sQP[r0 * ASTRIDE + c + 4];
        qf[ks][3] = sQP[(r0 + 8) * ASTRIDE + c + 4];
    }

    float o[8][4];
#pragma unroll
    for (int nt = 0; nt < 8; nt++)
#pragma unroll
        for (int l = 0; l < 4; l++) o[nt][l] = 0.f;
    float m0 = -1e30f, m1 = -1e30f, l0 = 0.f, l1 = 0.f;

    const int rowg = qt * 128 + w * 16 + g;
    const int kbmax = 2 * qt + 1;

    for (int kb = 0; kb <= kbmax; kb++) {
        CP_WAIT0();
        __syncthreads();
        if (kb < kbmax) {
            issue(kb + 1, (kb + 1) & 1);
            CP_COMMIT();
        }
        if (kb * 64 > qt * 128 + w * 16 + 15) continue;

        const uint32_t* sK = smem + ATT_QP + (kb & 1) * ATT_TILE;
        const uint32_t* sV = smem + ATT_QP + (2 + (kb & 1)) * ATT_TILE;

        // ---- S = Q K^T ----
        float s[8][4];
#pragma unroll
        for (int nt = 0; nt < 8; nt++)
#pragma unroll
            for (int l = 0; l < 4; l++) s[nt][l] = 0.f;
#pragma unroll
        for (int ks = 0; ks < 8; ks++) {
            uint32_t bf[8][2];
#pragma unroll
            for (int nt = 0; nt < 8; nt++) {
                bf[nt][0] = rnd(sK[(nt * 8 + g) * ASTRIDE + ks * 8 + tg]);
                bf[nt][1] = rnd(sK[(nt * 8 + g) * ASTRIDE + ks * 8 + tg + 4]);
            }
#pragma unroll
            for (int nt = 0; nt < 8; nt++)
                mma_tf32(s[nt][0], s[nt][1], s[nt][2], s[nt][3],
                         qf[ks][0], qf[ks][1], qf[ks][2], qf[ks][3],
                         bf[nt][0], bf[nt][1]);
        }

        // ---- causal mask ----
        if (kb * 64 + 63 > rowg) {
#pragma unroll
            for (int nt = 0; nt < 8; nt++) {
                int c = kb * 64 + nt * 8 + 2 * tg;
                if (c > rowg) s[nt][0] = -1e30f;
                if (c + 1 > rowg) s[nt][1] = -1e30f;
                if (c > rowg + 8) s[nt][2] = -1e30f;
                if (c + 1 > rowg + 8) s[nt][3] = -1e30f;
            }
        }

        // ---- online softmax ----
        float mx0 = -1e30f, mx1 = -1e30f;
#pragma unroll
        for (int nt = 0; nt < 8; nt++) {
            mx0 = fmaxf(mx0, fmaxf(s[nt][0], s[nt][1]));
            mx1 = fmaxf(mx1, fmaxf(s[nt][2], s[nt][3]));
        }
        mx0 = fmaxf(mx0, __shfl_xor_sync(0xffffffffu, mx0, 1));
        mx0 = fmaxf(mx0, __shfl_xor_sync(0xffffffffu, mx0, 2));
        mx1 = fmaxf(mx1, __shfl_xor_sync(0xffffffffu, mx1, 1));
        mx1 = fmaxf(mx1, __shfl_xor_sync(0xffffffffu, mx1, 2));
        float nm0 = fmaxf(m0, mx0), nm1 = fmaxf(m1, mx1);
        float sc0 = __expf(m0 - nm0), sc1 = __expf(m1 - nm1);
        m0 = nm0; m1 = nm1;
        float sum0 = 0.f, sum1 = 0.f;
#pragma unroll
        for (int nt = 0; nt < 8; nt++) {
            float p0 = __expf(s[nt][0] - nm0);
            float p1 = __expf(s[nt][1] - nm0);
            float p2 = __expf(s[nt][2] - nm1);
            float p3 = __expf(s[nt][3] - nm1);
            sum0 += p0 + p1; sum1 += p2 + p3;
            uint2 u01 = make_uint2(f2tf32(p0), f2tf32(p1));
            uint2 u23 = make_uint2(f2tf32(p2), f2tf32(p3));
            *reinterpret_cast<uint2*>(&sQP[r0 * ASTRIDE + nt * 8 + 2 * tg]) = u01;
            *reinterpret_cast<uint2*>(&sQP[(r0 + 8) * ASTRIDE + nt * 8 + 2 * tg]) = u23;
        }
        sum0 += __shfl_xor_sync(0xffffffffu, sum0, 1);
        sum0 += __shfl_xor_sync(0xffffffffu, sum0, 2);
        sum1 += __shfl_xor_sync(0xffffffffu, sum1, 1);
        sum1 += __shfl_xor_sync(0xffffffffu, sum1, 2);
        l0 = l0 * sc0 + sum0;
        l1 = l1 * sc1 + sum1;
#pragma unroll
        for (int nt = 0; nt < 8; nt++) {
            o[nt][0] *= sc0; o[nt][1] *= sc0;
            o[nt][2] *= sc1; o[nt][3] *= sc1;
        }
        __syncwarp();

        // ---- O += P V ----
#pragma unroll
        for (int ks = 0; ks < 8; ks++) {
            uint32_t a0 = sQP[r0 * ASTRIDE + ks * 8 + tg];
            uint32_t a1 = sQP[(r0 + 8) * ASTRIDE + ks * 8 + tg];
            uint32_t a2 = sQP[r0 * ASTRIDE + ks * 8 + tg + 4];
            uint32_t a3 = sQP[(r0 + 8) * ASTRIDE + ks * 8 + tg + 4];
#pragma unroll
            for (int nt = 0; nt < 8; nt++) {
                uint32_t b0 = rnd(sV[(ks * 8 + tg) * ASTRIDE + nt * 8 + g]);
                uint32_t b1 = rnd(sV[(ks * 8 + tg + 4) * ASTRIDE + nt * 8 + g]);
                mma_tf32(o[nt][0], o[nt][1], o[nt][2], o[nt][3], a0, a1, a2, a3, b0, b1);
            }
        }
    }

    float il0 = 1.f / l0, il1 = 1.f / l1;
    const size_t rg = (size_t)(b * TSEQ + qt * 128 + w * 16 + g);
#pragma unroll
    for (int nt = 0; nt < 8; nt++) {
        size_t col = headoff + nt * 8 + 2 * tg;
        *reinterpret_cast<float2*>(&O[rg * DMODEL + col]) =
            make_float2(o[nt][0] * il0, o[nt][1] * il0);
        *reinterpret_cast<float2*>(&O[(rg + 8) * DMODEL + col]) =
            make_float2(o[nt][2] * il1, o[nt][3] * il1);
    }
}

// ---------------- RMSNorm ----------------
__global__ void __launch_bounds__(256) rmsnorm_kernel(const float* __restrict__ x,
                                                      const float* __restrict__ w,
                                                      float* __restrict__ out) {
    const int row = blockIdx.x;
    const float* xr = x + (size_t)row * DMODEL;
    float* orow = out + (size_t)row * DMODEL;
    const int tid = threadIdx.x;

    float vals[4];
    float local = 0.f;
#pragma unroll
    for (int i = 0; i < 4; i++) {
        float v = xr[tid + i * 256];
        vals[i] = v;
        local += v * v;
    }
    for (int off = 16; off; off >>= 1) local += __shfl_xor_sync(0xffffffffu, local, off);
    __shared__ float red[8];
    __shared__ float rinv_s;
    int warp = tid >> 5, lane = tid & 31;
    if (lane == 0) red[warp] = local;
    __syncthreads();
    if (tid == 0) {
        float tot = 0.f;
#pragma unroll
        for (int i = 0; i < 8; i++) tot += red[i];
        rinv_s = rsqrtf(tot * (1.0f / DMODEL) + EPS);
    }
    __syncthreads();
    float rinv = rinv_s;
#pragma unroll
    for (int i = 0; i < 4; i++) {
        int c = tid + i * 256;
        orow[c] = vals[i] * rinv * w[c];
    }
}

// ---------------- RoPE (in place on q and k) ----------------
__global__ void rope_kernel(float* __restrict__ q, float* __restrict__ k) {
    int idx = blockIdx.x * blockDim.x + threadIdx.x;
    if (idx >= BT * 512) return;
    int row = idx >> 9;
    int p = idx & 511;
    int h = p >> 5;
    int i = p & 31;
    int t = row & (TSEQ - 1);
    float inv = expf(-((float)(2 * i) / 64.f) * 9.210340371976184f);
    float ang = (float)t * inv;
    float s, c;
    sincosf(ang, &s, &c);
    size_t base = (size_t)row * DMODEL + h * DHEAD + i;
    float qa = q[base], qb = q[base + 32];
    q[base] = qa * c - qb * s;
    q[base + 32] = qb * c + qa * s;
    float ka = k[base], kb2 = k[base + 32];
    k[base] = ka * c - kb2 * s;
    k[base + 32] = kb2 * c + ka * s;
}

// ---------------- mean over tokens (two-pass, deterministic) ----------------
__global__ void mean_pass1(const float* __restrict__ n2, float* __restrict__ gpart) {
    int b = blockIdx.y;
    int tc = blockIdx.z;
    int d = blockIdx.x * 256 + threadIdx.x;
    const float* p = n2 + (size_t)b * TSEQ * DMODEL + (size_t)tc * 256 * DMODEL + d;
    float s = 0.f;
    for (int t = 0; t < 256; t++) s += p[(size_t)t * DMODEL];
    gpart[((size_t)tc * BATCH + b) * DMODEL + d] = s;
}
__global__ void mean_pass2(const float* __restrict__ gpart, float* __restrict__ g) {
    int i = blockIdx.x * 256 + threadIdx.x;   // over BATCH*DMODEL
    float s = 0.f;
#pragma unroll
    for (int tc = 0; tc < 8; tc++) s += gpart[(size_t)tc * BATCH * DMODEL + i];
    g[i] = s * (1.f / TSEQ);
}

// ---------------- alpha/beta tiny MLP ----------------
__global__ void ab_kernel(const float* __restrict__ g, const float* __restrict__ fc1,
                          const float* __restrict__ fc2, float* __restrict__ ab) {
    __shared__ float hs[BATCH][ABH];
    int tid = threadIdx.x;
    int b = tid >> 5, hh = tid & 31;
    float s = 0.f;
    for (int d = 0; d < DMODEL; d++) s += g[b * DMODEL + d] * fc1[hh * DMODEL + d];
    hs[b][hh] = fmaxf(s, 0.f);
    __syncthreads();
    if (tid < 2 * BATCH) {
        int bb = tid >> 1, o = tid & 1;
        float s2 = 0.f;
#pragma unroll
        for (int j = 0; j < ABH; j++) s2 += hs[bb][j] * fc2[o * ABH + j];
        ab[bb * 2 + o] = 1.f / (1.f + expf(-s2));
    }
}

// ---------------- final combine ----------------
__global__ void combine_kernel(const float* __restrict__ x1, const float* __restrict__ ffn,
                               const float* __restrict__ proj, const float* __restrict__ ab,
                               float* __restrict__ out) {
    size_t idx = (size_t)blockIdx.x * blockDim.x + threadIdx.x;
    if (idx >= (size_t)BT * DMODEL) return;
    int b = (int)(idx >> 21);
    out[idx] = x1[idx] + ab[b * 2] * ffn[idx] + ab[b * 2 + 1] * proj[idx];
}

// ---------------- launch ----------------
extern "C" void kernel_launch(void* const* d_in, const int* in_sizes, int n_in,
                              void* d_out, int out_size) {
    const float* x       = (const float*)d_in[0];
    const float* norm1_w = (const float*)d_in[2];
    const float* Wq      = (const float*)d_in[3];
    const float* Wk      = (const float*)d_in[4];
    const float* Wv      = (const float*)d_in[5];
    const float* Wo      = (const float*)d_in[6];
    const float* norm2_w = (const float*)d_in[7];
    const float* w1      = (const float*)d_in[8];
    const float* w2      = (const float*)d_in[9];
    const float* fc1     = (const float*)d_in[10];
    const float* fc2     = (const float*)d_in[11];
    const float* down    = (const float*)d_in[12];
    const float* up      = (const float*)d_in[13];
    float* out = (float*)d_out;

    float *xn1, *q, *k, *v, *att, *x1, *n2, *hid, *ffn, *ph, *proj, *gpart, *gvec, *ab;
    cudaGetSymbolAddress((void**)&xn1,   g_xn1);
    cudaGetSymbolAddress((void**)&q,     g_q);
    cudaGetSymbolAddress((void**)&k,     g_k);
    cudaGetSymbolAddress((void**)&v,     g_v);
    cudaGetSymbolAddress((void**)&att,   g_att);
    cudaGetSymbolAddress((void**)&x1,    g_x1);
    cudaGetSymbolAddress((void**)&n2,    g_n2);
    cudaGetSymbolAddress((void**)&hid,   g_hid);
    cudaGetSymbolAddress((void**)&ffn,   g_ffn);
    cudaGetSymbolAddress((void**)&ph,    g_ph);
    cudaGetSymbolAddress((void**)&proj,  g_proj);
    cudaGetSymbolAddress((void**)&gpart, g_gpart);
    cudaGetSymbolAddress((void**)&gvec,  g_gvec);
    cudaGetSymbolAddress((void**)&ab,    g_ab);

    static bool attr_set = false;
    if (!attr_set) {
        cudaFuncSetAttribute((const void*)attn_mma_kernel,
                             cudaFuncAttributeMaxDynamicSharedMemorySize, ATT_SMEM_BYTES);
        cudaFuncSetAttribute((const void*)gemm_mma<0, false>,
                             cudaFuncAttributeMaxDynamicSharedMemorySize, GEMM_SMEM_BYTES);
        cudaFuncSetAttribute((const void*)gemm_mma<0, true>,
                             cudaFuncAttributeMaxDynamicSharedMemorySize, GEMM_SMEM_BYTES);
        cudaFuncSetAttribute((const void*)gemm_mma<1, false>,
                             cudaFuncAttributeMaxDynamicSharedMemorySize, GEMM_SMEM_BYTES);
        cudaFuncSetAttribute((const void*)gemm_mma<2, false>,
                             cudaFuncAttributeMaxDynamicSharedMemorySize, GEMM_SMEM_BYTES);
        cudaFuncSetAttribute((const void*)gemm_mma_qkv,
                             cudaFuncAttributeMaxDynamicSharedMemorySize, GEMM_SMEM_BYTES);
        attr_set = true;
    }

    // 1. norm1
    rmsnorm_kernel<<<BT, 256>>>(x, norm1_w, xn1);
    // 2. fused QKV projections
    gemm_mma_qkv<<<dim3(24, BT / 128), 256, GEMM_SMEM_BYTES>>>(xn1, Wq, Wk, Wv, q, k, v);
    // 3. RoPE on q, k
    rope_kernel<<<(BT * 512 + 255) / 256, 256>>>(q, k);
    // 4. attention (tf32 mma.sync flash, cp.async pipelined)
    attn_mma_kernel<<<dim3(TSEQ / 128, NHEADS, BATCH), 256, ATT_SMEM_BYTES>>>(q, k, v, att);
    // 5. output proj + residual
    gemm_mma<0, true><<<dim3(DMODEL / 128, BT / 128), 256, GEMM_SMEM_BYTES>>>(att, Wo, x, x1, DMODEL, DMODEL);
    // 6. norm2
    rmsnorm_kernel<<<BT, 256>>>(x1, norm2_w, n2);
    // 7. FFN
    gemm_mma<1, false><<<dim3(DFF / 128, BT / 128), 256, GEMM_SMEM_BYTES>>>(n2, w1, nullptr, hid, DFF, DMODEL);
    gemm_mma<0, false><<<dim3(DMODEL / 128, BT / 128), 256, GEMM_SMEM_BYTES>>>(hid, w2, nullptr, ffn, DMODEL, DFF);
    // 8. projection branch
    gemm_mma<2, false><<<dim3(BOT / 128, BT / 128), 256, GEMM_SMEM_BYTES>>>(n2, down, nullptr, ph, BOT, DMODEL);
    gemm_mma<0, false><<<dim3(DMODEL / 128, BT / 128), 256, GEMM_SMEM_BYTES>>>(ph, up, nullptr, proj, DMODEL, BOT);
    // 9. alpha/beta gate (two-pass mean, deterministic)
    mean_pass1<<<dim3(DMODEL / 256, BATCH, 8), 256>>>(n2, gpart);
    mean_pass2<<<BATCH * DMODEL / 256, 256>>>(gpart, gvec);
    ab_kernel<<<1, 128>>>(gvec, fc1, fc2, ab);
    // 10. combine
    combine_kernel<<<(BT * DMODEL + 255) / 256, 256>>>(x1, ffn, proj, ab, out);
}

// round 7
// speedup vs baseline: 7.0647x; 1.4307x over previous
#include <cuda_runtime.h>
#include <cuda_fp16.h>
#include <cuda_bf16.h>
#include <cstdint>
#include <math.h>

// Problem sizes (fixed)
#define BATCH 4
#define TSEQ 2048
#define BT (BATCH*TSEQ)       // 8192
#define DMODEL 1024
#define NHEADS 16
#define DHEAD 64
#define DFF 4096
#define BOT 256
#define ABH 32
#define EPS 1e-6f

// -------- static scratch (allocation-free contract) --------
__device__ __align__(256) __half g_xn1h[BT*DMODEL];
__device__ float g_q[BT*DMODEL];
__device__ float g_k[BT*DMODEL];
__device__ float g_v[BT*DMODEL];
__device__ __align__(256) __half g_atth[BT*DMODEL];
__device__ float g_x1[BT*DMODEL];
__device__ __align__(256) __half g_n2h[BT*DMODEL];
__device__ __align__(256) __half g_hidh[BT*DFF];
__device__ float g_ffn[BT*DMODEL];
__device__ __align__(256) __half g_phh[BT*BOT];
__device__ float g_proj[BT*DMODEL];
__device__ float g_gpart[8*BATCH*DMODEL];
__device__ float g_gvec[BATCH*DMODEL];
__device__ float g_ab[2*BATCH];
// fp16 weights (converted per call)
__device__ __align__(256) __half g_hWq[DMODEL*DMODEL];
__device__ __align__(256) __half g_hWk[DMODEL*DMODEL];
__device__ __align__(256) __half g_hWv[DMODEL*DMODEL];
__device__ __align__(256) __half g_hWo[DMODEL*DMODEL];
__device__ __align__(256) __half g_hw1[DFF*DMODEL];
__device__ __align__(256) __half g_hw2[DMODEL*DFF];
__device__ __align__(256) __half g_hdown[BOT*DMODEL];
__device__ __align__(256) __half g_hup[DMODEL*BOT];

// ---------------- helpers ----------------
__device__ __forceinline__ uint32_t smem_u32(const void* p) {
    uint32_t a;
    asm("{ .reg .u64 t; cvta.to.shared.u64 t, %1; cvt.u32.u64 %0, t; }" : "=r"(a) : "l"(p));
    return a;
}
__device__ __forceinline__ uint32_t f2tf32(float f) {
    uint32_t u;
    asm("cvt.rna.tf32.f32 %0, %1;" : "=r"(u) : "f"(f));
    return u;
}
__device__ __forceinline__ uint32_t rnd(uint32_t u) { return u + 0x1000u; }

__device__ __forceinline__ void cp16(uint32_t daddr, const void* gptr) {
    asm volatile("cp.async.cg.shared.global [%0], [%1], 16;" :: "r"(daddr), "l"(gptr) : "memory");
}
#define CP_COMMIT() asm volatile("cp.async.commit_group;" ::: "memory")
#define CP_WAIT2()  asm volatile("cp.async.wait_group 2;" ::: "memory")
#define CP_WAIT0()  asm volatile("cp.async.wait_group 0;" ::: "memory")

__device__ __forceinline__ void mma_tf32(float& c0, float& c1, float& c2, float& c3,
                                         uint32_t a0, uint32_t a1, uint32_t a2, uint32_t a3,
                                         uint32_t b0, uint32_t b1) {
    asm volatile(
        "mma.sync.aligned.m16n8k8.row.col.f32.tf32.tf32.f32 "
        "{%0,%1,%2,%3}, {%4,%5,%6,%7}, {%8,%9}, {%0,%1,%2,%3};"
        : "+f"(c0), "+f"(c1), "+f"(c2), "+f"(c3)
        : "r"(a0), "r"(a1), "r"(a2), "r"(a3), "r"(b0), "r"(b1));
}
__device__ __forceinline__ void mma_f16(float& c0, float& c1, float& c2, float& c3,
                                        uint32_t a0, uint32_t a1, uint32_t a2, uint32_t a3,
                                        uint32_t b0, uint32_t b1) {
    asm volatile(
        "mma.sync.aligned.m16n8k16.row.col.f32.f16.f16.f32 "
        "{%0,%1,%2,%3}, {%4,%5,%6,%7}, {%8,%9}, {%0,%1,%2,%3};"
        : "+f"(c0), "+f"(c1), "+f"(c2), "+f"(c3)
        : "r"(a0), "r"(a1), "r"(a2), "r"(a3), "r"(b0), "r"(b1));
}
__device__ __forceinline__ void ldsm4(uint32_t& r0, uint32_t& r1, uint32_t& r2, uint32_t& r3,
                                      uint32_t a) {
    asm volatile("ldmatrix.sync.aligned.m8n8.x4.shared.b16 {%0,%1,%2,%3}, [%4];"
                 : "=r"(r0), "=r"(r1), "=r"(r2), "=r"(r3) : "r"(a));
}

// ---------------- fp32 -> fp16 converter ----------------
__global__ void f2h_kernel(const float4* __restrict__ s, uint2* __restrict__ d, int n4) {
    int i = blockIdx.x * 256 + threadIdx.x;
    if (i >= n4) return;
    float4 v = s[i];
    __half2 lo = __floats2half2_rn(v.x, v.y);
    __half2 hi = __floats2half2_rn(v.z, v.w);
    d[i] = make_uint2(*(uint32_t*)&lo, *(uint32_t*)&hi);
}

// ============ fp16 mma.sync GEMM: C = A[M,K] @ B[N,K]^T (+epilogue) ============
// CTA 128x128, BK=32 (2 k16-steps), 4-stage cp.async, ldmatrix fragments.
// EPI: 0 none, 1 GELU, 2 ReLU. RESID adds fp32 R. OUTH: fp16 output.
#define SMSH 40                      // halves per smem row
#define HSTAGE_BYTES (128 * SMSH * 2 * 2)   // A+B per stage = 20480 B
#define GEMMH_SMEM (4 * HSTAGE_BYTES)       // 81920 B

template<int EPI, bool RESID, bool OUTH>
__device__ __forceinline__ void gemmh_body(const __half* __restrict__ A,
                                           const __half* __restrict__ B,
                                           const float* __restrict__ R,
                                           void* __restrict__ Cv,
                                           int N, int K, int bm, int bn) {
    extern __shared__ __half hsmem[];
    const uint32_t sbase = smem_u32(hsmem);

    const int tid = threadIdx.x;
    const int warp = tid >> 5;
    const int lane = tid & 31;
    const int g = lane >> 2;
    const int tg = lane & 3;
    const int sub = lane >> 3;     // 0..3
    const int rin = lane & 7;
    const int wm = (warp & 1) * 64;
    const int wn = (warp >> 1) * 32;

    const int NC = K >> 5;

    auto issue = [&](int kc) {
        const int stage = kc & 3;
        const uint32_t ab = sbase + stage * HSTAGE_BYTES;
        const uint32_t bb = ab + 128 * SMSH * 2;
        const int k0 = kc << 5;
#pragma unroll
        for (int i = 0; i < 2; i++) {
            int e = tid + i * 256;
            int r = e >> 2, q4 = e & 3;
            uint32_t soff = (uint32_t)(r * SMSH + q4 * 8) * 2;
            cp16(ab + soff, &A[(size_t)(bm + r) * K + k0 + q4 * 8]);
            cp16(bb + soff, &B[(size_t)(bn + r) * K + k0 + q4 * 8]);
        }
    };

    float acc[4][4][4];
#pragma unroll
    for (int i = 0; i < 4; i++)
#pragma unroll
        for (int j = 0; j < 4; j++)
#pragma unroll
            for (int l = 0; l < 4; l++) acc[i][j][l] = 0.f;

#pragma unroll
    for (int s = 0; s < 3; s++) {
        issue(s);
        CP_COMMIT();
    }

    for (int kc = 0; kc < NC; kc++) {
        CP_WAIT2();
        __syncthreads();
        if (kc + 3 < NC) issue(kc + 3);
        CP_COMMIT();

        const uint32_t sA = sbase + (kc & 3) * HSTAGE_BYTES;
        const uint32_t sB = sA + 128 * SMSH * 2;

#pragma unroll
        for (int ks = 0; ks < 2; ks++) {
            uint32_t af[4][4], bf[4][2];
#pragma unroll
            for (int mt = 0; mt < 4; mt++) {
                int row = wm + mt * 16 + rin + (sub & 1) * 8;
                int col = ks * 16 + (sub >> 1) * 8;
                ldsm4(af[mt][0], af[mt][1], af[mt][2], af[mt][3],
                      sA + (uint32_t)(row * SMSH + col) * 2);
            }
#pragma unroll
            for (int p = 0; p < 2; p++) {
                int nrow = wn + (2 * p + (sub >> 1)) * 8 + rin;
                int ncol = ks * 16 + (sub & 1) * 8;
                ldsm4(bf[2 * p][0], bf[2 * p][1], bf[2 * p + 1][0], bf[2 * p + 1][1],
                      sB + (uint32_t)(nrow * SMSH + ncol) * 2);
            }
#pragma unroll
            for (int mt = 0; mt < 4; mt++)
#pragma unroll
                for (int nt = 0; nt < 4; nt++)
                    mma_f16(acc[mt][nt][0], acc[mt][nt][1], acc[mt][nt][2], acc[mt][nt][3],
                            af[mt][0], af[mt][1], af[mt][2], af[mt][3],
                            bf[nt][0], bf[nt][1]);
        }
    }

#pragma unroll
    for (int mt = 0; mt < 4; mt++) {
#pragma unroll
        for (int nt = 0; nt < 4; nt++) {
            int row = bm + wm + mt * 16 + g;
            int col = bn + wn + nt * 8 + tg * 2;
#pragma unroll
            for (int half_i = 0; half_i < 2; half_i++) {
                int m = row + half_i * 8;
                float v0 = acc[mt][nt][half_i * 2 + 0];
                float v1 = acc[mt][nt][half_i * 2 + 1];
                if (EPI == 1) {
                    v0 = 0.5f * v0 * (1.f + erff(v0 * 0.70710678118f));
                    v1 = 0.5f * v1 * (1.f + erff(v1 * 0.70710678118f));
                }
                if (EPI == 2) { v0 = fmaxf(v0, 0.f); v1 = fmaxf(v1, 0.f); }
                if (RESID) {
                    float2 r2 = *reinterpret_cast<const float2*>(&R[(size_t)m * N + col]);
                    v0 += r2.x; v1 += r2.y;
                }
                if (OUTH) {
                    __half2 hv = __floats2half2_rn(v0, v1);
                    *reinterpret_cast<__half2*>(&((__half*)Cv)[(size_t)m * N + col]) = hv;
                } else {
                    *reinterpret_cast<float2*>(&((float*)Cv)[(size_t)m * N + col]) =
                        make_float2(v0, v1);
                }
            }
        }
    }
}

template<int EPI, bool RESID, bool OUTH>
__global__ void __launch_bounds__(256, 1) gemmh(const __half* __restrict__ A,
                                                const __half* __restrict__ B,
                                                const float* __restrict__ R,
                                                void* __restrict__ C,
                                                int N, int K) {
    gemmh_body<EPI, RESID, OUTH>(A, B, R, C, N, K, blockIdx.y * 128, blockIdx.x * 128);
}

// fused QKV: grid.x = 24 (8 n-tiles x 3 matrices), fp32 out
__global__ void __launch_bounds__(256, 1) gemmh_qkv(const __half* __restrict__ A,
                                                    const __half* __restrict__ B0,
                                                    const __half* __restrict__ B1,
                                                    const __half* __restrict__ B2,
                                                    float* __restrict__ C0,
                                                    float* __restrict__ C1,
                                                    float* __restrict__ C2) {
    const int sel = blockIdx.x >> 3;
    const __half* B = (sel == 0) ? B0 : (sel == 1) ? B1 : B2;
    float* C = (sel == 0) ? C0 : (sel == 1) ? C1 : C2;
    gemmh_body<0, false, false>(A, B, nullptr, C, DMODEL, DMODEL,
                                blockIdx.y * 128, (blockIdx.x & 7) * 128);
}

// ============ tf32 mma.sync flash attention (causal, cp.async double-buffered) ============
#define ASTRIDE 68
#define ATT_QP (128*ASTRIDE)
#define ATT_TILE (64*ASTRIDE)
#define ATT_SMEM_BYTES ((ATT_QP + 4*ATT_TILE) * 4)

__global__ void __launch_bounds__(256) attn_mma_kernel(const float* __restrict__ Q,
                                                       const float* __restrict__ K,
                                                       const float* __restrict__ V,
                                                       __half* __restrict__ O) {
    extern __shared__ uint32_t smem[];
    uint32_t* sQP = smem;
    const uint32_t sbase = smem_u32(smem);

    const int qt = (int)(gridDim.x - 1 - blockIdx.x);
    const int h = blockIdx.y;
    const int b = blockIdx.z;
    const int tid = threadIdx.x;
    const int w = tid >> 5;
    const int lane = tid & 31;
    const int g = lane >> 2;
    const int tg = lane & 3;
    const size_t headoff = (size_t)h * DHEAD;

    auto issue = [&](int kb, int buf) {
#pragma unroll
        for (int i = 0; i < 4; i++) {
            int e = tid + i * 256;
            int r = e >> 4, f4 = e & 15;
            size_t gb = ((size_t)(b * TSEQ + kb * 64 + r)) * DMODEL + headoff + f4 * 4;
            uint32_t soff = (uint32_t)(r * ASTRIDE + f4 * 4) * 4;
            cp16(sbase + (ATT_QP + buf * ATT_TILE) * 4 + soff, &K[gb]);
            cp16(sbase + (ATT_QP + (2 + buf) * ATT_TILE) * 4 + soff, &V[gb]);
        }
    };

    issue(0, 0);
    CP_COMMIT();

#pragma unroll
    for (int i = 0; i < 8; i++) {
        int e = tid + i * 256;
        int r = e >> 4, f4 = e & 15;
        const float4 v = *reinterpret_cast<const float4*>(
            &Q[((size_t)(b * TSEQ + qt * 128 + r)) * DMODEL + headoff + f4 * 4]);
        uint4 t;
        t.x = f2tf32(v.x * 0.125f); t.y = f2tf32(v.y * 0.125f);
        t.z = f2tf32(v.z * 0.125f); t.w = f2tf32(v.w * 0.125f);
        *reinterpret_cast<uint4*>(&sQP[r * ASTRIDE + f4 * 4]) = t;
    }
    __syncthreads();

    const int r0 = w * 16 + g;
    uint32_t qf[8][4];
#pragma unroll
    for (int ks = 0; ks < 8; ks++) {
        int c = ks * 8 + tg;
        qf[ks][0] = sQP[r0 * ASTRIDE + c];
        qf[ks][1] = sQP[(r0 + 8) * ASTRIDE + c];
        qf[ks][2] = sQP[r0 * ASTRIDE + c + 4];
        qf[ks][3] = sQP[(r0 + 8) * ASTRIDE + c + 4];
    }

    float o[8][4];
#pragma unroll
    for (int nt = 0; nt < 8; nt++)
#pragma unroll
        for (int l = 0; l < 4; l++) o[nt][l] = 0.f;
    float m0 = -1e30f, m1 = -1e30f, l0 = 0.f, l1 = 0.f;

    const int rowg = qt * 128 + w * 16 + g;
    const int kbmax = 2 * qt + 1;

    for (int kb = 0; kb <= kbmax; kb++) {
        CP_WAIT0();
        __syncthreads();
        if (kb < kbmax) {
            issue(kb + 1, (kb + 1) & 1);
            CP_COMMIT();
        }
        if (kb * 64 > qt * 128 + w * 16 + 15) continue;

        const uint32_t* sK = smem + ATT_QP + (kb & 1) * ATT_TILE;
        const uint32_t* sV = smem + ATT_QP + (2 + (kb & 1)) * ATT_TILE;

        float s[8][4];
#pragma unroll
        for (int nt = 0; nt < 8; nt++)
#pragma unroll
            for (int l = 0; l < 4; l++) s[nt][l] = 0.f;
#pragma unroll
        for (int ks = 0; ks < 8; ks++) {
            uint32_t bfr[8][2];
#pragma unroll
            for (int nt = 0; nt < 8; nt++) {
                bfr[nt][0] = rnd(sK[(nt * 8 + g) * ASTRIDE + ks * 8 + tg]);
                bfr[nt][1] = rnd(sK[(nt * 8 + g) * ASTRIDE + ks * 8 + tg + 4]);
            }
#pragma unroll
            for (int nt = 0; nt < 8; nt++)
                mma_tf32(s[nt][0], s[nt][1], s[nt][2], s[nt][3],
                         qf[ks][0], qf[ks][1], qf[ks][2], qf[ks][3],
                         bfr[nt][0], bfr[nt][1]);
        }

        if (kb * 64 + 63 > rowg) {
#pragma unroll
            for (int nt = 0; nt < 8; nt++) {
                int c = kb * 64 + nt * 8 + 2 * tg;
                if (c > rowg) s[nt][0] = -1e30f;
                if (c + 1 > rowg) s[nt][1] = -1e30f;
                if (c > rowg + 8) s[nt][2] = -1e30f;
                if (c + 1 > rowg + 8) s[nt][3] = -1e30f;
            }
        }

        float mx0 = -1e30f, mx1 = -1e30f;
#pragma unroll
        for (int nt = 0; nt < 8; nt++) {
            mx0 = fmaxf(mx0, fmaxf(s[nt][0], s[nt][1]));
            mx1 = fmaxf(mx1, fmaxf(s[nt][2], s[nt][3]));
        }
        mx0 = fmaxf(mx0, __shfl_xor_sync(0xffffffffu, mx0, 1));
        mx0 = fmaxf(mx0, __shfl_xor_sync(0xffffffffu, mx0, 2));
        mx1 = fmaxf(mx1, __shfl_xor_sync(0xffffffffu, mx1, 1));
        mx1 = fmaxf(mx1, __shfl_xor_sync(0xffffffffu, mx1, 2));
        float nm0 = fmaxf(m0, mx0), nm1 = fmaxf(m1, mx1);
        float sc0 = __expf(m0 - nm0), sc1 = __expf(m1 - nm1);
        m0 = nm0; m1 = nm1;
        float sum0 = 0.f, sum1 = 0.f;
#pragma unroll
        for (int nt = 0; nt < 8; nt++) {
            float p0 = __expf(s[nt][0] - nm0);
            float p1 = __expf(s[nt][1] - nm0);
            float p2 = __expf(s[nt][2] - nm1);
            float p3 = __expf(s[nt][3] - nm1);
            sum0 += p0 + p1; sum1 += p2 + p3;
            uint2 u01 = make_uint2(f2tf32(p0), f2tf32(p1));
            uint2 u23 = make_uint2(f2tf32(p2), f2tf32(p3));
            *reinterpret_cast<uint2*>(&sQP[r0 * ASTRIDE + nt * 8 + 2 * tg]) = u01;
            *reinterpret_cast<uint2*>(&sQP[(r0 + 8) * ASTRIDE + nt * 8 + 2 * tg]) = u23;
        }
        sum0 += __shfl_xor_sync(0xffffffffu, sum0, 1);
        sum0 += __shfl_xor_sync(0xffffffffu, sum0, 2);
        sum1 += __shfl_xor_sync(0xffffffffu, sum1, 1);
        sum1 += __shfl_xor_sync(0xffffffffu, sum1, 2);
        l0 = l0 * sc0 + sum0;
        l1 = l1 * sc1 + sum1;
#pragma unroll
        for (int nt = 0; nt < 8; nt++) {
            o[nt][0] *= sc0; o[nt][1] *= sc0;
            o[nt][2] *= sc1; o[nt][3] *= sc1;
        }
        __syncwarp();

#pragma unroll
        for (int ks = 0; ks < 8; ks++) {
            uint32_t a0 = sQP[r0 * ASTRIDE + ks * 8 + tg];
            uint32_t a1 = sQP[(r0 + 8) * ASTRIDE + ks * 8 + tg];
            uint32_t a2 = sQP[r0 * ASTRIDE + ks * 8 + tg + 4];
            uint32_t a3 = sQP[(r0 + 8) * ASTRIDE + ks * 8 + tg + 4];
#pragma unroll
            for (int nt = 0; nt < 8; nt++) {
                uint32_t b0 = rnd(sV[(ks * 8 + tg) * ASTRIDE + nt * 8 + g]);
                uint32_t b1 = rnd(sV[(ks * 8 + tg + 4) * ASTRIDE + nt * 8 + g]);
                mma_tf32(o[nt][0], o[nt][1], o[nt][2], o[nt][3], a0, a1, a2, a3, b0, b1);
            }
        }
    }

    float il0 = 1.f / l0, il1 = 1.f / l1;
    const size_t rg = (size_t)(b * TSEQ + qt * 128 + w * 16 + g);
#pragma unroll
    for (int nt = 0; nt < 8; nt++) {
        size_t col = headoff + nt * 8 + 2 * tg;
        *reinterpret_cast<__half2*>(&O[rg * DMODEL + col]) =
            __floats2half2_rn(o[nt][0] * il0, o[nt][1] * il0);
        *reinterpret_cast<__half2*>(&O[(rg + 8) * DMODEL + col]) =
            __floats2half2_rn(o[nt][2] * il1, o[nt][3] * il1);
    }
}

// ---------------- RMSNorm (fp32 in, fp16 out) ----------------
__global__ void __launch_bounds__(256) rmsnorm_kernel(const float* __restrict__ x,
                                                      const float* __restrict__ w,
                                                      __half* __restrict__ out) {
    const int row = blockIdx.x;
    const float* xr = x + (size_t)row * DMODEL;
    __half* orow = out + (size_t)row * DMODEL;
    const int tid = threadIdx.x;

    float vals[4];
    float local = 0.f;
#pragma unroll
    for (int i = 0; i < 4; i++) {
        float v = xr[tid + i * 256];
        vals[i] = v;
        local += v * v;
    }
    for (int off = 16; off; off >>= 1) local += __shfl_xor_sync(0xffffffffu, local, off);
    __shared__ float red[8];
    __shared__ float rinv_s;
    int warp = tid >> 5, lane = tid & 31;
    if (lane == 0) red[warp] = local;
    __syncthreads();
    if (tid == 0) {
        float tot = 0.f;
#pragma unroll
        for (int i = 0; i < 8; i++) tot += red[i];
        rinv_s = rsqrtf(tot * (1.0f / DMODEL) + EPS);
    }
    __syncthreads();
    float rinv = rinv_s;
#pragma unroll
    for (int i = 0; i < 4; i++) {
        int c = tid + i * 256;
        orow[c] = __float2half_rn(vals[i] * rinv * w[c]);
    }
}

// ---------------- RoPE (in place on q and k, fp32) ----------------
__global__ void rope_kernel(float* __restrict__ q, float* __restrict__ k) {
    int idx = blockIdx.x * blockDim.x + threadIdx.x;
    if (idx >= BT * 512) return;
    int row = idx >> 9;
    int p = idx & 511;
    int h = p >> 5;
    int i = p & 31;
    int t = row & (TSEQ - 1);
    float inv = expf(-((float)(2 * i) / 64.f) * 9.210340371976184f);
    float ang = (float)t * inv;
    float s, c;
    sincosf(ang, &s, &c);
    size_t base = (size_t)row * DMODEL + h * DHEAD + i;
    float qa = q[base], qb = q[base + 32];
    q[base] = qa * c - qb * s;
    q[base + 32] = qb * c + qa * s;
    float ka = k[base], kb2 = k[base + 32];
    k[base] = ka * c - kb2 * s;
    k[base + 32] = kb2 * c + ka * s;
}

// ---------------- mean over tokens (two-pass, fp16 input) ----------------
__global__ void mean_pass1(const __half* __restrict__ n2, float* __restrict__ gpart) {
    int b = blockIdx.y;
    int tc = blockIdx.z;
    int d = blockIdx.x * 256 + threadIdx.x;
    const __half* p = n2 + (size_t)b * TSEQ * DMODEL + (size_t)tc * 256 * DMODEL + d;
    float s = 0.f;
    for (int t = 0; t < 256; t++) s += __half2float(p[(size_t)t * DMODEL]);
    gpart[((size_t)tc * BATCH + b) * DMODEL + d] = s;
}
__global__ void mean_pass2(const float* __restrict__ gpart, float* __restrict__ g) {
    int i = blockIdx.x * 256 + threadIdx.x;
    float s = 0.f;
#pragma unroll
    for (int tc = 0; tc < 8; tc++) s += gpart[(size_t)tc * BATCH * DMODEL + i];
    g[i] = s * (1.f / TSEQ);
}

// ---------------- alpha/beta tiny MLP ----------------
__global__ void ab_kernel(const float* __restrict__ g, const float* __restrict__ fc1,
                          const float* __restrict__ fc2, float* __restrict__ ab) {
    __shared__ float hs[BATCH][ABH];
    int tid = threadIdx.x;
    int b = tid >> 5, hh = tid & 31;
    float s = 0.f;
    for (int d = 0; d < DMODEL; d++) s += g[b * DMODEL + d] * fc1[hh * DMODEL + d];
    hs[b][hh] = fmaxf(s, 0.f);
    __syncthreads();
    if (tid < 2 * BATCH) {
        int bb = tid >> 1, o = tid & 1;
        float s2 = 0.f;
#pragma unroll
        for (int j = 0; j < ABH; j++) s2 += hs[bb][j] * fc2[o * ABH + j];
        ab[bb * 2 + o] = 1.f / (1.f + expf(-s2));
    }
}

// ---------------- final combine ----------------
__global__ void combine_kernel(const float* __restrict__ x1, const float* __restrict__ ffn,
                               const float* __restrict__ proj, const float* __restrict__ ab,
                               float* __restrict__ out) {
    size_t idx = (size_t)blockIdx.x * blockDim.x + threadIdx.x;
    if (idx >= (size_t)BT * DMODEL) return;
    int b = (int)(idx >> 21);
    out[idx] = x1[idx] + ab[b * 2] * ffn[idx] + ab[b * 2 + 1] * proj[idx];
}

// ---------------- launch ----------------
extern "C" void kernel_launch(void* const* d_in, const int* in_sizes, int n_in,
                              void* d_out, int out_size) {
    const float* x       = (const float*)d_in[0];
    const float* norm1_w = (const float*)d_in[2];
    const float* Wq      = (const float*)d_in[3];
    const float* Wk      = (const float*)d_in[4];
    const float* Wv      = (const float*)d_in[5];
    const float* Wo      = (const float*)d_in[6];
    const float* norm2_w = (const float*)d_in[7];
    const float* w1      = (const float*)d_in[8];
    const float* w2      = (const float*)d_in[9];
    const float* fc1     = (const float*)d_in[10];
    const float* fc2     = (const float*)d_in[11];
    const float* down    = (const float*)d_in[12];
    const float* up      = (const float*)d_in[13];
    float* out = (float*)d_out;

    __half *xn1h, *atth, *n2h, *hidh, *phh;
    __half *hWq, *hWk, *hWv, *hWo, *hw1, *hw2, *hdown, *hup;
    float *q, *k, *v, *x1, *ffn, *proj, *gpart, *gvec, *ab;
    cudaGetSymbolAddress((void**)&xn1h,  g_xn1h);
    cudaGetSymbolAddress((void**)&q,     g_q);
    cudaGetSymbolAddress((void**)&k,     g_k);
    cudaGetSymbolAddress((void**)&v,     g_v);
    cudaGetSymbolAddress((void**)&atth,  g_atth);
    cudaGetSymbolAddress((void**)&x1,    g_x1);
    cudaGetSymbolAddress((void**)&n2h,   g_n2h);
    cudaGetSymbolAddress((void**)&hidh,  g_hidh);
    cudaGetSymbolAddress((void**)&ffn,   g_ffn);
    cudaGetSymbolAddress((void**)&phh,   g_phh);
    cudaGetSymbolAddress((void**)&proj,  g_proj);
    cudaGetSymbolAddress((void**)&gpart, g_gpart);
    cudaGetSymbolAddress((void**)&gvec,  g_gvec);
    cudaGetSymbolAddress((void**)&ab,    g_ab);
    cudaGetSymbolAddress((void**)&hWq,   g_hWq);
    cudaGetSymbolAddress((void**)&hWk,   g_hWk);
    cudaGetSymbolAddress((void**)&hWv,   g_hWv);
    cudaGetSymbolAddress((void**)&hWo,   g_hWo);
    cudaGetSymbolAddress((void**)&hw1,   g_hw1);
    cudaGetSymbolAddress((void**)&hw2,   g_hw2);
    cudaGetSymbolAddress((void**)&hdown, g_hdown);
    cudaGetSymbolAddress((void**)&hup,   g_hup);

    static bool attr_set = false;
    if (!attr_set) {
        cudaFuncSetAttribute((const void*)attn_mma_kernel,
                             cudaFuncAttributeMaxDynamicSharedMemorySize, ATT_SMEM_BYTES);
        cudaFuncSetAttribute((const void*)gemmh<0, false, false>,
                             cudaFuncAttributeMaxDynamicSharedMemorySize, GEMMH_SMEM);
        cudaFuncSetAttribute((const void*)gemmh<0, true, false>,
                             cudaFuncAttributeMaxDynamicSharedMemorySize, GEMMH_SMEM);
        cudaFuncSetAttribute((const void*)gemmh<1, false, true>,
                             cudaFuncAttributeMaxDynamicSharedMemorySize, GEMMH_SMEM);
        cudaFuncSetAttribute((const void*)gemmh<2, false, true>,
                             cudaFuncAttributeMaxDynamicSharedMemorySize, GEMMH_SMEM);
        cudaFuncSetAttribute((const void*)gemmh_qkv,
                             cudaFuncAttributeMaxDynamicSharedMemorySize, GEMMH_SMEM);
        attr_set = true;
    }

    // 0. convert weights to fp16
    f2h_kernel<<<(DMODEL*DMODEL/4 + 255)/256, 256>>>((const float4*)Wq, (uint2*)hWq, DMODEL*DMODEL/4);
    f2h_kernel<<<(DMODEL*DMODEL/4 + 255)/256, 256>>>((const float4*)Wk, (uint2*)hWk, DMODEL*DMODEL/4);
    f2h_kernel<<<(DMODEL*DMODEL/4 + 255)/256, 256>>>((const float4*)Wv, (uint2*)hWv, DMODEL*DMODEL/4);
    f2h_kernel<<<(DMODEL*DMODEL/4 + 255)/256, 256>>>((const float4*)Wo, (uint2*)hWo, DMODEL*DMODEL/4);
    f2h_kernel<<<(DFF*DMODEL/4 + 255)/256, 256>>>((const float4*)w1, (uint2*)hw1, DFF*DMODEL/4);
    f2h_kernel<<<(DFF*DMODEL/4 + 255)/256, 256>>>((const float4*)w2, (uint2*)hw2, DFF*DMODEL/4);
    f2h_kernel<<<(BOT*DMODEL/4 + 255)/256, 256>>>((const float4*)down, (uint2*)hdown, BOT*DMODEL/4);
    f2h_kernel<<<(BOT*DMODEL/4 + 255)/256, 256>>>((const float4*)up, (uint2*)hup, BOT*DMODEL/4);

    // 1. norm1 (fp16 out)
    rmsnorm_kernel<<<BT, 256>>>(x, norm1_w, xn1h);
    // 2. fused QKV projections (fp16 in, fp32 out)
    gemmh_qkv<<<dim3(24, BT / 128), 256, GEMMH_SMEM>>>(xn1h, hWq, hWk, hWv, q, k, v);
    // 3. RoPE on q, k
    rope_kernel<<<(BT * 512 + 255) / 256, 256>>>(q, k);
    // 4. attention (tf32 flash, fp16 out)
    attn_mma_kernel<<<dim3(TSEQ / 128, NHEADS, BATCH), 256, ATT_SMEM_BYTES>>>(q, k, v, atth);
    // 5. output proj + residual (fp32 out)
    gemmh<0, true, false><<<dim3(DMODEL / 128, BT / 128), 256, GEMMH_SMEM>>>(atth, hWo, x, x1, DMODEL, DMODEL);
    // 6. norm2 (fp16 out)
    rmsnorm_kernel<<<BT, 256>>>(x1, norm2_w, n2h);
    // 7. FFN
    gemmh<1, false, true><<<dim3(DFF / 128, BT / 128), 256, GEMMH_SMEM>>>(n2h, hw1, nullptr, hidh, DFF, DMODEL);
    gemmh<0, false, false><<<dim3(DMODEL / 128, BT / 128), 256, GEMMH_SMEM>>>(hidh, hw2, nullptr, ffn, DMODEL, DFF);
    // 8. projection branch
    gemmh<2, false, true><<<dim3(BOT / 128, BT / 128), 256, GEMMH_SMEM>>>(n2h, hdown, nullptr, phh, BOT, DMODEL);
    gemmh<0, false, false><<<dim3(DMODEL / 128, BT / 128), 256, GEMMH_SMEM>>>(phh, hup, nullptr, proj, DMODEL, BOT);
    // 9. alpha/beta gate
    mean_pass1<<<dim3(DMODEL / 256, BATCH, 8), 256>>>(n2h, gpart);
    mean_pass2<<<BATCH * DMODEL / 256, 256>>>(gpart, gvec);
    ab_kernel<<<1, 128>>>(gvec, fc1, fc2, ab);
    // 10. combine
    combine_kernel<<<(BT * DMODEL + 255) / 256, 256>>>(x1, ffn, proj, ab, out);
}

// round 8
// speedup vs baseline: 8.3284x; 1.1789x over previous
#include <cuda_runtime.h>
#include <cuda_fp16.h>
#include <cuda_bf16.h>
#include <cstdint>
#include <math.h>

// Problem sizes (fixed)
#define BATCH 4
#define TSEQ 2048
#define BT (BATCH*TSEQ)       // 8192
#define DMODEL 1024
#define NHEADS 16
#define DHEAD 64
#define DFF 4096
#define BOT 256
#define ABH 32
#define EPS 1e-6f

// -------- static scratch (allocation-free contract) --------
__device__ __align__(256) __half g_xn1h[BT*DMODEL];
__device__ float g_q[BT*DMODEL];
__device__ float g_k[BT*DMODEL];
__device__ __align__(256) __half g_qh[BT*DMODEL];
__device__ __align__(256) __half g_kh[BT*DMODEL];
__device__ __align__(256) __half g_vh[BT*DMODEL];
__device__ __align__(256) __half g_atth[BT*DMODEL];
__device__ float g_x1[BT*DMODEL];
__device__ __align__(256) __half g_n2h[BT*DMODEL];
__device__ __align__(256) __half g_hidh[BT*DFF];
__device__ float g_ffn[BT*DMODEL];
__device__ __align__(256) __half g_phh[BT*BOT];
__device__ float g_proj[BT*DMODEL];
__device__ float g_gpart[8*BATCH*DMODEL];
__device__ float g_gvec[BATCH*DMODEL];
__device__ float g_ab[2*BATCH];
// fp16 weights (converted per call)
__device__ __align__(256) __half g_hWq[DMODEL*DMODEL];
__device__ __align__(256) __half g_hWk[DMODEL*DMODEL];
__device__ __align__(256) __half g_hWv[DMODEL*DMODEL];
__device__ __align__(256) __half g_hWo[DMODEL*DMODEL];
__device__ __align__(256) __half g_hw1[DFF*DMODEL];
__device__ __align__(256) __half g_hw2[DMODEL*DFF];
__device__ __align__(256) __half g_hdown[BOT*DMODEL];
__device__ __align__(256) __half g_hup[DMODEL*BOT];

// ---------------- helpers ----------------
__device__ __forceinline__ uint32_t smem_u32(const void* p) {
    uint32_t a;
    asm("{ .reg .u64 t; cvta.to.shared.u64 t, %1; cvt.u32.u64 %0, t; }" : "=r"(a) : "l"(p));
    return a;
}
__device__ __forceinline__ void cp16(uint32_t daddr, const void* gptr) {
    asm volatile("cp.async.cg.shared.global [%0], [%1], 16;" :: "r"(daddr), "l"(gptr) : "memory");
}
#define CP_COMMIT() asm volatile("cp.async.commit_group;" ::: "memory")
#define CP_WAIT2()  asm volatile("cp.async.wait_group 2;" ::: "memory")
#define CP_WAIT0()  asm volatile("cp.async.wait_group 0;" ::: "memory")

__device__ __forceinline__ void mma_f16(float& c0, float& c1, float& c2, float& c3,
                                        uint32_t a0, uint32_t a1, uint32_t a2, uint32_t a3,
                                        uint32_t b0, uint32_t b1) {
    asm volatile(
        "mma.sync.aligned.m16n8k16.row.col.f32.f16.f16.f32 "
        "{%0,%1,%2,%3}, {%4,%5,%6,%7}, {%8,%9}, {%0,%1,%2,%3};"
        : "+f"(c0), "+f"(c1), "+f"(c2), "+f"(c3)
        : "r"(a0), "r"(a1), "r"(a2), "r"(a3), "r"(b0), "r"(b1));
}
__device__ __forceinline__ void ldsm4(uint32_t& r0, uint32_t& r1, uint32_t& r2, uint32_t& r3,
                                      uint32_t a) {
    asm volatile("ldmatrix.sync.aligned.m8n8.x4.shared.b16 {%0,%1,%2,%3}, [%4];"
                 : "=r"(r0), "=r"(r1), "=r"(r2), "=r"(r3) : "r"(a));
}
__device__ __forceinline__ void ldsm4t(uint32_t& r0, uint32_t& r1, uint32_t& r2, uint32_t& r3,
                                       uint32_t a) {
    asm volatile("ldmatrix.sync.aligned.m8n8.x4.trans.shared.b16 {%0,%1,%2,%3}, [%4];"
                 : "=r"(r0), "=r"(r1), "=r"(r2), "=r"(r3) : "r"(a));
}
__device__ __forceinline__ uint32_t packh2(float a, float b) {
    __half2 h = __floats2half2_rn(a, b);
    return *reinterpret_cast<uint32_t*>(&h);
}

// ---------------- fp32 -> fp16 converter ----------------
__global__ void f2h_kernel(const float4* __restrict__ s, uint2* __restrict__ d, int n4) {
    int i = blockIdx.x * 256 + threadIdx.x;
    if (i >= n4) return;
    float4 v = s[i];
    __half2 lo = __floats2half2_rn(v.x, v.y);
    __half2 hi = __floats2half2_rn(v.z, v.w);
    d[i] = make_uint2(*(uint32_t*)&lo, *(uint32_t*)&hi);
}

// ============ fp16 mma.sync GEMM: C = A[M,K] @ B[N,K]^T (+epilogue) ============
#define SMSH 40
#define HSTAGE_BYTES (128 * SMSH * 2 * 2)
#define GEMMH_SMEM (4 * HSTAGE_BYTES)

template<int EPI, bool RESID, bool OUTH>
__device__ __forceinline__ void gemmh_body(const __half* __restrict__ A,
                                           const __half* __restrict__ B,
                                           const float* __restrict__ R,
                                           void* __restrict__ Cv,
                                           int N, int K, int bm, int bn) {
    extern __shared__ __half hsmem[];
    const uint32_t sbase = smem_u32(hsmem);

    const int tid = threadIdx.x;
    const int warp = tid >> 5;
    const int lane = tid & 31;
    const int g = lane >> 2;
    const int tg = lane & 3;
    const int sub = lane >> 3;
    const int rin = lane & 7;
    const int wm = (warp & 1) * 64;
    const int wn = (warp >> 1) * 32;

    const int NC = K >> 5;

    auto issue = [&](int kc) {
        const int stage = kc & 3;
        const uint32_t ab = sbase + stage * HSTAGE_BYTES;
        const uint32_t bb = ab + 128 * SMSH * 2;
        const int k0 = kc << 5;
#pragma unroll
        for (int i = 0; i < 2; i++) {
            int e = tid + i * 256;
            int r = e >> 2, q4 = e & 3;
            uint32_t soff = (uint32_t)(r * SMSH + q4 * 8) * 2;
            cp16(ab + soff, &A[(size_t)(bm + r) * K + k0 + q4 * 8]);
            cp16(bb + soff, &B[(size_t)(bn + r) * K + k0 + q4 * 8]);
        }
    };

    float acc[4][4][4];
#pragma unroll
    for (int i = 0; i < 4; i++)
#pragma unroll
        for (int j = 0; j < 4; j++)
#pragma unroll
            for (int l = 0; l < 4; l++) acc[i][j][l] = 0.f;

#pragma unroll
    for (int s = 0; s < 3; s++) {
        issue(s);
        CP_COMMIT();
    }

    for (int kc = 0; kc < NC; kc++) {
        CP_WAIT2();
        __syncthreads();
        if (kc + 3 < NC) issue(kc + 3);
        CP_COMMIT();

        const uint32_t sA = sbase + (kc & 3) * HSTAGE_BYTES;
        const uint32_t sB = sA + 128 * SMSH * 2;

#pragma unroll
        for (int ks = 0; ks < 2; ks++) {
            uint32_t af[4][4], bf[4][2];
#pragma unroll
            for (int mt = 0; mt < 4; mt++) {
                int row = wm + mt * 16 + rin + (sub & 1) * 8;
                int col = ks * 16 + (sub >> 1) * 8;
                ldsm4(af[mt][0], af[mt][1], af[mt][2], af[mt][3],
                      sA + (uint32_t)(row * SMSH + col) * 2);
            }
#pragma unroll
            for (int p = 0; p < 2; p++) {
                int nrow = wn + (2 * p + (sub >> 1)) * 8 + rin;
                int ncol = ks * 16 + (sub & 1) * 8;
                ldsm4(bf[2 * p][0], bf[2 * p][1], bf[2 * p + 1][0], bf[2 * p + 1][1],
                      sB + (uint32_t)(nrow * SMSH + ncol) * 2);
            }
#pragma unroll
            for (int mt = 0; mt < 4; mt++)
#pragma unroll
                for (int nt = 0; nt < 4; nt++)
                    mma_f16(acc[mt][nt][0], acc[mt][nt][1], acc[mt][nt][2], acc[mt][nt][3],
                            af[mt][0], af[mt][1], af[mt][2], af[mt][3],
                            bf[nt][0], bf[nt][1]);
        }
    }

#pragma unroll
    for (int mt = 0; mt < 4; mt++) {
#pragma unroll
        for (int nt = 0; nt < 4; nt++) {
            int row = bm + wm + mt * 16 + g;
            int col = bn + wn + nt * 8 + tg * 2;
#pragma unroll
            for (int half_i = 0; half_i < 2; half_i++) {
                int m = row + half_i * 8;
                float v0 = acc[mt][nt][half_i * 2 + 0];
                float v1 = acc[mt][nt][half_i * 2 + 1];
                if (EPI == 1) {
                    v0 = 0.5f * v0 * (1.f + erff(v0 * 0.70710678118f));
                    v1 = 0.5f * v1 * (1.f + erff(v1 * 0.70710678118f));
                }
                if (EPI == 2) { v0 = fmaxf(v0, 0.f); v1 = fmaxf(v1, 0.f); }
                if (RESID) {
                    float2 r2 = *reinterpret_cast<const float2*>(&R[(size_t)m * N + col]);
                    v0 += r2.x; v1 += r2.y;
                }
                if (OUTH) {
                    __half2 hv = __floats2half2_rn(v0, v1);
                    *reinterpret_cast<__half2*>(&((__half*)Cv)[(size_t)m * N + col]) = hv;
                } else {
                    *reinterpret_cast<float2*>(&((float*)Cv)[(size_t)m * N + col]) =
                        make_float2(v0, v1);
                }
            }
        }
    }
}

template<int EPI, bool RESID, bool OUTH>
__global__ void __launch_bounds__(256, 1) gemmh(const __half* __restrict__ A,
                                                const __half* __restrict__ B,
                                                const float* __restrict__ R,
                                                void* __restrict__ C,
                                                int N, int K) {
    gemmh_body<EPI, RESID, OUTH>(A, B, R, C, N, K, blockIdx.y * 128, blockIdx.x * 128);
}

// fused QKV: grid.x = 24; Q,K out fp32 (RoPE next), V out fp16
__global__ void __launch_bounds__(256, 1) gemmh_qkv(const __half* __restrict__ A,
                                                    const __half* __restrict__ B0,
                                                    const __half* __restrict__ B1,
                                                    const __half* __restrict__ B2,
                                                    float* __restrict__ C0,
                                                    float* __restrict__ C1,
                                                    __half* __restrict__ C2) {
    const int sel = blockIdx.x >> 3;
    const int bn = (blockIdx.x & 7) * 128;
    const int bm = blockIdx.y * 128;
    if (sel == 2) {
        gemmh_body<0, false, true>(A, B2, nullptr, C2, DMODEL, DMODEL, bm, bn);
    } else {
        gemmh_body<0, false, false>(A, sel ? B1 : B0, nullptr, sel ? C1 : C0,
                                    DMODEL, DMODEL, bm, bn);
    }
}

// ============ fp16 mma.sync flash attention (causal, cp.async double-buffered) ============
// Smem (halves): Q 128x72, then K0,K1,V0,V1 each 64x72.
#define QSTR 72
#define AQ_HALVES (128*QSTR)
#define AT_HALVES (64*QSTR)
#define ATT_SMEM_BYTES ((AQ_HALVES + 4*AT_HALVES) * 2)

__global__ void __launch_bounds__(256) attn_mma_kernel(const __half* __restrict__ Q,
                                                       const __half* __restrict__ K,
                                                       const __half* __restrict__ V,
                                                       __half* __restrict__ O) {
    extern __shared__ __half asmem[];
    const uint32_t sbase = smem_u32(asmem);
    const uint32_t sQ = sbase;

    const int qt = (int)(gridDim.x - 1 - blockIdx.x);
    const int h = blockIdx.y;
    const int b = blockIdx.z;
    const int tid = threadIdx.x;
    const int w = tid >> 5;
    const int lane = tid & 31;
    const int g = lane >> 2;
    const int tg = lane & 3;
    const int sub = lane >> 3;
    const int rin = lane & 7;
    const size_t headoff = (size_t)h * DHEAD;

    // issue cp.async load of K/V tile kb into buffer buf (fp16, 8KB each)
    auto issue = [&](int kb, int buf) {
        const uint32_t kb_base = sbase + (AQ_HALVES + buf * AT_HALVES) * 2;
        const uint32_t vb_base = sbase + (AQ_HALVES + (2 + buf) * AT_HALVES) * 2;
#pragma unroll
        for (int i = 0; i < 2; i++) {
            int e = tid + i * 256;
            int r = e >> 3, c8 = e & 7;
            size_t gb = ((size_t)(b * TSEQ + kb * 64 + r)) * DMODEL + headoff + c8 * 8;
            uint32_t soff = (uint32_t)(r * QSTR + c8 * 8) * 2;
            cp16(kb_base + soff, &K[gb]);
            cp16(vb_base + soff, &V[gb]);
        }
    };

    // K/V tile 0 + Q tile via cp.async
    issue(0, 0);
#pragma unroll
    for (int i = 0; i < 4; i++) {
        int e = tid + i * 256;
        int r = e >> 3, c8 = e & 7;
        size_t gb = ((size_t)(b * TSEQ + qt * 128 + r)) * DMODEL + headoff + c8 * 8;
        cp16(sQ + (uint32_t)(r * QSTR + c8 * 8) * 2, &Q[gb]);
    }
    CP_COMMIT();
    CP_WAIT0();
    __syncthreads();

    // preload Q fragments: warp w owns rows [w*16, w*16+16), 4 k-steps of 16
    uint32_t qf[4][4];
#pragma unroll
    for (int ks = 0; ks < 4; ks++) {
        int row = w * 16 + rin + (sub & 1) * 8;
        int col = ks * 16 + (sub >> 1) * 8;
        ldsm4(qf[ks][0], qf[ks][1], qf[ks][2], qf[ks][3],
              sQ + (uint32_t)(row * QSTR + col) * 2);
    }

    float o[8][4];
#pragma unroll
    for (int nt = 0; nt < 8; nt++)
#pragma unroll
        for (int l = 0; l < 4; l++) o[nt][l] = 0.f;
    float m0 = -1e30f, m1 = -1e30f, l0 = 0.f, l1 = 0.f;

    const int rowg = qt * 128 + w * 16 + g;
    const int kbmax = 2 * qt + 1;

    for (int kb = 0; kb <= kbmax; kb++) {
        CP_WAIT0();
        __syncthreads();
        if (kb < kbmax) {
            issue(kb + 1, (kb + 1) & 1);
            CP_COMMIT();
        }
        if (kb * 64 > qt * 128 + w * 16 + 15) continue;

        const uint32_t sK = sbase + (AQ_HALVES + (kb & 1) * AT_HALVES) * 2;
        const uint32_t sV = sbase + (AQ_HALVES + (2 + (kb & 1)) * AT_HALVES) * 2;

        // ---- S = Q K^T  (K rows = keys(n), cols = headdim(k)) ----
        float s[8][4];
#pragma unroll
        for (int nt = 0; nt < 8; nt++)
#pragma unroll
            for (int l = 0; l < 4; l++) s[nt][l] = 0.f;
#pragma unroll
        for (int ks = 0; ks < 4; ks++) {
            uint32_t bf[8][2];
#pragma unroll
            for (int p = 0; p < 4; p++) {
                int nrow = (2 * p + (sub >> 1)) * 8 + rin;
                int ncol = ks * 16 + (sub & 1) * 8;
                ldsm4(bf[2 * p][0], bf[2 * p][1], bf[2 * p + 1][0], bf[2 * p + 1][1],
                      sK + (uint32_t)(nrow * QSTR + ncol) * 2);
            }
#pragma unroll
            for (int nt = 0; nt < 8; nt++)
                mma_f16(s[nt][0], s[nt][1], s[nt][2], s[nt][3],
                        qf[ks][0], qf[ks][1], qf[ks][2], qf[ks][3],
                        bf[nt][0], bf[nt][1]);
        }

        // ---- causal mask ----
        if (kb * 64 + 63 > rowg) {
#pragma unroll
            for (int nt = 0; nt < 8; nt++) {
                int c = kb * 64 + nt * 8 + 2 * tg;
                if (c > rowg) s[nt][0] = -1e30f;
                if (c + 1 > rowg) s[nt][1] = -1e30f;
                if (c > rowg + 8) s[nt][2] = -1e30f;
                if (c + 1 > rowg + 8) s[nt][3] = -1e30f;
            }
        }

        // ---- online softmax; P packs directly into m16n8k16 A-fragments ----
        float mx0 = -1e30f, mx1 = -1e30f;
#pragma unroll
        for (int nt = 0; nt < 8; nt++) {
            mx0 = fmaxf(mx0, fmaxf(s[nt][0], s[nt][1]));
            mx1 = fmaxf(mx1, fmaxf(s[nt][2], s[nt][3]));
        }
        mx0 = fmaxf(mx0, __shfl_xor_sync(0xffffffffu, mx0, 1));
        mx0 = fmaxf(mx0, __shfl_xor_sync(0xffffffffu, mx0, 2));
        mx1 = fmaxf(mx1, __shfl_xor_sync(0xffffffffu, mx1, 1));
        mx1 = fmaxf(mx1, __shfl_xor_sync(0xffffffffu, mx1, 2));
        float nm0 = fmaxf(m0, mx0), nm1 = fmaxf(m1, mx1);
        float sc0 = __expf(m0 - nm0), sc1 = __expf(m1 - nm1);
        m0 = nm0; m1 = nm1;
        float sum0 = 0.f, sum1 = 0.f;
        uint32_t pf[4][4];
#pragma unroll
        for (int nt = 0; nt < 8; nt++) {
            float p0 = __expf(s[nt][0] - nm0);
            float p1 = __expf(s[nt][1] - nm0);
            float p2 = __expf(s[nt][2] - nm1);
            float p3 = __expf(s[nt][3] - nm1);
            sum0 += p0 + p1; sum1 += p2 + p3;
            int ks = nt >> 1;
            if ((nt & 1) == 0) {
                pf[ks][0] = packh2(p0, p1);
                pf[ks][1] = packh2(p2, p3);
            } else {
                pf[ks][2] = packh2(p0, p1);
                pf[ks][3] = packh2(p2, p3);
            }
        }
        sum0 += __shfl_xor_sync(0xffffffffu, sum0, 1);
        sum0 += __shfl_xor_sync(0xffffffffu, sum0, 2);
        sum1 += __shfl_xor_sync(0xffffffffu, sum1, 1);
        sum1 += __shfl_xor_sync(0xffffffffu, sum1, 2);
        l0 = l0 * sc0 + sum0;
        l1 = l1 * sc1 + sum1;
#pragma unroll
        for (int nt = 0; nt < 8; nt++) {
            o[nt][0] *= sc0; o[nt][1] *= sc0;
            o[nt][2] *= sc1; o[nt][3] *= sc1;
        }

        // ---- O += P V  (V rows = keys(k), cols = headdim(n); trans ldmatrix) ----
#pragma unroll
        for (int ks = 0; ks < 4; ks++) {
            uint32_t vf[8][2];
#pragma unroll
            for (int np = 0; np < 4; np++) {
                int krow = ks * 16 + ((sub & 1) * 8) + rin;
                int ncol = np * 16 + (sub >> 1) * 8;
                ldsm4t(vf[2 * np][0], vf[2 * np][1], vf[2 * np + 1][0], vf[2 * np + 1][1],
                       sV + (uint32_t)(krow * QSTR + ncol) * 2);
            }
#pragma unroll
            for (int nt = 0; nt < 8; nt++)
                mma_f16(o[nt][0], o[nt][1], o[nt][2], o[nt][3],
                        pf[ks][0], pf[ks][1], pf[ks][2], pf[ks][3],
                        vf[nt][0], vf[nt][1]);
        }
    }

    float il0 = 1.f / l0, il1 = 1.f / l1;
    const size_t rg = (size_t)(b * TSEQ + qt * 128 + w * 16 + g);
#pragma unroll
    for (int nt = 0; nt < 8; nt++) {
        size_t col = headoff + nt * 8 + 2 * tg;
        *reinterpret_cast<__half2*>(&O[rg * DMODEL + col]) =
            __floats2half2_rn(o[nt][0] * il0, o[nt][1] * il0);
        *reinterpret_cast<__half2*>(&O[(rg + 8) * DMODEL + col]) =
            __floats2half2_rn(o[nt][2] * il1, o[nt][3] * il1);
    }
}

// ---------------- RMSNorm (fp32 in, fp16 out) ----------------
__global__ void __launch_bounds__(256) rmsnorm_kernel(const float* __restrict__ x,
                                                      const float* __restrict__ w,
                                                      __half* __restrict__ out) {
    const int row = blockIdx.x;
    const float* xr = x + (size_t)row * DMODEL;
    __half* orow = out + (size_t)row * DMODEL;
    const int tid = threadIdx.x;

    float vals[4];
    float local = 0.f;
#pragma unroll
    for (int i = 0; i < 4; i++) {
        float v = xr[tid + i * 256];
        vals[i] = v;
        local += v * v;
    }
    for (int off = 16; off; off >>= 1) local += __shfl_xor_sync(0xffffffffu, local, off);
    __shared__ float red[8];
    __shared__ float rinv_s;
    int warp = tid >> 5, lane = tid & 31;
    if (lane == 0) red[warp] = local;
    __syncthreads();
    if (tid == 0) {
        float tot = 0.f;
#pragma unroll
        for (int i = 0; i < 8; i++) tot += red[i];
        rinv_s = rsqrtf(tot * (1.0f / DMODEL) + EPS);
    }
    __syncthreads();
    float rinv = rinv_s;
#pragma unroll
    for (int i = 0; i < 4; i++) {
        int c = tid + i * 256;
        orow[c] = __float2half_rn(vals[i] * rinv * w[c]);
    }
}

// ---------------- RoPE: fp32 q,k in -> fp16 qh (scaled 1/8), kh out ----------------
__global__ void rope_kernel(const float* __restrict__ q, const float* __restrict__ k,
                            __half* __restrict__ qh, __half* __restrict__ kh) {
    int idx = blockIdx.x * blockDim.x + threadIdx.x;
    if (idx >= BT * 512) return;
    int row = idx >> 9;
    int p = idx & 511;
    int h = p >> 5;
    int i = p & 31;
    int t = row & (TSEQ - 1);
    float inv = expf(-((float)(2 * i) / 64.f) * 9.210340371976184f);
    float ang = (float)t * inv;
    float s, c;
    sincosf(ang, &s, &c);
    size_t base = (size_t)row * DMODEL + h * DHEAD + i;
    float qa = q[base], qb = q[base + 32];
    qh[base]      = __float2half_rn((qa * c - qb * s) * 0.125f);
    qh[base + 32] = __float2half_rn((qb * c + qa * s) * 0.125f);
    float ka = k[base], kb2 = k[base + 32];
    kh[base]      = __float2half_rn(ka * c - kb2 * s);
    kh[base + 32] = __float2half_rn(kb2 * c + ka * s);
}

// ---------------- mean over tokens (two-pass, fp16 input) ----------------
__global__ void mean_pass1(const __half* __restrict__ n2, float* __restrict__ gpart) {
    int b = blockIdx.y;
    int tc = blockIdx.z;
    int d = blockIdx.x * 256 + threadIdx.x;
    const __half* p = n2 + (size_t)b * TSEQ * DMODEL + (size_t)tc * 256 * DMODEL + d;
    float s = 0.f;
    for (int t = 0; t < 256; t++) s += __half2float(p[(size_t)t * DMODEL]);
    gpart[((size_t)tc * BATCH + b) * DMODEL + d] = s;
}
__global__ void mean_pass2(const float* __restrict__ gpart, float* __restrict__ g) {
    int i = blockIdx.x * 256 + threadIdx.x;
    float s = 0.f;
#pragma unroll
    for (int tc = 0; tc < 8; tc++) s += gpart[(size_t)tc * BATCH * DMODEL + i];
    g[i] = s * (1.f / TSEQ);
}

// ---------------- alpha/beta tiny MLP ----------------
__global__ void ab_kernel(const float* __restrict__ g, const float* __restrict__ fc1,
                          const float* __restrict__ fc2, float* __restrict__ ab) {
    __shared__ float hs[BATCH][ABH];
    int tid = threadIdx.x;
    int b = tid >> 5, hh = tid & 31;
    float s = 0.f;
    for (int d = 0; d < DMODEL; d++) s += g[b * DMODEL + d] * fc1[hh * DMODEL + d];
    hs[b][hh] = fmaxf(s, 0.f);
    __syncthreads();
    if (tid < 2 * BATCH) {
        int bb = tid >> 1, o = tid & 1;
        float s2 = 0.f;
#pragma unroll
        for (int j = 0; j < ABH; j++) s2 += hs[bb][j] * fc2[o * ABH + j];
        ab[bb * 2 + o] = 1.f / (1.f + expf(-s2));
    }
}

// ---------------- final combine ----------------
__global__ void combine_kernel(const float* __restrict__ x1, const float* __restrict__ ffn,
                               const float* __restrict__ proj, const float* __restrict__ ab,
                               float* __restrict__ out) {
    size_t idx = (size_t)blockIdx.x * blockDim.x + threadIdx.x;
    if (idx >= (size_t)BT * DMODEL) return;
    int b = (int)(idx >> 21);
    out[idx] = x1[idx] + ab[b * 2] * ffn[idx] + ab[b * 2 + 1] * proj[idx];
}

// ---------------- launch ----------------
extern "C" void kernel_launch(void* const* d_in, const int* in_sizes, int n_in,
                              void* d_out, int out_size) {
    const float* x       = (const float*)d_in[0];
    const float* norm1_w = (const float*)d_in[2];
    const float* Wq      = (const float*)d_in[3];
    const float* Wk      = (const float*)d_in[4];
    const float* Wv      = (const float*)d_in[5];
    const float* Wo      = (const float*)d_in[6];
    const float* norm2_w = (const float*)d_in[7];
    const float* w1      = (const float*)d_in[8];
    const float* w2      = (const float*)d_in[9];
    const float* fc1     = (const float*)d_in[10];
    const float* fc2     = (const float*)d_in[11];
    const float* down    = (const float*)d_in[12];
    const float* up      = (const float*)d_in[13];
    float* out = (float*)d_out;

    __half *xn1h, *qh, *kh, *vh, *atth, *n2h, *hidh, *phh;
    __half *hWq, *hWk, *hWv, *hWo, *hw1, *hw2, *hdown, *hup;
    float *q, *k, *x1, *ffn, *proj, *gpart, *gvec, *ab;
    cudaGetSymbolAddress((void**)&xn1h,  g_xn1h);
    cudaGetSymbolAddress((void**)&q,     g_q);
    cudaGetSymbolAddress((void**)&k,     g_k);
    cudaGetSymbolAddress((void**)&qh,    g_qh);
    cudaGetSymbolAddress((void**)&kh,    g_kh);
    cudaGetSymbolAddress((void**)&vh,    g_vh);
    cudaGetSymbolAddress((void**)&atth,  g_atth);
    cudaGetSymbolAddress((void**)&x1,    g_x1);
    cudaGetSymbolAddress((void**)&n2h,   g_n2h);
    cudaGetSymbolAddress((void**)&hidh,  g_hidh);
    cudaGetSymbolAddress((void**)&ffn,   g_ffn);
    cudaGetSymbolAddress((void**)&phh,   g_phh);
    cudaGetSymbolAddress((void**)&proj,  g_proj);
    cudaGetSymbolAddress((void**)&gpart, g_gpart);
    cudaGetSymbolAddress((void**)&gvec,  g_gvec);
    cudaGetSymbolAddress((void**)&ab,    g_ab);
    cudaGetSymbolAddress((void**)&hWq,   g_hWq);
    cudaGetSymbolAddress((void**)&hWk,   g_hWk);
    cudaGetSymbolAddress((void**)&hWv,   g_hWv);
    cudaGetSymbolAddress((void**)&hWo,   g_hWo);
    cudaGetSymbolAddress((void**)&hw1,   g_hw1);
    cudaGetSymbolAddress((void**)&hw2,   g_hw2);
    cudaGetSymbolAddress((void**)&hdown, g_hdown);
    cudaGetSymbolAddress((void**)&hup,   g_hup);

    static bool attr_set = false;
    if (!attr_set) {
        cudaFuncSetAttribute((const void*)attn_mma_kernel,
                             cudaFuncAttributeMaxDynamicSharedMemorySize, ATT_SMEM_BYTES);
        cudaFuncSetAttribute((const void*)gemmh<0, false, false>,
                             cudaFuncAttributeMaxDynamicSharedMemorySize, GEMMH_SMEM);
        cudaFuncSetAttribute((const void*)gemmh<0, true, false>,
                             cudaFuncAttributeMaxDynamicSharedMemorySize, GEMMH_SMEM);
        cudaFuncSetAttribute((const void*)gemmh<1, false, true>,
                             cudaFuncAttributeMaxDynamicSharedMemorySize, GEMMH_SMEM);
        cudaFuncSetAttribute((const void*)gemmh<2, false, true>,
                             cudaFuncAttributeMaxDynamicSharedMemorySize, GEMMH_SMEM);
        cudaFuncSetAttribute((const void*)gemmh_qkv,
                             cudaFuncAttributeMaxDynamicSharedMemorySize, GEMMH_SMEM);
        attr_set = true;
    }

    // 0. convert weights to fp16
    f2h_kernel<<<(DMODEL*DMODEL/4 + 255)/256, 256>>>((const float4*)Wq, (uint2*)hWq, DMODEL*DMODEL/4);
    f2h_kernel<<<(DMODEL*DMODEL/4 + 255)/256, 256>>>((const float4*)Wk, (uint2*)hWk, DMODEL*DMODEL/4);
    f2h_kernel<<<(DMODEL*DMODEL/4 + 255)/256, 256>>>((const float4*)Wv, (uint2*)hWv, DMODEL*DMODEL/4);
    f2h_kernel<<<(DMODEL*DMODEL/4 + 255)/256, 256>>>((const float4*)Wo, (uint2*)hWo, DMODEL*DMODEL/4);
    f2h_kernel<<<(DFF*DMODEL/4 + 255)/256, 256>>>((const float4*)w1, (uint2*)hw1, DFF*DMODEL/4);
    f2h_kernel<<<(DFF*DMODEL/4 + 255)/256, 256>>>((const float4*)w2, (uint2*)hw2, DFF*DMODEL/4);
    f2h_kernel<<<(BOT*DMODEL/4 + 255)/256, 256>>>((const float4*)down, (uint2*)hdown, BOT*DMODEL/4);
    f2h_kernel<<<(BOT*DMODEL/4 + 255)/256, 256>>>((const float4*)up, (uint2*)hup, BOT*DMODEL/4);

    // 1. norm1 (fp16 out)
    rmsnorm_kernel<<<BT, 256>>>(x, norm1_w, xn1h);
    // 2. fused QKV (Q,K fp32 out; V fp16 out)
    gemmh_qkv<<<dim3(24, BT / 128), 256, GEMMH_SMEM>>>(xn1h, hWq, hWk, hWv, q, k, vh);
    // 3. RoPE: fp32 -> fp16 (q pre-scaled by 1/8)
    rope_kernel<<<(BT * 512 + 255) / 256, 256>>>(q, k, qh, kh);
    // 4. attention (fp16 mma flash)
    attn_mma_kernel<<<dim3(TSEQ / 128, NHEADS, BATCH), 256, ATT_SMEM_BYTES>>>(qh, kh, vh, atth);
    // 5. output proj + residual (fp32 out)
    gemmh<0, true, false><<<dim3(DMODEL / 128, BT / 128), 256, GEMMH_SMEM>>>(atth, hWo, x, x1, DMODEL, DMODEL);
    // 6. norm2 (fp16 out)
    rmsnorm_kernel<<<BT, 256>>>(x1, norm2_w, n2h);
    // 7. FFN
    gemmh<1, false, true><<<dim3(DFF / 128, BT / 128), 256, GEMMH_SMEM>>>(n2h, hw1, nullptr, hidh, DFF, DMODEL);
    gemmh<0, false, false><<<dim3(DMODEL / 128, BT / 128), 256, GEMMH_SMEM>>>(hidh, hw2, nullptr, ffn, DMODEL, DFF);
    // 8. projection branch
    gemmh<2, false, true><<<dim3(BOT / 128, BT / 128), 256, GEMMH_SMEM>>>(n2h, hdown, nullptr, phh, BOT, DMODEL);
    gemmh<0, false, false><<<dim3(DMODEL / 128, BT / 128), 256, GEMMH_SMEM>>>(phh, hup, nullptr, proj, DMODEL, BOT);
    // 9. alpha/beta gate
    mean_pass1<<<dim3(DMODEL / 256, BATCH, 8), 256>>>(n2h, gpart);
    mean_pass2<<<BATCH * DMODEL / 256, 256>>>(gpart, gvec);
    ab_kernel<<<1, 128>>>(gvec, fc1, fc2, ab);
    // 10. combine
    combine_kernel<<<(BT * DMODEL + 255) / 256, 256>>>(x1, ffn, proj, ab, out);
}

// round 9
// speedup vs baseline: 10.0091x; 1.2018x over previous
#include <cuda_runtime.h>
#include <cuda_fp16.h>
#include <cuda_bf16.h>
#include <cstdint>
#include <math.h>

// Problem sizes (fixed)
#define BATCH 4
#define TSEQ 2048
#define BT (BATCH*TSEQ)       // 8192
#define DMODEL 1024
#define NHEADS 16
#define DHEAD 64
#define DFF 4096
#define BOT 256
#define ABH 32
#define EPS 1e-6f

// -------- static scratch (allocation-free contract) --------
__device__ __align__(256) __half g_xn1h[BT*DMODEL];
__device__ __align__(256) __half g_qh[BT*DMODEL];
__device__ __align__(256) __half g_kh[BT*DMODEL];
__device__ __align__(256) __half g_vh[BT*DMODEL];
__device__ __align__(256) __half g_atth[BT*DMODEL];
__device__ float g_x1[BT*DMODEL];
__device__ __align__(256) __half g_n2h[BT*DMODEL];
__device__ __align__(256) __half g_hidh[BT*DFF];
__device__ float g_ffn[BT*DMODEL];
__device__ __align__(256) __half g_phh[BT*BOT];
__device__ float g_gpart[8*BATCH*DMODEL];
__device__ float g_gvec[BATCH*DMODEL];
__device__ float g_ab[2*BATCH];
// fp16 weights (converted per call)
__device__ __align__(256) __half g_hWq[DMODEL*DMODEL];
__device__ __align__(256) __half g_hWk[DMODEL*DMODEL];
__device__ __align__(256) __half g_hWv[DMODEL*DMODEL];
__device__ __align__(256) __half g_hWo[DMODEL*DMODEL];
__device__ __align__(256) __half g_hw1[DFF*DMODEL];
__device__ __align__(256) __half g_hw2[DMODEL*DFF];
__device__ __align__(256) __half g_hdown[BOT*DMODEL];
__device__ __align__(256) __half g_hup[DMODEL*BOT];

// ---------------- helpers ----------------
__device__ __forceinline__ uint32_t smem_u32(const void* p) {
    uint32_t a;
    asm("{ .reg .u64 t; cvta.to.shared.u64 t, %1; cvt.u32.u64 %0, t; }" : "=r"(a) : "l"(p));
    return a;
}
__device__ __forceinline__ void cp16(uint32_t daddr, const void* gptr) {
    asm volatile("cp.async.cg.shared.global [%0], [%1], 16;" :: "r"(daddr), "l"(gptr) : "memory");
}
#define CP_COMMIT() asm volatile("cp.async.commit_group;" ::: "memory")
#define CP_WAIT1()  asm volatile("cp.async.wait_group 1;" ::: "memory")
#define CP_WAIT0()  asm volatile("cp.async.wait_group 0;" ::: "memory")

__device__ __forceinline__ void mma_f16(float& c0, float& c1, float& c2, float& c3,
                                        uint32_t a0, uint32_t a1, uint32_t a2, uint32_t a3,
                                        uint32_t b0, uint32_t b1) {
    asm volatile(
        "mma.sync.aligned.m16n8k16.row.col.f32.f16.f16.f32 "
        "{%0,%1,%2,%3}, {%4,%5,%6,%7}, {%8,%9}, {%0,%1,%2,%3};"
        : "+f"(c0), "+f"(c1), "+f"(c2), "+f"(c3)
        : "r"(a0), "r"(a1), "r"(a2), "r"(a3), "r"(b0), "r"(b1));
}
__device__ __forceinline__ void ldsm4(uint32_t& r0, uint32_t& r1, uint32_t& r2, uint32_t& r3,
                                      uint32_t a) {
    asm volatile("ldmatrix.sync.aligned.m8n8.x4.shared.b16 {%0,%1,%2,%3}, [%4];"
                 : "=r"(r0), "=r"(r1), "=r"(r2), "=r"(r3) : "r"(a));
}
__device__ __forceinline__ void ldsm4t(uint32_t& r0, uint32_t& r1, uint32_t& r2, uint32_t& r3,
                                       uint32_t a) {
    asm volatile("ldmatrix.sync.aligned.m8n8.x4.trans.shared.b16 {%0,%1,%2,%3}, [%4];"
                 : "=r"(r0), "=r"(r1), "=r"(r2), "=r"(r3) : "r"(a));
}
__device__ __forceinline__ uint32_t packh2(float a, float b) {
    __half2 h = __floats2half2_rn(a, b);
    return *reinterpret_cast<uint32_t*>(&h);
}

// ---------------- fp32 -> fp16 converter ----------------
__global__ void f2h_kernel(const float4* __restrict__ s, uint2* __restrict__ d, int n4) {
    int i = blockIdx.x * 256 + threadIdx.x;
    if (i >= n4) return;
    float4 v = s[i];
    __half2 lo = __floats2half2_rn(v.x, v.y);
    __half2 hi = __floats2half2_rn(v.z, v.w);
    d[i] = make_uint2(*(uint32_t*)&lo, *(uint32_t*)&hi);
}

// ============ fp16 mma.sync GEMM: C = A[M,K] @ B[N,K]^T (+epilogue) ============
// CTA 128x128, BK=32, 3-stage cp.async, 2 CTAs/SM.
// EPI: 0 none, 1 GELU, 2 ReLU, 3 combine(out = R + ab0*R2 + ab1*acc).
#define SMSH 40
#define HSTAGE_BYTES (128 * SMSH * 2 * 2)
#define GEMMH_SMEM (3 * HSTAGE_BYTES)

template<int EPI, bool RESID, bool OUTH>
__device__ __forceinline__ void gemmh_body(const __half* __restrict__ A,
                                           const __half* __restrict__ B,
                                           const float* __restrict__ R,
                                           void* __restrict__ Cv,
                                           int N, int K, int bm, int bn,
                                           const float* __restrict__ R2 = nullptr,
                                           const float* __restrict__ AB = nullptr) {
    extern __shared__ __half hsmem[];
    const uint32_t sbase = smem_u32(hsmem);

    const int tid = threadIdx.x;
    const int warp = tid >> 5;
    const int lane = tid & 31;
    const int g = lane >> 2;
    const int tg = lane & 3;
    const int sub = lane >> 3;
    const int rin = lane & 7;
    const int wm = (warp & 1) * 64;
    const int wn = (warp >> 1) * 32;

    const int NC = K >> 5;

    auto issue = [&](int kc) {
        const int stage = kc % 3;
        const uint32_t ab = sbase + stage * HSTAGE_BYTES;
        const uint32_t bb = ab + 128 * SMSH * 2;
        const int k0 = kc << 5;
#pragma unroll
        for (int i = 0; i < 2; i++) {
            int e = tid + i * 256;
            int r = e >> 2, q4 = e & 3;
            uint32_t soff = (uint32_t)(r * SMSH + q4 * 8) * 2;
            cp16(ab + soff, &A[(size_t)(bm + r) * K + k0 + q4 * 8]);
            cp16(bb + soff, &B[(size_t)(bn + r) * K + k0 + q4 * 8]);
        }
    };

    float acc[4][4][4];
#pragma unroll
    for (int i = 0; i < 4; i++)
#pragma unroll
        for (int j = 0; j < 4; j++)
#pragma unroll
            for (int l = 0; l < 4; l++) acc[i][j][l] = 0.f;

    issue(0); CP_COMMIT();
    issue(1); CP_COMMIT();

    for (int kc = 0; kc < NC; kc++) {
        CP_WAIT1();
        __syncthreads();
        if (kc + 2 < NC) issue(kc + 2);
        CP_COMMIT();

        const uint32_t sA = sbase + (kc % 3) * HSTAGE_BYTES;
        const uint32_t sB = sA + 128 * SMSH * 2;

#pragma unroll
        for (int ks = 0; ks < 2; ks++) {
            uint32_t af[4][4], bf[4][2];
#pragma unroll
            for (int mt = 0; mt < 4; mt++) {
                int row = wm + mt * 16 + rin + (sub & 1) * 8;
                int col = ks * 16 + (sub >> 1) * 8;
                ldsm4(af[mt][0], af[mt][1], af[mt][2], af[mt][3],
                      sA + (uint32_t)(row * SMSH + col) * 2);
            }
#pragma unroll
            for (int p = 0; p < 2; p++) {
                int nrow = wn + (2 * p + (sub >> 1)) * 8 + rin;
                int ncol = ks * 16 + (sub & 1) * 8;
                ldsm4(bf[2 * p][0], bf[2 * p][1], bf[2 * p + 1][0], bf[2 * p + 1][1],
                      sB + (uint32_t)(nrow * SMSH + ncol) * 2);
            }
#pragma unroll
            for (int mt = 0; mt < 4; mt++)
#pragma unroll
                for (int nt = 0; nt < 4; nt++)
                    mma_f16(acc[mt][nt][0], acc[mt][nt][1], acc[mt][nt][2], acc[mt][nt][3],
                            af[mt][0], af[mt][1], af[mt][2], af[mt][3],
                            bf[nt][0], bf[nt][1]);
        }
    }

#pragma unroll
    for (int mt = 0; mt < 4; mt++) {
#pragma unroll
        for (int nt = 0; nt < 4; nt++) {
            int row = bm + wm + mt * 16 + g;
            int col = bn + wn + nt * 8 + tg * 2;
#pragma unroll
            for (int half_i = 0; half_i < 2; half_i++) {
                int m = row + half_i * 8;
                float v0 = acc[mt][nt][half_i * 2 + 0];
                float v1 = acc[mt][nt][half_i * 2 + 1];
                if (EPI == 1) {
                    v0 = 0.5f * v0 * (1.f + erff(v0 * 0.70710678118f));
                    v1 = 0.5f * v1 * (1.f + erff(v1 * 0.70710678118f));
                }
                if (EPI == 2) { v0 = fmaxf(v0, 0.f); v1 = fmaxf(v1, 0.f); }
                if (EPI == 3) {
                    int bidx = m >> 11;      // 2048 rows per batch
                    float al = AB[bidx * 2], be = AB[bidx * 2 + 1];
                    float2 rx = *reinterpret_cast<const float2*>(&R[(size_t)m * N + col]);
                    float2 rf = *reinterpret_cast<const float2*>(&R2[(size_t)m * N + col]);
                    v0 = rx.x + al * rf.x + be * v0;
                    v1 = rx.y + al * rf.y + be * v1;
                }
                if (RESID) {
                    float2 r2 = *reinterpret_cast<const float2*>(&R[(size_t)m * N + col]);
                    v0 += r2.x; v1 += r2.y;
                }
                if (OUTH) {
                    __half2 hv = __floats2half2_rn(v0, v1);
                    *reinterpret_cast<__half2*>(&((__half*)Cv)[(size_t)m * N + col]) = hv;
                } else {
                    *reinterpret_cast<float2*>(&((float*)Cv)[(size_t)m * N + col]) =
                        make_float2(v0, v1);
                }
            }
        }
    }
}

template<int EPI, bool RESID, bool OUTH>
__global__ void __launch_bounds__(256, 2) gemmh(const __half* __restrict__ A,
                                                const __half* __restrict__ B,
                                                const float* __restrict__ R,
                                                void* __restrict__ C,
                                                int N, int K) {
    gemmh_body<EPI, RESID, OUTH>(A, B, R, C, N, K, blockIdx.y * 128, blockIdx.x * 128);
}

// up-GEMM with fused combine: out = x1 + ab0*ffn + ab1*(A@B^T)
__global__ void __launch_bounds__(256, 2) gemmh_up_combine(const __half* __restrict__ A,
                                                           const __half* __restrict__ B,
                                                           const float* __restrict__ x1,
                                                           const float* __restrict__ ffn,
                                                           const float* __restrict__ ab,
                                                           float* __restrict__ out) {
    gemmh_body<3, false, false>(A, B, x1, out, DMODEL, BOT,
                                blockIdx.y * 128, blockIdx.x * 128, ffn, ab);
}

// fused QKV: grid.x = 24; all outputs fp16 (q,k raw — RoPE applied after)
__global__ void __launch_bounds__(256, 2) gemmh_qkv(const __half* __restrict__ A,
                                                    const __half* __restrict__ B0,
                                                    const __half* __restrict__ B1,
                                                    const __half* __restrict__ B2,
                                                    __half* __restrict__ C0,
                                                    __half* __restrict__ C1,
                                                    __half* __restrict__ C2) {
    const int sel = blockIdx.x >> 3;
    const __half* B = (sel == 0) ? B0 : (sel == 1) ? B1 : B2;
    __half* C = (sel == 0) ? C0 : (sel == 1) ? C1 : C2;
    gemmh_body<0, false, true>(A, B, nullptr, C, DMODEL, DMODEL,
                               blockIdx.y * 128, (blockIdx.x & 7) * 128);
}

// ============ fp16 mma.sync flash attention (causal, cp.async double-buffered) ============
#define QSTR 72
#define AQ_HALVES (128*QSTR)
#define AT_HALVES (64*QSTR)
#define ATT_SMEM_BYTES ((AQ_HALVES + 4*AT_HALVES) * 2)

__global__ void __launch_bounds__(256) attn_mma_kernel(const __half* __restrict__ Q,
                                                       const __half* __restrict__ K,
                                                       const __half* __restrict__ V,
                                                       __half* __restrict__ O) {
    extern __shared__ __half asmem[];
    const uint32_t sbase = smem_u32(asmem);
    const uint32_t sQ = sbase;

    const int qt = (int)(gridDim.x - 1 - blockIdx.x);
    const int h = blockIdx.y;
    const int b = blockIdx.z;
    const int tid = threadIdx.x;
    const int w = tid >> 5;
    const int lane = tid & 31;
    const int g = lane >> 2;
    const int tg = lane & 3;
    const int sub = lane >> 3;
    const int rin = lane & 7;
    const size_t headoff = (size_t)h * DHEAD;

    auto issue = [&](int kb, int buf) {
        const uint32_t kb_base = sbase + (AQ_HALVES + buf * AT_HALVES) * 2;
        const uint32_t vb_base = sbase + (AQ_HALVES + (2 + buf) * AT_HALVES) * 2;
#pragma unroll
        for (int i = 0; i < 2; i++) {
            int e = tid + i * 256;
            int r = e >> 3, c8 = e & 7;
            size_t gb = ((size_t)(b * TSEQ + kb * 64 + r)) * DMODEL + headoff + c8 * 8;
            uint32_t soff = (uint32_t)(r * QSTR + c8 * 8) * 2;
            cp16(kb_base + soff, &K[gb]);
            cp16(vb_base + soff, &V[gb]);
        }
    };

    issue(0, 0);
#pragma unroll
    for (int i = 0; i < 4; i++) {
        int e = tid + i * 256;
        int r = e >> 3, c8 = e & 7;
        size_t gb = ((size_t)(b * TSEQ + qt * 128 + r)) * DMODEL + headoff + c8 * 8;
        cp16(sQ + (uint32_t)(r * QSTR + c8 * 8) * 2, &Q[gb]);
    }
    CP_COMMIT();
    CP_WAIT0();
    __syncthreads();

    uint32_t qf[4][4];
#pragma unroll
    for (int ks = 0; ks < 4; ks++) {
        int row = w * 16 + rin + (sub & 1) * 8;
        int col = ks * 16 + (sub >> 1) * 8;
        ldsm4(qf[ks][0], qf[ks][1], qf[ks][2], qf[ks][3],
              sQ + (uint32_t)(row * QSTR + col) * 2);
    }

    float o[8][4];
#pragma unroll
    for (int nt = 0; nt < 8; nt++)
#pragma unroll
        for (int l = 0; l < 4; l++) o[nt][l] = 0.f;
    float m0 = -1e30f, m1 = -1e30f, l0 = 0.f, l1 = 0.f;

    const int rowg = qt * 128 + w * 16 + g;
    const int kbmax = 2 * qt + 1;

    for (int kb = 0; kb <= kbmax; kb++) {
        CP_WAIT0();
        __syncthreads();
        if (kb < kbmax) {
            issue(kb + 1, (kb + 1) & 1);
            CP_COMMIT();
        }
        if (kb * 64 > qt * 128 + w * 16 + 15) continue;

        const uint32_t sK = sbase + (AQ_HALVES + (kb & 1) * AT_HALVES) * 2;
        const uint32_t sV = sbase + (AQ_HALVES + (2 + (kb & 1)) * AT_HALVES) * 2;

        float s[8][4];
#pragma unroll
        for (int nt = 0; nt < 8; nt++)
#pragma unroll
            for (int l = 0; l < 4; l++) s[nt][l] = 0.f;
#pragma unroll
        for (int ks = 0; ks < 4; ks++) {
            uint32_t bf[8][2];
#pragma unroll
            for (int p = 0; p < 4; p++) {
                int nrow = (2 * p + (sub >> 1)) * 8 + rin;
                int ncol = ks * 16 + (sub & 1) * 8;
                ldsm4(bf[2 * p][0], bf[2 * p][1], bf[2 * p + 1][0], bf[2 * p + 1][1],
                      sK + (uint32_t)(nrow * QSTR + ncol) * 2);
            }
#pragma unroll
            for (int nt = 0; nt < 8; nt++)
                mma_f16(s[nt][0], s[nt][1], s[nt][2], s[nt][3],
                        qf[ks][0], qf[ks][1], qf[ks][2], qf[ks][3],
                        bf[nt][0], bf[nt][1]);
        }

        if (kb * 64 + 63 > rowg) {
#pragma unroll
            for (int nt = 0; nt < 8; nt++) {
                int c = kb * 64 + nt * 8 + 2 * tg;
                if (c > rowg) s[nt][0] = -1e30f;
                if (c + 1 > rowg) s[nt][1] = -1e30f;
                if (c > rowg + 8) s[nt][2] = -1e30f;
                if (c + 1 > rowg + 8) s[nt][3] = -1e30f;
            }
        }

        float mx0 = -1e30f, mx1 = -1e30f;
#pragma unroll
        for (int nt = 0; nt < 8; nt++) {
            mx0 = fmaxf(mx0, fmaxf(s[nt][0], s[nt][1]));
            mx1 = fmaxf(mx1, fmaxf(s[nt][2], s[nt][3]));
        }
        mx0 = fmaxf(mx0, __shfl_xor_sync(0xffffffffu, mx0, 1));
        mx0 = fmaxf(mx0, __shfl_xor_sync(0xffffffffu, mx0, 2));
        mx1 = fmaxf(mx1, __shfl_xor_sync(0xffffffffu, mx1, 1));
        mx1 = fmaxf(mx1, __shfl_xor_sync(0xffffffffu, mx1, 2));
        float nm0 = fmaxf(m0, mx0), nm1 = fmaxf(m1, mx1);
        float sc0 = __expf(m0 - nm0), sc1 = __expf(m1 - nm1);
        m0 = nm0; m1 = nm1;
        float sum0 = 0.f, sum1 = 0.f;
        uint32_t pf[4][4];
#pragma unroll
        for (int nt = 0; nt < 8; nt++) {
            float p0 = __expf(s[nt][0] - nm0);
            float p1 = __expf(s[nt][1] - nm0);
            float p2 = __expf(s[nt][2] - nm1);
            float p3 = __expf(s[nt][3] - nm1);
            sum0 += p0 + p1; sum1 += p2 + p3;
            int ks = nt >> 1;
            if ((nt & 1) == 0) {
                pf[ks][0] = packh2(p0, p1);
                pf[ks][1] = packh2(p2, p3);
            } else {
                pf[ks][2] = packh2(p0, p1);
                pf[ks][3] = packh2(p2, p3);
            }
        }
        sum0 += __shfl_xor_sync(0xffffffffu, sum0, 1);
        sum0 += __shfl_xor_sync(0xffffffffu, sum0, 2);
        sum1 += __shfl_xor_sync(0xffffffffu, sum1, 1);
        sum1 += __shfl_xor_sync(0xffffffffu, sum1, 2);
        l0 = l0 * sc0 + sum0;
        l1 = l1 * sc1 + sum1;
#pragma unroll
        for (int nt = 0; nt < 8; nt++) {
            o[nt][0] *= sc0; o[nt][1] *= sc0;
            o[nt][2] *= sc1; o[nt][3] *= sc1;
        }

#pragma unroll
        for (int ks = 0; ks < 4; ks++) {
            uint32_t vf[8][2];
#pragma unroll
            for (int np = 0; np < 4; np++) {
                int krow = ks * 16 + ((sub & 1) * 8) + rin;
                int ncol = np * 16 + (sub >> 1) * 8;
                ldsm4t(vf[2 * np][0], vf[2 * np][1], vf[2 * np + 1][0], vf[2 * np + 1][1],
                       sV + (uint32_t)(krow * QSTR + ncol) * 2);
            }
#pragma unroll
            for (int nt = 0; nt < 8; nt++)
                mma_f16(o[nt][0], o[nt][1], o[nt][2], o[nt][3],
                        pf[ks][0], pf[ks][1], pf[ks][2], pf[ks][3],
                        vf[nt][0], vf[nt][1]);
        }
    }

    float il0 = 1.f / l0, il1 = 1.f / l1;
    const size_t rg = (size_t)(b * TSEQ + qt * 128 + w * 16 + g);
#pragma unroll
    for (int nt = 0; nt < 8; nt++) {
        size_t col = headoff + nt * 8 + 2 * tg;
        *reinterpret_cast<__half2*>(&O[rg * DMODEL + col]) =
            __floats2half2_rn(o[nt][0] * il0, o[nt][1] * il0);
        *reinterpret_cast<__half2*>(&O[(rg + 8) * DMODEL + col]) =
            __floats2half2_rn(o[nt][2] * il1, o[nt][3] * il1);
    }
}

// ---------------- RMSNorm (fp32 in, fp16 out) ----------------
__global__ void __launch_bounds__(256) rmsnorm_kernel(const float* __restrict__ x,
                                                      const float* __restrict__ w,
                                                      __half* __restrict__ out) {
    const int row = blockIdx.x;
    const float* xr = x + (size_t)row * DMODEL;
    __half* orow = out + (size_t)row * DMODEL;
    const int tid = threadIdx.x;

    float vals[4];
    float local = 0.f;
#pragma unroll
    for (int i = 0; i < 4; i++) {
        float v = xr[tid + i * 256];
        vals[i] = v;
        local += v * v;
    }
    for (int off = 16; off; off >>= 1) local += __shfl_xor_sync(0xffffffffu, local, off);
    __shared__ float red[8];
    __shared__ float rinv_s;
    int warp = tid >> 5, lane = tid & 31;
    if (lane == 0) red[warp] = local;
    __syncthreads();
    if (tid == 0) {
        float tot = 0.f;
#pragma unroll
        for (int i = 0; i < 8; i++) tot += red[i];
        rinv_s = rsqrtf(tot * (1.0f / DMODEL) + EPS);
    }
    __syncthreads();
    float rinv = rinv_s;
#pragma unroll
    for (int i = 0; i < 4; i++) {
        int c = tid + i * 256;
        orow[c] = __float2half_rn(vals[i] * rinv * w[c]);
    }
}

// ---------------- RoPE: fp16 in-place rotate (q scaled by 1/8) ----------------
__global__ void rope_kernel(__half* __restrict__ qh, __half* __restrict__ kh) {
    int idx = blockIdx.x * blockDim.x + threadIdx.x;
    if (idx >= BT * 512) return;
    int row = idx >> 9;
    int p = idx & 511;
    int h = p >> 5;
    int i = p & 31;
    int t = row & (TSEQ - 1);
    float inv = expf(-((float)(2 * i) / 64.f) * 9.210340371976184f);
    float ang = (float)t * inv;
    float s, c;
    sincosf(ang, &s, &c);
    size_t base = (size_t)row * DMODEL + h * DHEAD + i;
    float qa = __half2float(qh[base]), qb = __half2float(qh[base + 32]);
    qh[base]      = __float2half_rn((qa * c - qb * s) * 0.125f);
    qh[base + 32] = __float2half_rn((qb * c + qa * s) * 0.125f);
    float ka = __half2float(kh[base]), kb2 = __half2float(kh[base + 32]);
    kh[base]      = __float2half_rn(ka * c - kb2 * s);
    kh[base + 32] = __float2half_rn(kb2 * c + ka * s);
}

// ---------------- mean over tokens (two-pass, fp16 input) ----------------
__global__ void mean_pass1(const __half* __restrict__ n2, float* __restrict__ gpart) {
    int b = blockIdx.y;
    int tc = blockIdx.z;
    int d = blockIdx.x * 256 + threadIdx.x;
    const __half* p = n2 + (size_t)b * TSEQ * DMODEL + (size_t)tc * 256 * DMODEL + d;
    float s = 0.f;
    for (int t = 0; t < 256; t++) s += __half2float(p[(size_t)t * DMODEL]);
    gpart[((size_t)tc * BATCH + b) * DMODEL + d] = s;
}
__global__ void mean_pass2(const float* __restrict__ gpart, float* __restrict__ g) {
    int i = blockIdx.x * 256 + threadIdx.x;
    float s = 0.f;
#pragma unroll
    for (int tc = 0; tc < 8; tc++) s += gpart[(size_t)tc * BATCH * DMODEL + i];
    g[i] = s * (1.f / TSEQ);
}

// ---------------- alpha/beta tiny MLP ----------------
__global__ void ab_kernel(const float* __restrict__ g, const float* __restrict__ fc1,
                          const float* __restrict__ fc2, float* __restrict__ ab) {
    __shared__ float hs[BATCH][ABH];
    int tid = threadIdx.x;
    int b = tid >> 5, hh = tid & 31;
    float s = 0.f;
    for (int d = 0; d < DMODEL; d++) s += g[b * DMODEL + d] * fc1[hh * DMODEL + d];
    hs[b][hh] = fmaxf(s, 0.f);
    __syncthreads();
    if (tid < 2 * BATCH) {
        int bb = tid >> 1, o = tid & 1;
        float s2 = 0.f;
#pragma unroll
        for (int j = 0; j < ABH; j++) s2 += hs[bb][j] * fc2[o * ABH + j];
        ab[bb * 2 + o] = 1.f / (1.f + expf(-s2));
    }
}

// ---------------- launch ----------------
extern "C" void kernel_launch(void* const* d_in, const int* in_sizes, int n_in,
                              void* d_out, int out_size) {
    const float* x       = (const float*)d_in[0];
    const float* norm1_w = (const float*)d_in[2];
    const float* Wq      = (const float*)d_in[3];
    const float* Wk      = (const float*)d_in[4];
    const float* Wv      = (const float*)d_in[5];
    const float* Wo      = (const float*)d_in[6];
    const float* norm2_w = (const float*)d_in[7];
    const float* w1      = (const float*)d_in[8];
    const float* w2      = (const float*)d_in[9];
    const float* fc1     = (const float*)d_in[10];
    const float* fc2     = (const float*)d_in[11];
    const float* down    = (const float*)d_in[12];
    const float* up      = (const float*)d_in[13];
    float* out = (float*)d_out;

    __half *xn1h, *qh, *kh, *vh, *atth, *n2h, *hidh, *phh;
    __half *hWq, *hWk, *hWv, *hWo, *hw1, *hw2, *hdown, *hup;
    float *x1, *ffn, *gpart, *gvec, *ab;
    cudaGetSymbolAddress((void**)&xn1h,  g_xn1h);
    cudaGetSymbolAddress((void**)&qh,    g_qh);
    cudaGetSymbolAddress((void**)&kh,    g_kh);
    cudaGetSymbolAddress((void**)&vh,    g_vh);
    cudaGetSymbolAddress((void**)&atth,  g_atth);
    cudaGetSymbolAddress((void**)&x1,    g_x1);
    cudaGetSymbolAddress((void**)&n2h,   g_n2h);
    cudaGetSymbolAddress((void**)&hidh,  g_hidh);
    cudaGetSymbolAddress((void**)&ffn,   g_ffn);
    cudaGetSymbolAddress((void**)&phh,   g_phh);
    cudaGetSymbolAddress((void**)&gpart, g_gpart);
    cudaGetSymbolAddress((void**)&gvec,  g_gvec);
    cudaGetSymbolAddress((void**)&ab,    g_ab);
    cudaGetSymbolAddress((void**)&hWq,   g_hWq);
    cudaGetSymbolAddress((void**)&hWk,   g_hWk);
    cudaGetSymbolAddress((void**)&hWv,   g_hWv);
    cudaGetSymbolAddress((void**)&hWo,   g_hWo);
    cudaGetSymbolAddress((void**)&hw1,   g_hw1);
    cudaGetSymbolAddress((void**)&hw2,   g_hw2);
    cudaGetSymbolAddress((void**)&hdown, g_hdown);
    cudaGetSymbolAddress((void**)&hup,   g_hup);

    static bool attr_set = false;
    if (!attr_set) {
        cudaFuncSetAttribute((const void*)attn_mma_kernel,
                             cudaFuncAttributeMaxDynamicSharedMemorySize, ATT_SMEM_BYTES);
        cudaFuncSetAttribute((const void*)gemmh<0, false, false>,
                             cudaFuncAttributeMaxDynamicSharedMemorySize, GEMMH_SMEM);
        cudaFuncSetAttribute((const void*)gemmh<0, true, false>,
                             cudaFuncAttributeMaxDynamicSharedMemorySize, GEMMH_SMEM);
        cudaFuncSetAttribute((const void*)gemmh<1, false, true>,
                             cudaFuncAttributeMaxDynamicSharedMemorySize, GEMMH_SMEM);
        cudaFuncSetAttribute((const void*)gemmh<2, false, true>,
                             cudaFuncAttributeMaxDynamicSharedMemorySize, GEMMH_SMEM);
        cudaFuncSetAttribute((const void*)gemmh_qkv,
                             cudaFuncAttributeMaxDynamicSharedMemorySize, GEMMH_SMEM);
        cudaFuncSetAttribute((const void*)gemmh_up_combine,
                             cudaFuncAttributeMaxDynamicSharedMemorySize, GEMMH_SMEM);
        attr_set = true;
    }

    // 0. convert weights to fp16
    f2h_kernel<<<(DMODEL*DMODEL/4 + 255)/256, 256>>>((const float4*)Wq, (uint2*)hWq, DMODEL*DMODEL/4);
    f2h_kernel<<<(DMODEL*DMODEL/4 + 255)/256, 256>>>((const float4*)Wk, (uint2*)hWk, DMODEL*DMODEL/4);
    f2h_kernel<<<(DMODEL*DMODEL/4 + 255)/256, 256>>>((const float4*)Wv, (uint2*)hWv, DMODEL*DMODEL/4);
    f2h_kernel<<<(DMODEL*DMODEL/4 + 255)/256, 256>>>((const float4*)Wo, (uint2*)hWo, DMODEL*DMODEL/4);
    f2h_kernel<<<(DFF*DMODEL/4 + 255)/256, 256>>>((const float4*)w1, (uint2*)hw1, DFF*DMODEL/4);
    f2h_kernel<<<(DFF*DMODEL/4 + 255)/256, 256>>>((const float4*)w2, (uint2*)hw2, DFF*DMODEL/4);
    f2h_kernel<<<(BOT*DMODEL/4 + 255)/256, 256>>>((const float4*)down, (uint2*)hdown, BOT*DMODEL/4);
    f2h_kernel<<<(BOT*DMODEL/4 + 255)/256, 256>>>((const float4*)up, (uint2*)hup, BOT*DMODEL/4);

    // 1. norm1 (fp16 out)
    rmsnorm_kernel<<<BT, 256>>>(x, norm1_w, xn1h);
    // 2. fused QKV (all fp16 out)
    gemmh_qkv<<<dim3(24, BT / 128), 256, GEMMH_SMEM>>>(xn1h, hWq, hWk, hWv, qh, kh, vh);
    // 3. RoPE (fp16 in-place; q pre-scaled by 1/8)
    rope_kernel<<<(BT * 512 + 255) / 256, 256>>>(qh, kh);
    // 4. attention (fp16 mma flash)
    attn_mma_kernel<<<dim3(TSEQ / 128, NHEADS, BATCH), 256, ATT_SMEM_BYTES>>>(qh, kh, vh, atth);
    // 5. output proj + residual (fp32 out)
    gemmh<0, true, false><<<dim3(DMODEL / 128, BT / 128), 256, GEMMH_SMEM>>>(atth, hWo, x, x1, DMODEL, DMODEL);
    // 6. norm2 (fp16 out)
    rmsnorm_kernel<<<BT, 256>>>(x1, norm2_w, n2h);
    // 7. alpha/beta gate (before FFN so ab is ready for fused combine)
    mean_pass1<<<dim3(DMODEL / 256, BATCH, 8), 256>>>(n2h, gpart);
    mean_pass2<<<BATCH * DMODEL / 256, 256>>>(gpart, gvec);
    ab_kernel<<<1, 128>>>(gvec, fc1, fc2, ab);
    // 8. FFN
    gemmh<1, false, true><<<dim3(DFF / 128, BT / 128), 256, GEMMH_SMEM>>>(n2h, hw1, nullptr, hidh, DFF, DMODEL);
    gemmh<0, false, false><<<dim3(DMODEL / 128, BT / 128), 256, GEMMH_SMEM>>>(hidh, hw2, nullptr, ffn, DMODEL, DFF);
    // 9. projection branch
    gemmh<2, false, true><<<dim3(BOT / 128, BT / 128), 256, GEMMH_SMEM>>>(n2h, hdown, nullptr, phh, BOT, DMODEL);
    // 10. up-proj + fused combine -> out
    gemmh_up_combine<<<dim3(DMODEL / 128, BT / 128), 256, GEMMH_SMEM>>>(phh, hup, x1, ffn, ab, out);
}